// round 1
// baseline (speedup 1.0000x reference)
#include <cuda_runtime.h>
#include <cuda_bf16.h>
#include <cstdint>

#define NN 100000
#define EE 300000
#define DD 256
#define GG 4000
#define LL 5
#define F_IN 40

// ---------------- scratch (device globals: allocation-free) ----------------
__device__ float g_h[NN * DD];        // node features (current layer)
__device__ float g_agg[NN * DD];      // aggregated messages
__device__ float g_t[NN * 2 * DD];    // hidden 512 buffer
__device__ float g_sum[DD];
__device__ float g_sumsq[DD];
__device__ float g_mol[GG * DD];
__device__ float g_cnt[GG];
__device__ float g_z1[GG * DD];
__device__ float g_z2[GG * DD];

// ---------------- helpers ----------------
__device__ __forceinline__ void red_add_v4(float* addr, float4 v) {
    asm volatile("red.global.add.v4.f32 [%0], {%1,%2,%3,%4};"
                 :: "l"(addr), "f"(v.x), "f"(v.y), "f"(v.z), "f"(v.w)
                 : "memory");
}

// ---------------- embed: h = relu(x @ embW + embB), K=40 ----------------
__global__ void embed_kernel(const float* __restrict__ x,
                             const float* __restrict__ W,
                             const float* __restrict__ b) {
    int node = blockIdx.x;
    __shared__ float xs[F_IN];
    if (threadIdx.x < F_IN) xs[threadIdx.x] = x[node * F_IN + threadIdx.x];
    __syncthreads();
    int d = threadIdx.x;
    float acc = b[d];
#pragma unroll
    for (int k = 0; k < F_IN; k++)
        acc = fmaf(xs[k], W[k * DD + d], acc);
    g_h[node * DD + d] = fmaxf(acc, 0.f);
}

// ---------------- agg init: agg = h + ee1[l][4] + ee2[l][0] ----------------
__global__ void init_agg_kernel(const float* __restrict__ ee1s,
                                const float* __restrict__ ee2s) {
    int i = blockIdx.x * 256 + threadIdx.x;
    if (i >= NN * DD) return;
    int d = i & (DD - 1);
    g_agg[i] = g_h[i] + ee1s[d] + ee2s[d];
}

// ---------------- edge scatter: agg[dst] += h[src] + ee1[ea0] + ee2[ea1] ----
__global__ void scatter_kernel(const int* __restrict__ src,
                               const int* __restrict__ dst,
                               const int* __restrict__ eattr,
                               const float* __restrict__ ee1l,
                               const float* __restrict__ ee2l) {
    int e = blockIdx.x * 4 + (threadIdx.x >> 6);
    int c = threadIdx.x & 63;   // float4 chunk (64 * 4 = 256 floats)
    if (e >= EE) return;
    int s  = src[e];
    int d  = dst[e];
    int a0 = eattr[2 * e];
    int a1 = eattr[2 * e + 1];
    float4 v  = ((const float4*)(g_h + (size_t)s * DD))[c];
    float4 t1 = ((const float4*)(ee1l + a0 * DD))[c];
    float4 t2 = ((const float4*)(ee2l + a1 * DD))[c];
    v.x += t1.x + t2.x;
    v.y += t1.y + t2.y;
    v.z += t1.z + t2.z;
    v.w += t1.w + t2.w;
    red_add_v4(g_agg + (size_t)d * DD + c * 4, v);
}

// ---------------- generic tiled GEMM: C = A[M,K] @ B[K,Nc] + bias (opt relu) ----
// BM=BN=64, BK=16, 256 threads, 4x4 microtile. K must be a multiple of 16,
// Nc a multiple of 4.
template <int RELU>
__global__ void __launch_bounds__(256) gemm_bias(const float* __restrict__ A,
                                                 const float* __restrict__ B,
                                                 const float* __restrict__ bias,
                                                 float* __restrict__ C,
                                                 int M, int K, int Nc) {
    __shared__ float As[16][64];
    __shared__ float Bs[16][64];

    int tid  = threadIdx.x;
    int row0 = blockIdx.y * 64;
    int col0 = blockIdx.x * 64;
    int ty   = tid >> 4;        // 0..15
    int tx   = tid & 15;        // 0..15

    int ar = tid >> 2;          // A tile row 0..63
    int ak = (tid & 3) * 4;     // A tile k start 0,4,8,12
    int bk = tid >> 4;          // B tile k 0..15
    int bc = (tid & 15) * 4;    // B tile col 0..60

    float acc[4][4];
#pragma unroll
    for (int i = 0; i < 4; i++)
#pragma unroll
        for (int j = 0; j < 4; j++) acc[i][j] = 0.f;

    int arow = row0 + ar;
    int bcol = col0 + bc;

    for (int k0 = 0; k0 < K; k0 += 16) {
        float4 av = make_float4(0.f, 0.f, 0.f, 0.f);
        if (arow < M)
            av = *(const float4*)(A + (size_t)arow * K + k0 + ak);
        As[ak + 0][ar] = av.x;
        As[ak + 1][ar] = av.y;
        As[ak + 2][ar] = av.z;
        As[ak + 3][ar] = av.w;

        float4 bv = make_float4(0.f, 0.f, 0.f, 0.f);
        if (bcol < Nc)
            bv = *(const float4*)(B + (size_t)(k0 + bk) * Nc + bcol);
        *(float4*)(&Bs[bk][bc]) = bv;

        __syncthreads();
#pragma unroll
        for (int k = 0; k < 16; k++) {
            float4 a4 = *(const float4*)(&As[k][ty * 4]);
            float4 b4 = *(const float4*)(&Bs[k][tx * 4]);
            float a[4] = {a4.x, a4.y, a4.z, a4.w};
            float b[4] = {b4.x, b4.y, b4.z, b4.w};
#pragma unroll
            for (int i = 0; i < 4; i++)
#pragma unroll
                for (int j = 0; j < 4; j++)
                    acc[i][j] = fmaf(a[i], b[j], acc[i][j]);
        }
        __syncthreads();
    }

#pragma unroll
    for (int i = 0; i < 4; i++) {
        int r = row0 + ty * 4 + i;
        if (r < M) {
#pragma unroll
            for (int j = 0; j < 4; j++) {
                int c = col0 + tx * 4 + j;
                if (c < Nc) {
                    float v = acc[i][j] + bias[c];
                    if (RELU) v = fmaxf(v, 0.f);
                    C[(size_t)r * Nc + c] = v;
                }
            }
        }
    }
}

// ---------------- batchnorm ----------------
__global__ void zero_stats_kernel() {
    g_sum[threadIdx.x]   = 0.f;
    g_sumsq[threadIdx.x] = 0.f;
}

__global__ void bn_stats_kernel() {
    int d = threadIdx.x;
    float s = 0.f, s2 = 0.f;
    for (int i = blockIdx.x; i < NN; i += gridDim.x) {
        float v = g_h[(size_t)i * DD + d];
        s  += v;
        s2 += v * v;
    }
    atomicAdd(&g_sum[d], s);
    atomicAdd(&g_sumsq[d], s2);
}

__global__ void bn_apply_kernel(const float* __restrict__ gamma,
                                const float* __restrict__ beta,
                                int relu) {
    int i = blockIdx.x * 256 + threadIdx.x;
    if (i >= NN * DD) return;
    int d = i & (DD - 1);
    const float invN = 1.f / (float)NN;
    float mu  = g_sum[d] * invN;
    float var = g_sumsq[d] * invN - mu * mu;
    float v = (g_h[i] - mu) * rsqrtf(var + 1e-5f) * gamma[d] + beta[d];
    g_h[i] = relu ? fmaxf(v, 0.f) : v;
}

// ---------------- pooling ----------------
__global__ void zero_pool_kernel() {
    int i = blockIdx.x * 256 + threadIdx.x;
    if (i < GG * DD) g_mol[i] = 0.f;
    if (i < GG) g_cnt[i] = 0.f;
}

__global__ void count_kernel(const int* __restrict__ batch) {
    int i = blockIdx.x * 256 + threadIdx.x;
    if (i < NN) atomicAdd(&g_cnt[batch[i]], 1.f);
}

__global__ void pool_scatter_kernel(const int* __restrict__ batch) {
    int n = blockIdx.x * 4 + (threadIdx.x >> 6);
    int c = threadIdx.x & 63;
    if (n >= NN) return;
    int g = batch[n];
    float4 v = ((const float4*)(g_h + (size_t)n * DD))[c];
    red_add_v4(g_mol + (size_t)g * DD + c * 4, v);
}

__global__ void pool_div_kernel() {
    int i = blockIdx.x * 256 + threadIdx.x;
    if (i >= GG * DD) return;
    g_mol[i] /= fmaxf(g_cnt[i >> 8], 1.f);
}

// ---------------- head final: out = z @ hWo + hbo, K=32 ----------------
__global__ void head_final_kernel(const float* __restrict__ w,
                                  const float* __restrict__ b,
                                  float* __restrict__ out) {
    int g = blockIdx.x * 256 + threadIdx.x;
    if (g >= GG) return;
    float acc = b[0];
#pragma unroll
    for (int k = 0; k < 32; k++)
        acc = fmaf(g_z2[g * 32 + k], w[k], acc);
    out[g] = acc;
}

// ---------------- launch ----------------
extern "C" void kernel_launch(void* const* d_in, const int* in_sizes, int n_in,
                              void* d_out, int out_size) {
    const float* x          = (const float*)d_in[0];
    const int*   edge_index = (const int*)d_in[1];
    const int*   edge_attr  = (const int*)d_in[2];
    const int*   batch      = (const int*)d_in[3];
    const float* embW       = (const float*)d_in[4];
    const float* embB       = (const float*)d_in[5];
    const float* ee1        = (const float*)d_in[6];   // (5,6,256)
    const float* ee2        = (const float*)d_in[7];   // (5,3,256)
    const float* W1         = (const float*)d_in[8];   // (5,256,512)
    const float* b1         = (const float*)d_in[9];   // (5,512)
    const float* W2         = (const float*)d_in[10];  // (5,512,256)
    const float* b2         = (const float*)d_in[11];  // (5,256)
    const float* bn_g       = (const float*)d_in[12];
    const float* bn_b       = (const float*)d_in[13];
    const float* hW0 = (const float*)d_in[14];
    const float* hb0 = (const float*)d_in[15];
    const float* hW1 = (const float*)d_in[16];
    const float* hb1 = (const float*)d_in[17];
    const float* hW2 = (const float*)d_in[18];
    const float* hb2 = (const float*)d_in[19];
    const float* hW3 = (const float*)d_in[20];
    const float* hb3 = (const float*)d_in[21];
    const float* hWo = (const float*)d_in[22];
    const float* hbo = (const float*)d_in[23];
    float* out = (float*)d_out;

    float *p_agg, *p_t, *p_h, *p_mol, *p_z1, *p_z2;
    cudaGetSymbolAddress((void**)&p_h,   g_h);
    cudaGetSymbolAddress((void**)&p_agg, g_agg);
    cudaGetSymbolAddress((void**)&p_t,   g_t);
    cudaGetSymbolAddress((void**)&p_mol, g_mol);
    cudaGetSymbolAddress((void**)&p_z1,  g_z1);
    cudaGetSymbolAddress((void**)&p_z2,  g_z2);

    const int elemGrid = (NN * DD + 255) / 256;

    // embed
    embed_kernel<<<NN, 256>>>(x, embW, embB);

    // GNN layers
    for (int l = 0; l < LL; l++) {
        const float* ee1l = ee1 + (size_t)l * 6 * DD;
        const float* ee2l = ee2 + (size_t)l * 3 * DD;
        init_agg_kernel<<<elemGrid, 256>>>(ee1l + 4 * DD, ee2l /* row 0 */);
        scatter_kernel<<<(EE + 3) / 4, 256>>>(edge_index, edge_index + EE,
                                              edge_attr, ee1l, ee2l);
        gemm_bias<1><<<dim3(8, (NN + 63) / 64), 256>>>(
            p_agg, W1 + (size_t)l * DD * 2 * DD, b1 + (size_t)l * 2 * DD,
            p_t, NN, DD, 2 * DD);
        gemm_bias<0><<<dim3(4, (NN + 63) / 64), 256>>>(
            p_t, W2 + (size_t)l * 2 * DD * DD, b2 + (size_t)l * DD,
            p_h, NN, 2 * DD, DD);
        zero_stats_kernel<<<1, 256>>>();
        bn_stats_kernel<<<512, 256>>>();
        bn_apply_kernel<<<elemGrid, 256>>>(bn_g + (size_t)l * DD,
                                           bn_b + (size_t)l * DD,
                                           (l < LL - 1) ? 1 : 0);
    }

    // pooling
    zero_pool_kernel<<<(GG * DD + 255) / 256, 256>>>();
    count_kernel<<<(NN + 255) / 256, 256>>>(batch);
    pool_scatter_kernel<<<(NN + 3) / 4, 256>>>(batch);
    pool_div_kernel<<<(GG * DD + 255) / 256, 256>>>();

    // head MLP
    gemm_bias<1><<<dim3(4, (GG + 63) / 64), 256>>>(p_mol, hW0, hb0, p_z1, GG, 256, 256);
    gemm_bias<1><<<dim3(2, (GG + 63) / 64), 256>>>(p_z1,  hW1, hb1, p_z2, GG, 256, 128);
    gemm_bias<1><<<dim3(1, (GG + 63) / 64), 256>>>(p_z2,  hW2, hb2, p_z1, GG, 128, 64);
    gemm_bias<1><<<dim3(1, (GG + 63) / 64), 256>>>(p_z1,  hW3, hb3, p_z2, GG, 64, 32);
    head_final_kernel<<<(GG + 255) / 256, 256>>>(hWo, hbo, out);
}

// round 2
// speedup vs baseline: 1.0909x; 1.0909x over previous
#include <cuda_runtime.h>
#include <cuda_bf16.h>
#include <cstdint>

#define NN 100000
#define EE 300000
#define DD 256
#define GG 4000
#define LL 5
#define F_IN 40

// ---------------- scratch (device globals: allocation-free) ----------------
__device__ float g_h[NN * DD];        // node features (current layer)
__device__ float g_agg[NN * DD];      // aggregated messages
__device__ float g_t[NN * 2 * DD];    // hidden 512 buffer
__device__ float g_sum[DD];
__device__ float g_sumsq[DD];
__device__ float g_mol[GG * DD];
__device__ float g_cnt[GG];
__device__ float g_z1[GG * DD];
__device__ float g_z2[GG * DD];

// ---------------- helpers ----------------
__device__ __forceinline__ void red_add_v4(float* addr, float4 v) {
    asm volatile("red.global.add.v4.f32 [%0], {%1,%2,%3,%4};"
                 :: "l"(addr), "f"(v.x), "f"(v.y), "f"(v.z), "f"(v.w)
                 : "memory");
}

// ---------------- embed: h = relu(x @ embW + embB), K=40 ----------------
__global__ void embed_kernel(const float* __restrict__ x,
                             const float* __restrict__ W,
                             const float* __restrict__ b) {
    int node = blockIdx.x;
    __shared__ float xs[F_IN];
    if (threadIdx.x < F_IN) xs[threadIdx.x] = x[node * F_IN + threadIdx.x];
    __syncthreads();
    int d = threadIdx.x;
    float acc = b[d];
#pragma unroll
    for (int k = 0; k < F_IN; k++)
        acc = fmaf(xs[k], W[k * DD + d], acc);
    g_h[node * DD + d] = fmaxf(acc, 0.f);
}

// ---------------- agg init: agg = h + ee1[l][4] + ee2[l][0] ----------------
__global__ void init_agg_kernel(const float* __restrict__ ee1s,
                                const float* __restrict__ ee2s) {
    int i = blockIdx.x * 256 + threadIdx.x;
    if (i >= NN * DD) return;
    int d = i & (DD - 1);
    g_agg[i] = g_h[i] + ee1s[d] + ee2s[d];
}

// ---------------- edge scatter: agg[dst] += h[src] + ee1[ea0] + ee2[ea1] ----
__global__ void scatter_kernel(const int* __restrict__ src,
                               const int* __restrict__ dst,
                               const int* __restrict__ eattr,
                               const float* __restrict__ ee1l,
                               const float* __restrict__ ee2l) {
    int e = blockIdx.x * 4 + (threadIdx.x >> 6);
    int c = threadIdx.x & 63;   // float4 chunk (64 * 4 = 256 floats)
    if (e >= EE) return;
    int s  = src[e];
    int d  = dst[e];
    int a0 = eattr[2 * e];
    int a1 = eattr[2 * e + 1];
    float4 v  = ((const float4*)(g_h + (size_t)s * DD))[c];
    float4 t1 = ((const float4*)(ee1l + a0 * DD))[c];
    float4 t2 = ((const float4*)(ee2l + a1 * DD))[c];
    v.x += t1.x + t2.x;
    v.y += t1.y + t2.y;
    v.z += t1.z + t2.z;
    v.w += t1.w + t2.w;
    red_add_v4(g_agg + (size_t)d * DD + c * 4, v);
}

// ============ big GEMM: 128x128 tile, 8x8 micro, double-buffered ============
// C[M,Nc] = A[M,K] @ B[K,Nc] + bias, optional relu.
// Requires: K % 16 == 0, Nc % 128 == 0 (true for all big calls).
template <int RELU>
__global__ void __launch_bounds__(256) gemm128(const float* __restrict__ A,
                                               const float* __restrict__ B,
                                               const float* __restrict__ bias,
                                               float* __restrict__ C,
                                               int M, int K, int Nc) {
    __shared__ float As[2][16][128];
    __shared__ float Bs[2][16][128];

    const int tid  = threadIdx.x;
    const int row0 = blockIdx.y * 128;
    const int col0 = blockIdx.x * 128;

    // A loader: each thread loads 8 consecutive k for one row
    const int ar = tid >> 1;            // 0..127
    const int ak = (tid & 1) * 8;       // 0 or 8
    const bool a_ok = (row0 + ar) < M;
    const float* Aptr = A + (size_t)(a_ok ? (row0 + ar) : 0) * K + ak;

    // B loader: each thread loads rows bk and bk+8, 4 cols
    const int bk = tid >> 5;            // 0..7
    const int bn = (tid & 31) * 4;      // 0..124
    const float* Bptr = B + (size_t)bk * Nc + col0 + bn;

    // compute mapping: 16x16 thread grid, 2x2 blocks of float4
    const int ty = tid >> 4;            // 0..15
    const int tx = tid & 15;            // 0..15

    float acc[8][8];
#pragma unroll
    for (int i = 0; i < 8; i++)
#pragma unroll
        for (int j = 0; j < 8; j++) acc[i][j] = 0.f;

    const int ktiles = K >> 4;

    // preload tile 0
    {
        float4 av0 = make_float4(0,0,0,0), av1 = make_float4(0,0,0,0);
        if (a_ok) {
            av0 = *(const float4*)(Aptr + 0);
            av1 = *(const float4*)(Aptr + 4);
        }
        As[0][ak+0][ar] = av0.x; As[0][ak+1][ar] = av0.y;
        As[0][ak+2][ar] = av0.z; As[0][ak+3][ar] = av0.w;
        As[0][ak+4][ar] = av1.x; As[0][ak+5][ar] = av1.y;
        As[0][ak+6][ar] = av1.z; As[0][ak+7][ar] = av1.w;
        float4 bv0 = *(const float4*)(Bptr);
        float4 bv1 = *(const float4*)(Bptr + (size_t)8 * Nc);
        *(float4*)(&Bs[0][bk][bn])     = bv0;
        *(float4*)(&Bs[0][bk + 8][bn]) = bv1;
    }
    __syncthreads();

    for (int kt = 0; kt < ktiles; kt++) {
        const int cbuf = kt & 1;
        const int nbuf = cbuf ^ 1;
        float4 av0, av1, bv0, bv1;
        const bool more = (kt + 1) < ktiles;
        if (more) {
            const float* Ap = Aptr + (size_t)(kt + 1) * 16;
            av0 = make_float4(0,0,0,0); av1 = make_float4(0,0,0,0);
            if (a_ok) {
                av0 = *(const float4*)(Ap + 0);
                av1 = *(const float4*)(Ap + 4);
            }
            const float* Bp = Bptr + (size_t)(kt + 1) * 16 * Nc;
            bv0 = *(const float4*)(Bp);
            bv1 = *(const float4*)(Bp + (size_t)8 * Nc);
        }

#pragma unroll
        for (int k = 0; k < 16; k++) {
            float4 a0 = *(const float4*)(&As[cbuf][k][tx * 0 + ty * 4]);
            float4 a1 = *(const float4*)(&As[cbuf][k][64 + ty * 4]);
            float4 b0 = *(const float4*)(&Bs[cbuf][k][tx * 4]);
            float4 b1 = *(const float4*)(&Bs[cbuf][k][64 + tx * 4]);
            float a[8] = {a0.x, a0.y, a0.z, a0.w, a1.x, a1.y, a1.z, a1.w};
            float b[8] = {b0.x, b0.y, b0.z, b0.w, b1.x, b1.y, b1.z, b1.w};
#pragma unroll
            for (int i = 0; i < 8; i++)
#pragma unroll
                for (int j = 0; j < 8; j++)
                    acc[i][j] = fmaf(a[i], b[j], acc[i][j]);
        }

        if (more) {
            As[nbuf][ak+0][ar] = av0.x; As[nbuf][ak+1][ar] = av0.y;
            As[nbuf][ak+2][ar] = av0.z; As[nbuf][ak+3][ar] = av0.w;
            As[nbuf][ak+4][ar] = av1.x; As[nbuf][ak+5][ar] = av1.y;
            As[nbuf][ak+6][ar] = av1.z; As[nbuf][ak+7][ar] = av1.w;
            *(float4*)(&Bs[nbuf][bk][bn])     = bv0;
            *(float4*)(&Bs[nbuf][bk + 8][bn]) = bv1;
        }
        __syncthreads();
    }

    // epilogue
    float bcol[8];
#pragma unroll
    for (int j = 0; j < 8; j++) {
        int c = col0 + (j < 4 ? tx * 4 + j : 64 + tx * 4 + j - 4);
        bcol[j] = bias[c];
    }
#pragma unroll
    for (int i = 0; i < 8; i++) {
        int r = row0 + (i < 4 ? ty * 4 + i : 64 + ty * 4 + i - 4);
        if (r < M) {
            float4 o0, o1;
            o0.x = acc[i][0] + bcol[0]; o0.y = acc[i][1] + bcol[1];
            o0.z = acc[i][2] + bcol[2]; o0.w = acc[i][3] + bcol[3];
            o1.x = acc[i][4] + bcol[4]; o1.y = acc[i][5] + bcol[5];
            o1.z = acc[i][6] + bcol[6]; o1.w = acc[i][7] + bcol[7];
            if (RELU) {
                o0.x = fmaxf(o0.x, 0.f); o0.y = fmaxf(o0.y, 0.f);
                o0.z = fmaxf(o0.z, 0.f); o0.w = fmaxf(o0.w, 0.f);
                o1.x = fmaxf(o1.x, 0.f); o1.y = fmaxf(o1.y, 0.f);
                o1.z = fmaxf(o1.z, 0.f); o1.w = fmaxf(o1.w, 0.f);
            }
            *(float4*)(C + (size_t)r * Nc + col0 + tx * 4)      = o0;
            *(float4*)(C + (size_t)r * Nc + col0 + 64 + tx * 4) = o1;
        }
    }
}

// ---------------- small GEMM (head MLP): 64x64 tile ----------------
template <int RELU>
__global__ void __launch_bounds__(256) gemm_bias(const float* __restrict__ A,
                                                 const float* __restrict__ B,
                                                 const float* __restrict__ bias,
                                                 float* __restrict__ C,
                                                 int M, int K, int Nc) {
    __shared__ float As[16][64];
    __shared__ float Bs[16][64];

    int tid  = threadIdx.x;
    int row0 = blockIdx.y * 64;
    int col0 = blockIdx.x * 64;
    int ty   = tid >> 4;
    int tx   = tid & 15;

    int ar = tid >> 2;
    int ak = (tid & 3) * 4;
    int bk = tid >> 4;
    int bc = (tid & 15) * 4;

    float acc[4][4];
#pragma unroll
    for (int i = 0; i < 4; i++)
#pragma unroll
        for (int j = 0; j < 4; j++) acc[i][j] = 0.f;

    int arow = row0 + ar;
    int bcol = col0 + bc;

    for (int k0 = 0; k0 < K; k0 += 16) {
        float4 av = make_float4(0.f, 0.f, 0.f, 0.f);
        if (arow < M)
            av = *(const float4*)(A + (size_t)arow * K + k0 + ak);
        As[ak + 0][ar] = av.x;
        As[ak + 1][ar] = av.y;
        As[ak + 2][ar] = av.z;
        As[ak + 3][ar] = av.w;

        float4 bv = make_float4(0.f, 0.f, 0.f, 0.f);
        if (bcol < Nc)
            bv = *(const float4*)(B + (size_t)(k0 + bk) * Nc + bcol);
        *(float4*)(&Bs[bk][bc]) = bv;

        __syncthreads();
#pragma unroll
        for (int k = 0; k < 16; k++) {
            float4 a4 = *(const float4*)(&As[k][ty * 4]);
            float4 b4 = *(const float4*)(&Bs[k][tx * 4]);
            float a[4] = {a4.x, a4.y, a4.z, a4.w};
            float b[4] = {b4.x, b4.y, b4.z, b4.w};
#pragma unroll
            for (int i = 0; i < 4; i++)
#pragma unroll
                for (int j = 0; j < 4; j++)
                    acc[i][j] = fmaf(a[i], b[j], acc[i][j]);
        }
        __syncthreads();
    }

#pragma unroll
    for (int i = 0; i < 4; i++) {
        int r = row0 + ty * 4 + i;
        if (r < M) {
#pragma unroll
            for (int j = 0; j < 4; j++) {
                int c = col0 + tx * 4 + j;
                if (c < Nc) {
                    float v = acc[i][j] + bias[c];
                    if (RELU) v = fmaxf(v, 0.f);
                    C[(size_t)r * Nc + c] = v;
                }
            }
        }
    }
}

// ---------------- batchnorm ----------------
__global__ void zero_stats_kernel() {
    g_sum[threadIdx.x]   = 0.f;
    g_sumsq[threadIdx.x] = 0.f;
}

__global__ void bn_stats_kernel() {
    int d = threadIdx.x;
    float s = 0.f, s2 = 0.f;
    for (int i = blockIdx.x; i < NN; i += gridDim.x) {
        float v = g_h[(size_t)i * DD + d];
        s  += v;
        s2 += v * v;
    }
    atomicAdd(&g_sum[d], s);
    atomicAdd(&g_sumsq[d], s2);
}

// bn apply + relu, fused with next-layer agg init (agg = h + ee1n + ee2n)
__global__ void bn_apply_fused_kernel(const float* __restrict__ gamma,
                                      const float* __restrict__ beta,
                                      int relu,
                                      const float* __restrict__ ee1n,
                                      const float* __restrict__ ee2n,
                                      int write_agg) {
    int i = blockIdx.x * 256 + threadIdx.x;
    if (i >= NN * DD) return;
    int d = i & (DD - 1);
    const float invN = 1.f / (float)NN;
    float mu  = g_sum[d] * invN;
    float var = g_sumsq[d] * invN - mu * mu;
    float v = (g_h[i] - mu) * rsqrtf(var + 1e-5f) * gamma[d] + beta[d];
    if (relu) v = fmaxf(v, 0.f);
    g_h[i] = v;
    if (write_agg) g_agg[i] = v + ee1n[d] + ee2n[d];
}

// ---------------- pooling ----------------
__global__ void zero_pool_kernel() {
    int i = blockIdx.x * 256 + threadIdx.x;
    if (i < GG * DD) g_mol[i] = 0.f;
    if (i < GG) g_cnt[i] = 0.f;
}

__global__ void count_kernel(const int* __restrict__ batch) {
    int i = blockIdx.x * 256 + threadIdx.x;
    if (i < NN) atomicAdd(&g_cnt[batch[i]], 1.f);
}

__global__ void pool_scatter_kernel(const int* __restrict__ batch) {
    int n = blockIdx.x * 4 + (threadIdx.x >> 6);
    int c = threadIdx.x & 63;
    if (n >= NN) return;
    int g = batch[n];
    float4 v = ((const float4*)(g_h + (size_t)n * DD))[c];
    red_add_v4(g_mol + (size_t)g * DD + c * 4, v);
}

__global__ void pool_div_kernel() {
    int i = blockIdx.x * 256 + threadIdx.x;
    if (i >= GG * DD) return;
    g_mol[i] /= fmaxf(g_cnt[i >> 8], 1.f);
}

// ---------------- head final: out = z @ hWo + hbo, K=32 ----------------
__global__ void head_final_kernel(const float* __restrict__ w,
                                  const float* __restrict__ b,
                                  float* __restrict__ out) {
    int g = blockIdx.x * 256 + threadIdx.x;
    if (g >= GG) return;
    float acc = b[0];
#pragma unroll
    for (int k = 0; k < 32; k++)
        acc = fmaf(g_z2[g * 32 + k], w[k], acc);
    out[g] = acc;
}

// ---------------- launch ----------------
extern "C" void kernel_launch(void* const* d_in, const int* in_sizes, int n_in,
                              void* d_out, int out_size) {
    const float* x          = (const float*)d_in[0];
    const int*   edge_index = (const int*)d_in[1];
    const int*   edge_attr  = (const int*)d_in[2];
    const int*   batch      = (const int*)d_in[3];
    const float* embW       = (const float*)d_in[4];
    const float* embB       = (const float*)d_in[5];
    const float* ee1        = (const float*)d_in[6];   // (5,6,256)
    const float* ee2        = (const float*)d_in[7];   // (5,3,256)
    const float* W1         = (const float*)d_in[8];   // (5,256,512)
    const float* b1         = (const float*)d_in[9];   // (5,512)
    const float* W2         = (const float*)d_in[10];  // (5,512,256)
    const float* b2         = (const float*)d_in[11];  // (5,256)
    const float* bn_g       = (const float*)d_in[12];
    const float* bn_b       = (const float*)d_in[13];
    const float* hW0 = (const float*)d_in[14];
    const float* hb0 = (const float*)d_in[15];
    const float* hW1 = (const float*)d_in[16];
    const float* hb1 = (const float*)d_in[17];
    const float* hW2 = (const float*)d_in[18];
    const float* hb2 = (const float*)d_in[19];
    const float* hW3 = (const float*)d_in[20];
    const float* hb3 = (const float*)d_in[21];
    const float* hWo = (const float*)d_in[22];
    const float* hbo = (const float*)d_in[23];
    float* out = (float*)d_out;

    float *p_agg, *p_t, *p_h, *p_mol, *p_z1, *p_z2;
    cudaGetSymbolAddress((void**)&p_h,   g_h);
    cudaGetSymbolAddress((void**)&p_agg, g_agg);
    cudaGetSymbolAddress((void**)&p_t,   g_t);
    cudaGetSymbolAddress((void**)&p_mol, g_mol);
    cudaGetSymbolAddress((void**)&p_z1,  g_z1);
    cudaGetSymbolAddress((void**)&p_z2,  g_z2);

    const int elemGrid = (NN * DD + 255) / 256;
    const int rowBlocks = (NN + 127) / 128;

    // embed
    embed_kernel<<<NN, 256>>>(x, embW, embB);

    // layer-0 agg init (later layers fused into bn_apply)
    init_agg_kernel<<<elemGrid, 256>>>(ee1 + 4 * DD, ee2);

    // GNN layers
    for (int l = 0; l < LL; l++) {
        const float* ee1l = ee1 + (size_t)l * 6 * DD;
        const float* ee2l = ee2 + (size_t)l * 3 * DD;
        scatter_kernel<<<(EE + 3) / 4, 256>>>(edge_index, edge_index + EE,
                                              edge_attr, ee1l, ee2l);
        gemm128<1><<<dim3(4, rowBlocks), 256>>>(
            p_agg, W1 + (size_t)l * DD * 2 * DD, b1 + (size_t)l * 2 * DD,
            p_t, NN, DD, 2 * DD);
        gemm128<0><<<dim3(2, rowBlocks), 256>>>(
            p_t, W2 + (size_t)l * 2 * DD * DD, b2 + (size_t)l * DD,
            p_h, NN, 2 * DD, DD);
        zero_stats_kernel<<<1, 256>>>();
        bn_stats_kernel<<<512, 256>>>();
        int last = (l == LL - 1);
        const float* ee1n = ee1 + (size_t)(l + 1) * 6 * DD + 4 * DD;
        const float* ee2n = ee2 + (size_t)(l + 1) * 3 * DD;
        bn_apply_fused_kernel<<<elemGrid, 256>>>(
            bn_g + (size_t)l * DD, bn_b + (size_t)l * DD,
            last ? 0 : 1,
            last ? (ee1) : ee1n, last ? (ee2) : ee2n,  // dummy ptrs when last
            last ? 0 : 1);
    }

    // pooling
    zero_pool_kernel<<<(GG * DD + 255) / 256, 256>>>();
    count_kernel<<<(NN + 255) / 256, 256>>>(batch);
    pool_scatter_kernel<<<(NN + 3) / 4, 256>>>(batch);
    pool_div_kernel<<<(GG * DD + 255) / 256, 256>>>();

    // head MLP
    gemm_bias<1><<<dim3(4, (GG + 63) / 64), 256>>>(p_mol, hW0, hb0, p_z1, GG, 256, 256);
    gemm_bias<1><<<dim3(2, (GG + 63) / 64), 256>>>(p_z1,  hW1, hb1, p_z2, GG, 256, 128);
    gemm_bias<1><<<dim3(1, (GG + 63) / 64), 256>>>(p_z2,  hW2, hb2, p_z1, GG, 128, 64);
    gemm_bias<1><<<dim3(1, (GG + 63) / 64), 256>>>(p_z1,  hW3, hb3, p_z2, GG, 64, 32);
    head_final_kernel<<<(GG + 255) / 256, 256>>>(hWo, hbo, out);
}

// round 3
// speedup vs baseline: 1.9390x; 1.7775x over previous
#include <cuda_runtime.h>
#include <cuda_bf16.h>
#include <cstdint>

#define NN 100000
#define EE 300000
#define DD 256
#define GG 4000
#define LL 5
#define F_IN 40

// ---------------- scratch (device globals: allocation-free) ----------------
__device__ float g_h[NN * DD];
__device__ float g_agg[NN * DD];
__device__ float g_t[NN * 2 * DD];
__device__ float g_sum[DD];
__device__ float g_sumsq[DD];
__device__ float g_mol[GG * DD];
__device__ float g_cnt[GG];
__device__ float g_z1[GG * DD];
__device__ float g_z2[GG * DD];

// ---------------- helpers ----------------
__device__ __forceinline__ void red_add_v4(float* addr, float4 v) {
    asm volatile("red.global.add.v4.f32 [%0], {%1,%2,%3,%4};"
                 :: "l"(addr), "f"(v.x), "f"(v.y), "f"(v.z), "f"(v.w)
                 : "memory");
}

__device__ __forceinline__ void ldsm4(uint32_t r[4], uint32_t addr) {
    asm volatile("ldmatrix.sync.aligned.m8n8.x4.shared.b16 {%0,%1,%2,%3}, [%4];"
        : "=r"(r[0]), "=r"(r[1]), "=r"(r[2]), "=r"(r[3]) : "r"(addr));
}
__device__ __forceinline__ void ldsm4t(uint32_t r[4], uint32_t addr) {
    asm volatile("ldmatrix.sync.aligned.m8n8.x4.trans.shared.b16 {%0,%1,%2,%3}, [%4];"
        : "=r"(r[0]), "=r"(r[1]), "=r"(r[2]), "=r"(r[3]) : "r"(addr));
}
__device__ __forceinline__ void mma16816(float c[4], const uint32_t a[4],
                                         uint32_t b0, uint32_t b1) {
    asm volatile("mma.sync.aligned.m16n8k16.row.col.f32.bf16.bf16.f32 "
        "{%0,%1,%2,%3}, {%4,%5,%6,%7}, {%8,%9}, {%0,%1,%2,%3};"
        : "+f"(c[0]), "+f"(c[1]), "+f"(c[2]), "+f"(c[3])
        : "r"(a[0]), "r"(a[1]), "r"(a[2]), "r"(a[3]), "r"(b0), "r"(b1));
}

// split two fp32 into bf16 hi pair + bf16 lo pair (packed)
__device__ __forceinline__ void split2(float f0, float f1,
                                       uint32_t& h, uint32_t& l) {
    __nv_bfloat16 h0 = __float2bfloat16(f0);
    __nv_bfloat16 h1 = __float2bfloat16(f1);
    float r0 = f0 - __bfloat162float(h0);
    float r1 = f1 - __bfloat162float(h1);
    __nv_bfloat162 hp(h0, h1);
    __nv_bfloat162 lp(__float2bfloat16(r0), __float2bfloat16(r1));
    h = *reinterpret_cast<uint32_t*>(&hp);
    l = *reinterpret_cast<uint32_t*>(&lp);
}

// ---------------- embed: h = relu(x @ embW + embB), K=40 ----------------
__global__ void embed_kernel(const float* __restrict__ x,
                             const float* __restrict__ W,
                             const float* __restrict__ b) {
    int node = blockIdx.x;
    __shared__ float xs[F_IN];
    if (threadIdx.x < F_IN) xs[threadIdx.x] = x[node * F_IN + threadIdx.x];
    __syncthreads();
    int d = threadIdx.x;
    float acc = b[d];
#pragma unroll
    for (int k = 0; k < F_IN; k++)
        acc = fmaf(xs[k], W[k * DD + d], acc);
    g_h[node * DD + d] = fmaxf(acc, 0.f);
}

// ---------------- agg init ----------------
__global__ void init_agg_kernel(const float* __restrict__ ee1s,
                                const float* __restrict__ ee2s) {
    int i = blockIdx.x * 256 + threadIdx.x;
    if (i >= NN * DD) return;
    int d = i & (DD - 1);
    g_agg[i] = g_h[i] + ee1s[d] + ee2s[d];
}

// ---------------- edge scatter ----------------
__global__ void scatter_kernel(const int* __restrict__ src,
                               const int* __restrict__ dst,
                               const int* __restrict__ eattr,
                               const float* __restrict__ ee1l,
                               const float* __restrict__ ee2l) {
    int e = blockIdx.x * 4 + (threadIdx.x >> 6);
    int c = threadIdx.x & 63;
    if (e >= EE) return;
    int s  = src[e];
    int d  = dst[e];
    int a0 = eattr[2 * e];
    int a1 = eattr[2 * e + 1];
    float4 v  = ((const float4*)(g_h + (size_t)s * DD))[c];
    float4 t1 = ((const float4*)(ee1l + a0 * DD))[c];
    float4 t2 = ((const float4*)(ee2l + a1 * DD))[c];
    v.x += t1.x + t2.x;
    v.y += t1.y + t2.y;
    v.z += t1.z + t2.z;
    v.w += t1.w + t2.w;
    red_add_v4(g_agg + (size_t)d * DD + c * 4, v);
}

// ============ tensor-core GEMM, bf16 3-way split emulating fp32 ============
// C[M,Nc] = A[M,K] @ B[K,Nc] + bias (opt relu). K%32==0, Nc%128==0.
// Tile 128x128x32, 256 threads (8 warps: 4 along m, 2 along n).
// smem planes (32KB): AH[128x32 bf16] AL BH[32x128 bf16] BL
#define OFF_AH 0
#define OFF_AL 8192
#define OFF_BH 16384
#define OFF_BL 24576

template <int RELU>
__global__ void __launch_bounds__(256) gemm_tc(const float* __restrict__ A,
                                               const float* __restrict__ B,
                                               const float* __restrict__ bias,
                                               float* __restrict__ C,
                                               int M, int K, int Nc) {
    __shared__ __align__(1024) char sm[32768];
    const int tid  = threadIdx.x;
    const int lane = tid & 31;
    const int warp = tid >> 5;
    const int wm   = warp >> 1;   // 0..3
    const int wn   = warp & 1;    // 0..1
    const int row0 = blockIdx.y * 128;
    const int col0 = blockIdx.x * 128;

    // ---- loader mapping ----
    const int am   = tid >> 1;              // A row 0..127
    const int akb  = (tid & 1) * 16;        // A k base 0/16
    const bool aok = (row0 + am) < M;
    const float* Ap = A + (size_t)(aok ? row0 + am : 0) * K + akb;

    const int bkr  = tid >> 3;              // B k row 0..31
    const int bnb  = (tid & 7) * 16;        // B n base
    const float* Bp = B + (size_t)bkr * Nc + col0 + bnb;

    // swizzled smem byte offsets for stores (chunk0, chunk1 of hi/lo)
    const uint32_t aso0 = (uint32_t)(am * 64 + (akb + 0) * 2) ^ ((am & 6) << 3);
    const uint32_t aso1 = (uint32_t)(am * 64 + (akb + 8) * 2) ^ ((am & 6) << 3);
    const uint32_t bso0 = (uint32_t)(bkr * 256 + (bnb + 0) * 2) ^ ((bkr & 7) << 4);
    const uint32_t bso1 = (uint32_t)(bkr * 256 + (bnb + 8) * 2) ^ ((bkr & 7) << 4);

    uint32_t smbase;
    asm("{ .reg .u64 t; cvta.to.shared.u64 t, %1; cvt.u32.u64 %0, t; }"
        : "=r"(smbase) : "l"(sm));

    float acc[2][8][4];
#pragma unroll
    for (int mi = 0; mi < 2; mi++)
#pragma unroll
        for (int nt = 0; nt < 8; nt++)
#pragma unroll
            for (int q = 0; q < 4; q++) acc[mi][nt][q] = 0.f;

    const int ktiles = K >> 5;

    float4 afr[4], bfr[4];
    // preload tile 0
    {
        if (aok) {
#pragma unroll
            for (int i = 0; i < 4; i++) afr[i] = *(const float4*)(Ap + i * 4);
        } else {
#pragma unroll
            for (int i = 0; i < 4; i++) afr[i] = make_float4(0, 0, 0, 0);
        }
#pragma unroll
        for (int i = 0; i < 4; i++) bfr[i] = *(const float4*)(Bp + i * 4);
    }

    for (int kt = 0; kt < ktiles; kt++) {
        __syncthreads();   // previous compute done reading smem
        // ---- convert + store staged tile ----
        {
            uint4 h, l;
            split2(afr[0].x, afr[0].y, h.x, l.x);
            split2(afr[0].z, afr[0].w, h.y, l.y);
            split2(afr[1].x, afr[1].y, h.z, l.z);
            split2(afr[1].z, afr[1].w, h.w, l.w);
            *(uint4*)(sm + OFF_AH + aso0) = h;
            *(uint4*)(sm + OFF_AL + aso0) = l;
            split2(afr[2].x, afr[2].y, h.x, l.x);
            split2(afr[2].z, afr[2].w, h.y, l.y);
            split2(afr[3].x, afr[3].y, h.z, l.z);
            split2(afr[3].z, afr[3].w, h.w, l.w);
            *(uint4*)(sm + OFF_AH + aso1) = h;
            *(uint4*)(sm + OFF_AL + aso1) = l;

            split2(bfr[0].x, bfr[0].y, h.x, l.x);
            split2(bfr[0].z, bfr[0].w, h.y, l.y);
            split2(bfr[1].x, bfr[1].y, h.z, l.z);
            split2(bfr[1].z, bfr[1].w, h.w, l.w);
            *(uint4*)(sm + OFF_BH + bso0) = h;
            *(uint4*)(sm + OFF_BL + bso0) = l;
            split2(bfr[2].x, bfr[2].y, h.x, l.x);
            split2(bfr[2].z, bfr[2].w, h.y, l.y);
            split2(bfr[3].x, bfr[3].y, h.z, l.z);
            split2(bfr[3].z, bfr[3].w, h.w, l.w);
            *(uint4*)(sm + OFF_BH + bso1) = h;
            *(uint4*)(sm + OFF_BL + bso1) = l;
        }
        __syncthreads();

        // ---- prefetch next tile (overlaps with mma below) ----
        if (kt + 1 < ktiles) {
            const float* ap = Ap + (kt + 1) * 32;
            if (aok) {
#pragma unroll
                for (int i = 0; i < 4; i++) afr[i] = *(const float4*)(ap + i * 4);
            }
            const float* bp = Bp + (size_t)(kt + 1) * 32 * Nc;
#pragma unroll
            for (int i = 0; i < 4; i++) bfr[i] = *(const float4*)(bp + i * 4);
        }

        // ---- compute: 2 k16 steps ----
#pragma unroll
        for (int ks = 0; ks < 2; ks++) {
            uint32_t a_h[2][4], a_l[2][4];
#pragma unroll
            for (int mi = 0; mi < 2; mi++) {
                int m = wm * 32 + mi * 16 + (lane & 15);
                int k = ks * 16 + (lane >> 4) * 8;
                uint32_t byte = (uint32_t)(m * 64 + k * 2) ^ ((m & 6) << 3);
                ldsm4(a_h[mi], smbase + OFF_AH + byte);
                ldsm4(a_l[mi], smbase + OFF_AL + byte);
            }
#pragma unroll
            for (int nj = 0; nj < 4; nj++) {
                int k = ks * 16 + (lane & 15);
                int n = wn * 64 + nj * 16 + (lane >> 4) * 8;
                uint32_t byte = (uint32_t)(k * 256 + n * 2) ^ ((k & 7) << 4);
                uint32_t bh[4], bl[4];
                ldsm4t(bh, smbase + OFF_BH + byte);
                ldsm4t(bl, smbase + OFF_BL + byte);
#pragma unroll
                for (int mi = 0; mi < 2; mi++) {
                    mma16816(acc[mi][2 * nj],     a_h[mi], bh[0], bh[1]);
                    mma16816(acc[mi][2 * nj],     a_h[mi], bl[0], bl[1]);
                    mma16816(acc[mi][2 * nj],     a_l[mi], bh[0], bh[1]);
                    mma16816(acc[mi][2 * nj + 1], a_h[mi], bh[2], bh[3]);
                    mma16816(acc[mi][2 * nj + 1], a_h[mi], bl[2], bl[3]);
                    mma16816(acc[mi][2 * nj + 1], a_l[mi], bh[2], bh[3]);
                }
            }
        }
    }

    // ---- epilogue ----
#pragma unroll
    for (int mi = 0; mi < 2; mi++) {
        int r0 = row0 + wm * 32 + mi * 16 + (lane >> 2);
#pragma unroll
        for (int nt = 0; nt < 8; nt++) {
            int c = col0 + wn * 64 + nt * 8 + (lane & 3) * 2;
            float2 bv = *(const float2*)(bias + c);
            float* a4 = acc[mi][nt];
            float2 o0, o1;
            o0.x = a4[0] + bv.x; o0.y = a4[1] + bv.y;
            o1.x = a4[2] + bv.x; o1.y = a4[3] + bv.y;
            if (RELU) {
                o0.x = fmaxf(o0.x, 0.f); o0.y = fmaxf(o0.y, 0.f);
                o1.x = fmaxf(o1.x, 0.f); o1.y = fmaxf(o1.y, 0.f);
            }
            if (r0 < M)     *(float2*)(C + (size_t)r0 * Nc + c)       = o0;
            if (r0 + 8 < M) *(float2*)(C + (size_t)(r0 + 8) * Nc + c) = o1;
        }
    }
}

// ---------------- small GEMM (head MLP): 64x64 tile ----------------
template <int RELU>
__global__ void __launch_bounds__(256) gemm_bias(const float* __restrict__ A,
                                                 const float* __restrict__ B,
                                                 const float* __restrict__ bias,
                                                 float* __restrict__ C,
                                                 int M, int K, int Nc) {
    __shared__ float As[16][64];
    __shared__ float Bs[16][64];

    int tid  = threadIdx.x;
    int row0 = blockIdx.y * 64;
    int col0 = blockIdx.x * 64;
    int ty   = tid >> 4;
    int tx   = tid & 15;

    int ar = tid >> 2;
    int ak = (tid & 3) * 4;
    int bk = tid >> 4;
    int bc = (tid & 15) * 4;

    float acc[4][4];
#pragma unroll
    for (int i = 0; i < 4; i++)
#pragma unroll
        for (int j = 0; j < 4; j++) acc[i][j] = 0.f;

    int arow = row0 + ar;
    int bcol = col0 + bc;

    for (int k0 = 0; k0 < K; k0 += 16) {
        float4 av = make_float4(0.f, 0.f, 0.f, 0.f);
        if (arow < M)
            av = *(const float4*)(A + (size_t)arow * K + k0 + ak);
        As[ak + 0][ar] = av.x;
        As[ak + 1][ar] = av.y;
        As[ak + 2][ar] = av.z;
        As[ak + 3][ar] = av.w;

        float4 bv = make_float4(0.f, 0.f, 0.f, 0.f);
        if (bcol < Nc)
            bv = *(const float4*)(B + (size_t)(k0 + bk) * Nc + bcol);
        *(float4*)(&Bs[bk][bc]) = bv;

        __syncthreads();
#pragma unroll
        for (int k = 0; k < 16; k++) {
            float4 a4 = *(const float4*)(&As[k][ty * 4]);
            float4 b4 = *(const float4*)(&Bs[k][tx * 4]);
            float a[4] = {a4.x, a4.y, a4.z, a4.w};
            float b[4] = {b4.x, b4.y, b4.z, b4.w};
#pragma unroll
            for (int i = 0; i < 4; i++)
#pragma unroll
                for (int j = 0; j < 4; j++)
                    acc[i][j] = fmaf(a[i], b[j], acc[i][j]);
        }
        __syncthreads();
    }

#pragma unroll
    for (int i = 0; i < 4; i++) {
        int r = row0 + ty * 4 + i;
        if (r < M) {
#pragma unroll
            for (int j = 0; j < 4; j++) {
                int c = col0 + tx * 4 + j;
                if (c < Nc) {
                    float v = acc[i][j] + bias[c];
                    if (RELU) v = fmaxf(v, 0.f);
                    C[(size_t)r * Nc + c] = v;
                }
            }
        }
    }
}

// ---------------- batchnorm ----------------
__global__ void zero_stats_kernel() {
    g_sum[threadIdx.x]   = 0.f;
    g_sumsq[threadIdx.x] = 0.f;
}

__global__ void bn_stats_kernel() {
    int d = threadIdx.x;
    float s = 0.f, s2 = 0.f;
    for (int i = blockIdx.x; i < NN; i += gridDim.x) {
        float v = g_h[(size_t)i * DD + d];
        s  += v;
        s2 += v * v;
    }
    atomicAdd(&g_sum[d], s);
    atomicAdd(&g_sumsq[d], s2);
}

__global__ void bn_apply_fused_kernel(const float* __restrict__ gamma,
                                      const float* __restrict__ beta,
                                      int relu,
                                      const float* __restrict__ ee1n,
                                      const float* __restrict__ ee2n,
                                      int write_agg) {
    int i = blockIdx.x * 256 + threadIdx.x;
    if (i >= NN * DD) return;
    int d = i & (DD - 1);
    const float invN = 1.f / (float)NN;
    float mu  = g_sum[d] * invN;
    float var = g_sumsq[d] * invN - mu * mu;
    float v = (g_h[i] - mu) * rsqrtf(var + 1e-5f) * gamma[d] + beta[d];
    if (relu) v = fmaxf(v, 0.f);
    g_h[i] = v;
    if (write_agg) g_agg[i] = v + ee1n[d] + ee2n[d];
}

// ---------------- pooling ----------------
__global__ void zero_pool_kernel() {
    int i = blockIdx.x * 256 + threadIdx.x;
    if (i < GG * DD) g_mol[i] = 0.f;
    if (i < GG) g_cnt[i] = 0.f;
}

__global__ void count_kernel(const int* __restrict__ batch) {
    int i = blockIdx.x * 256 + threadIdx.x;
    if (i < NN) atomicAdd(&g_cnt[batch[i]], 1.f);
}

__global__ void pool_scatter_kernel(const int* __restrict__ batch) {
    int n = blockIdx.x * 4 + (threadIdx.x >> 6);
    int c = threadIdx.x & 63;
    if (n >= NN) return;
    int g = batch[n];
    float4 v = ((const float4*)(g_h + (size_t)n * DD))[c];
    red_add_v4(g_mol + (size_t)g * DD + c * 4, v);
}

__global__ void pool_div_kernel() {
    int i = blockIdx.x * 256 + threadIdx.x;
    if (i >= GG * DD) return;
    g_mol[i] /= fmaxf(g_cnt[i >> 8], 1.f);
}

// ---------------- head final ----------------
__global__ void head_final_kernel(const float* __restrict__ w,
                                  const float* __restrict__ b,
                                  float* __restrict__ out) {
    int g = blockIdx.x * 256 + threadIdx.x;
    if (g >= GG) return;
    float acc = b[0];
#pragma unroll
    for (int k = 0; k < 32; k++)
        acc = fmaf(g_z2[g * 32 + k], w[k], acc);
    out[g] = acc;
}

// ---------------- launch ----------------
extern "C" void kernel_launch(void* const* d_in, const int* in_sizes, int n_in,
                              void* d_out, int out_size) {
    const float* x          = (const float*)d_in[0];
    const int*   edge_index = (const int*)d_in[1];
    const int*   edge_attr  = (const int*)d_in[2];
    const int*   batch      = (const int*)d_in[3];
    const float* embW       = (const float*)d_in[4];
    const float* embB       = (const float*)d_in[5];
    const float* ee1        = (const float*)d_in[6];
    const float* ee2        = (const float*)d_in[7];
    const float* W1         = (const float*)d_in[8];
    const float* b1         = (const float*)d_in[9];
    const float* W2         = (const float*)d_in[10];
    const float* b2         = (const float*)d_in[11];
    const float* bn_g       = (const float*)d_in[12];
    const float* bn_b       = (const float*)d_in[13];
    const float* hW0 = (const float*)d_in[14];
    const float* hb0 = (const float*)d_in[15];
    const float* hW1 = (const float*)d_in[16];
    const float* hb1 = (const float*)d_in[17];
    const float* hW2 = (const float*)d_in[18];
    const float* hb2 = (const float*)d_in[19];
    const float* hW3 = (const float*)d_in[20];
    const float* hb3 = (const float*)d_in[21];
    const float* hWo = (const float*)d_in[22];
    const float* hbo = (const float*)d_in[23];
    float* out = (float*)d_out;

    float *p_agg, *p_t, *p_h, *p_mol, *p_z1, *p_z2;
    cudaGetSymbolAddress((void**)&p_h,   g_h);
    cudaGetSymbolAddress((void**)&p_agg, g_agg);
    cudaGetSymbolAddress((void**)&p_t,   g_t);
    cudaGetSymbolAddress((void**)&p_mol, g_mol);
    cudaGetSymbolAddress((void**)&p_z1,  g_z1);
    cudaGetSymbolAddress((void**)&p_z2,  g_z2);

    const int elemGrid = (NN * DD + 255) / 256;
    const int rowBlocks = (NN + 127) / 128;

    embed_kernel<<<NN, 256>>>(x, embW, embB);
    init_agg_kernel<<<elemGrid, 256>>>(ee1 + 4 * DD, ee2);

    for (int l = 0; l < LL; l++) {
        const float* ee1l = ee1 + (size_t)l * 6 * DD;
        const float* ee2l = ee2 + (size_t)l * 3 * DD;
        scatter_kernel<<<(EE + 3) / 4, 256>>>(edge_index, edge_index + EE,
                                              edge_attr, ee1l, ee2l);
        gemm_tc<1><<<dim3(4, rowBlocks), 256>>>(
            p_agg, W1 + (size_t)l * DD * 2 * DD, b1 + (size_t)l * 2 * DD,
            p_t, NN, DD, 2 * DD);
        gemm_tc<0><<<dim3(2, rowBlocks), 256>>>(
            p_t, W2 + (size_t)l * 2 * DD * DD, b2 + (size_t)l * DD,
            p_h, NN, 2 * DD, DD);
        zero_stats_kernel<<<1, 256>>>();
        bn_stats_kernel<<<512, 256>>>();
        int last = (l == LL - 1);
        const float* ee1n = ee1 + (size_t)(l + 1) * 6 * DD + 4 * DD;
        const float* ee2n = ee2 + (size_t)(l + 1) * 3 * DD;
        bn_apply_fused_kernel<<<elemGrid, 256>>>(
            bn_g + (size_t)l * DD, bn_b + (size_t)l * DD,
            last ? 0 : 1,
            last ? ee1 : ee1n, last ? ee2 : ee2n,
            last ? 0 : 1);
    }

    zero_pool_kernel<<<(GG * DD + 255) / 256, 256>>>();
    count_kernel<<<(NN + 255) / 256, 256>>>(batch);
    pool_scatter_kernel<<<(NN + 3) / 4, 256>>>(batch);
    pool_div_kernel<<<(GG * DD + 255) / 256, 256>>>();

    gemm_bias<1><<<dim3(4, (GG + 63) / 64), 256>>>(p_mol, hW0, hb0, p_z1, GG, 256, 256);
    gemm_bias<1><<<dim3(2, (GG + 63) / 64), 256>>>(p_z1,  hW1, hb1, p_z2, GG, 256, 128);
    gemm_bias<1><<<dim3(1, (GG + 63) / 64), 256>>>(p_z2,  hW2, hb2, p_z1, GG, 128, 64);
    gemm_bias<1><<<dim3(1, (GG + 63) / 64), 256>>>(p_z1,  hW3, hb3, p_z2, GG, 64, 32);
    head_final_kernel<<<(GG + 255) / 256, 256>>>(hWo, hbo, out);
}

// round 4
// speedup vs baseline: 1.9675x; 1.0147x over previous
#include <cuda_runtime.h>
#include <cuda_bf16.h>
#include <cstdint>

#define NN 100000
#define EE 300000
#define DD 256
#define GG 4000
#define LL 5
#define F_IN 40

// ---------------- scratch (device globals: allocation-free) ----------------
__device__ float g_h[NN * DD];
__device__ float g_agg[NN * DD];
__device__ float g_t[NN * 2 * DD];
__device__ float g_sum[DD];
__device__ float g_sumsq[DD];
__device__ float g_mol[GG * DD];
__device__ float g_cnt[GG];
__device__ float g_z1[GG * DD];
__device__ float g_z2[GG * DD];

// ---------------- helpers ----------------
__device__ __forceinline__ void red_add_v4(float* addr, float4 v) {
    asm volatile("red.global.add.v4.f32 [%0], {%1,%2,%3,%4};"
                 :: "l"(addr), "f"(v.x), "f"(v.y), "f"(v.z), "f"(v.w)
                 : "memory");
}

__device__ __forceinline__ void ldsm4(uint32_t r[4], uint32_t addr) {
    asm volatile("ldmatrix.sync.aligned.m8n8.x4.shared.b16 {%0,%1,%2,%3}, [%4];"
        : "=r"(r[0]), "=r"(r[1]), "=r"(r[2]), "=r"(r[3]) : "r"(addr));
}
__device__ __forceinline__ void ldsm4t(uint32_t r[4], uint32_t addr) {
    asm volatile("ldmatrix.sync.aligned.m8n8.x4.trans.shared.b16 {%0,%1,%2,%3}, [%4];"
        : "=r"(r[0]), "=r"(r[1]), "=r"(r[2]), "=r"(r[3]) : "r"(addr));
}
__device__ __forceinline__ void mma16816(float c[4], const uint32_t a[4],
                                         uint32_t b0, uint32_t b1) {
    asm volatile("mma.sync.aligned.m16n8k16.row.col.f32.bf16.bf16.f32 "
        "{%0,%1,%2,%3}, {%4,%5,%6,%7}, {%8,%9}, {%0,%1,%2,%3};"
        : "+f"(c[0]), "+f"(c[1]), "+f"(c[2]), "+f"(c[3])
        : "r"(a[0]), "r"(a[1]), "r"(a[2]), "r"(a[3]), "r"(b0), "r"(b1));
}

// split two fp32 into bf16 hi pair + bf16 lo pair (packed)
__device__ __forceinline__ void split2(float f0, float f1,
                                       uint32_t& h, uint32_t& l) {
    __nv_bfloat16 h0 = __float2bfloat16(f0);
    __nv_bfloat16 h1 = __float2bfloat16(f1);
    float r0 = f0 - __bfloat162float(h0);
    float r1 = f1 - __bfloat162float(h1);
    __nv_bfloat162 hp(h0, h1);
    __nv_bfloat162 lp(__float2bfloat16(r0), __float2bfloat16(r1));
    h = *reinterpret_cast<uint32_t*>(&hp);
    l = *reinterpret_cast<uint32_t*>(&lp);
}

// ---------------- embed ----------------
__global__ void embed_kernel(const float* __restrict__ x,
                             const float* __restrict__ W,
                             const float* __restrict__ b) {
    int node = blockIdx.x;
    __shared__ float xs[F_IN];
    if (threadIdx.x < F_IN) xs[threadIdx.x] = x[node * F_IN + threadIdx.x];
    __syncthreads();
    int d = threadIdx.x;
    float acc = b[d];
#pragma unroll
    for (int k = 0; k < F_IN; k++)
        acc = fmaf(xs[k], W[k * DD + d], acc);
    g_h[node * DD + d] = fmaxf(acc, 0.f);
}

// ---------------- agg init ----------------
__global__ void init_agg_kernel(const float* __restrict__ ee1s,
                                const float* __restrict__ ee2s) {
    int i = blockIdx.x * 256 + threadIdx.x;
    if (i >= NN * DD) return;
    int d = i & (DD - 1);
    g_agg[i] = g_h[i] + ee1s[d] + ee2s[d];
}

// ---------------- edge scatter ----------------
__global__ void scatter_kernel(const int* __restrict__ src,
                               const int* __restrict__ dst,
                               const int* __restrict__ eattr,
                               const float* __restrict__ ee1l,
                               const float* __restrict__ ee2l) {
    int e = blockIdx.x * 4 + (threadIdx.x >> 6);
    int c = threadIdx.x & 63;
    if (e >= EE) return;
    int s  = src[e];
    int d  = dst[e];
    int a0 = eattr[2 * e];
    int a1 = eattr[2 * e + 1];
    float4 v  = ((const float4*)(g_h + (size_t)s * DD))[c];
    float4 t1 = ((const float4*)(ee1l + a0 * DD))[c];
    float4 t2 = ((const float4*)(ee2l + a1 * DD))[c];
    v.x += t1.x + t2.x;
    v.y += t1.y + t2.y;
    v.z += t1.z + t2.z;
    v.w += t1.w + t2.w;
    red_add_v4(g_agg + (size_t)d * DD + c * 4, v);
}

// ============ tensor-core GEMM, bf16 3-way split, DOUBLE-BUFFERED ============
// C[M,Nc] = A[M,K] @ B[K,Nc] + bias (opt relu). K%32==0, Nc%128==0.
// Tile 128x128x32, 256 threads (8 warps: 4 along m, 2 along n).
// Dynamic smem: 2 stages x 32KB. Stage layout: AH 0 | AL 8K | BH 16K | BL 24K
#define STAGE 32768
#define OFF_AH 0
#define OFF_AL 8192
#define OFF_BH 16384
#define OFF_BL 24576

template <int RELU>
__global__ void __launch_bounds__(256) gemm_tc(const float* __restrict__ A,
                                               const float* __restrict__ B,
                                               const float* __restrict__ bias,
                                               float* __restrict__ C,
                                               int M, int K, int Nc) {
    extern __shared__ __align__(1024) char sm[];
    const int tid  = threadIdx.x;
    const int lane = tid & 31;
    const int warp = tid >> 5;
    const int wm   = warp >> 1;   // 0..3
    const int wn   = warp & 1;    // 0..1
    const int row0 = blockIdx.y * 128;
    const int col0 = blockIdx.x * 128;

    // ---- loader mapping ----
    const int am   = tid >> 1;              // A row 0..127
    const int akb  = (tid & 1) * 16;        // A k base 0/16
    const bool aok = (row0 + am) < M;
    const float* Ap = A + (size_t)(aok ? row0 + am : 0) * K + akb;

    const int bkr  = tid >> 3;              // B k row 0..31
    const int bnb  = (tid & 7) * 16;        // B n base
    const float* Bp = B + (size_t)bkr * Nc + col0 + bnb;

    const uint32_t aso0 = (uint32_t)(am * 64 + (akb + 0) * 2) ^ ((am & 6) << 3);
    const uint32_t aso1 = (uint32_t)(am * 64 + (akb + 8) * 2) ^ ((am & 6) << 3);
    const uint32_t bso0 = (uint32_t)(bkr * 256 + (bnb + 0) * 2) ^ ((bkr & 7) << 4);
    const uint32_t bso1 = (uint32_t)(bkr * 256 + (bnb + 8) * 2) ^ ((bkr & 7) << 4);

    uint32_t smbase;
    asm("{ .reg .u64 t; cvta.to.shared.u64 t, %1; cvt.u32.u64 %0, t; }"
        : "=r"(smbase) : "l"(sm));

    float acc[2][8][4];
#pragma unroll
    for (int mi = 0; mi < 2; mi++)
#pragma unroll
        for (int nt = 0; nt < 8; nt++)
#pragma unroll
            for (int q = 0; q < 4; q++) acc[mi][nt][q] = 0.f;

    const int ktiles = K >> 5;

    float4 afr[4], bfr[4];

    // ---- load tile 0 → regs, convert → stage 0 ----
    {
        if (aok) {
#pragma unroll
            for (int i = 0; i < 4; i++) afr[i] = *(const float4*)(Ap + i * 4);
        } else {
#pragma unroll
            for (int i = 0; i < 4; i++) afr[i] = make_float4(0, 0, 0, 0);
        }
#pragma unroll
        for (int i = 0; i < 4; i++) bfr[i] = *(const float4*)(Bp + i * 4);

        char* st = sm;
        uint4 h, l;
        split2(afr[0].x, afr[0].y, h.x, l.x);
        split2(afr[0].z, afr[0].w, h.y, l.y);
        split2(afr[1].x, afr[1].y, h.z, l.z);
        split2(afr[1].z, afr[1].w, h.w, l.w);
        *(uint4*)(st + OFF_AH + aso0) = h;
        *(uint4*)(st + OFF_AL + aso0) = l;
        split2(afr[2].x, afr[2].y, h.x, l.x);
        split2(afr[2].z, afr[2].w, h.y, l.y);
        split2(afr[3].x, afr[3].y, h.z, l.z);
        split2(afr[3].z, afr[3].w, h.w, l.w);
        *(uint4*)(st + OFF_AH + aso1) = h;
        *(uint4*)(st + OFF_AL + aso1) = l;

        split2(bfr[0].x, bfr[0].y, h.x, l.x);
        split2(bfr[0].z, bfr[0].w, h.y, l.y);
        split2(bfr[1].x, bfr[1].y, h.z, l.z);
        split2(bfr[1].z, bfr[1].w, h.w, l.w);
        *(uint4*)(st + OFF_BH + bso0) = h;
        *(uint4*)(st + OFF_BL + bso0) = l;
        split2(bfr[2].x, bfr[2].y, h.x, l.x);
        split2(bfr[2].z, bfr[2].w, h.y, l.y);
        split2(bfr[3].x, bfr[3].y, h.z, l.z);
        split2(bfr[3].z, bfr[3].w, h.w, l.w);
        *(uint4*)(st + OFF_BH + bso1) = h;
        *(uint4*)(st + OFF_BL + bso1) = l;
    }

    for (int kt = 0; kt < ktiles; kt++) {
        __syncthreads();   // stage[kt&1] fully written; prior reads of other stage done
        const uint32_t cbase = smbase + (kt & 1) * STAGE;
        const bool more = (kt + 1) < ktiles;

        // ---- prefetch next tile (in flight during MMA burst) ----
        if (more) {
            const float* ap = Ap + (kt + 1) * 32;
            if (aok) {
#pragma unroll
                for (int i = 0; i < 4; i++) afr[i] = *(const float4*)(ap + i * 4);
            }
            const float* bp = Bp + (size_t)(kt + 1) * 32 * Nc;
#pragma unroll
            for (int i = 0; i < 4; i++) bfr[i] = *(const float4*)(bp + i * 4);
        }

        // ---- compute: 2 k16 steps from current stage ----
#pragma unroll
        for (int ks = 0; ks < 2; ks++) {
            uint32_t a_h[2][4], a_l[2][4];
#pragma unroll
            for (int mi = 0; mi < 2; mi++) {
                int m = wm * 32 + mi * 16 + (lane & 15);
                int k = ks * 16 + (lane >> 4) * 8;
                uint32_t byte = (uint32_t)(m * 64 + k * 2) ^ ((m & 6) << 3);
                ldsm4(a_h[mi], cbase + OFF_AH + byte);
                ldsm4(a_l[mi], cbase + OFF_AL + byte);
            }
#pragma unroll
            for (int nj = 0; nj < 4; nj++) {
                int k = ks * 16 + (lane & 15);
                int n = wn * 64 + nj * 16 + (lane >> 4) * 8;
                uint32_t byte = (uint32_t)(k * 256 + n * 2) ^ ((k & 7) << 4);
                uint32_t bh[4], bl[4];
                ldsm4t(bh, cbase + OFF_BH + byte);
                ldsm4t(bl, cbase + OFF_BL + byte);
#pragma unroll
                for (int mi = 0; mi < 2; mi++) {
                    mma16816(acc[mi][2 * nj],     a_h[mi], bh[0], bh[1]);
                    mma16816(acc[mi][2 * nj],     a_h[mi], bl[0], bl[1]);
                    mma16816(acc[mi][2 * nj],     a_l[mi], bh[0], bh[1]);
                    mma16816(acc[mi][2 * nj + 1], a_h[mi], bh[2], bh[3]);
                    mma16816(acc[mi][2 * nj + 1], a_h[mi], bl[2], bl[3]);
                    mma16816(acc[mi][2 * nj + 1], a_l[mi], bh[2], bh[3]);
                }
            }
        }

        // ---- convert + store prefetched tile into the other stage ----
        if (more) {
            char* st = sm + ((kt + 1) & 1) * STAGE;
            uint4 h, l;
            split2(afr[0].x, afr[0].y, h.x, l.x);
            split2(afr[0].z, afr[0].w, h.y, l.y);
            split2(afr[1].x, afr[1].y, h.z, l.z);
            split2(afr[1].z, afr[1].w, h.w, l.w);
            *(uint4*)(st + OFF_AH + aso0) = h;
            *(uint4*)(st + OFF_AL + aso0) = l;
            split2(afr[2].x, afr[2].y, h.x, l.x);
            split2(afr[2].z, afr[2].w, h.y, l.y);
            split2(afr[3].x, afr[3].y, h.z, l.z);
            split2(afr[3].z, afr[3].w, h.w, l.w);
            *(uint4*)(st + OFF_AH + aso1) = h;
            *(uint4*)(st + OFF_AL + aso1) = l;

            split2(bfr[0].x, bfr[0].y, h.x, l.x);
            split2(bfr[0].z, bfr[0].w, h.y, l.y);
            split2(bfr[1].x, bfr[1].y, h.z, l.z);
            split2(bfr[1].z, bfr[1].w, h.w, l.w);
            *(uint4*)(st + OFF_BH + bso0) = h;
            *(uint4*)(st + OFF_BL + bso0) = l;
            split2(bfr[2].x, bfr[2].y, h.x, l.x);
            split2(bfr[2].z, bfr[2].w, h.y, l.y);
            split2(bfr[3].x, bfr[3].y, h.z, l.z);
            split2(bfr[3].z, bfr[3].w, h.w, l.w);
            *(uint4*)(st + OFF_BH + bso1) = h;
            *(uint4*)(st + OFF_BL + bso1) = l;
        }
    }

    // ---- epilogue ----
#pragma unroll
    for (int mi = 0; mi < 2; mi++) {
        int r0 = row0 + wm * 32 + mi * 16 + (lane >> 2);
#pragma unroll
        for (int nt = 0; nt < 8; nt++) {
            int c = col0 + wn * 64 + nt * 8 + (lane & 3) * 2;
            float2 bv = *(const float2*)(bias + c);
            float* a4 = acc[mi][nt];
            float2 o0, o1;
            o0.x = a4[0] + bv.x; o0.y = a4[1] + bv.y;
            o1.x = a4[2] + bv.x; o1.y = a4[3] + bv.y;
            if (RELU) {
                o0.x = fmaxf(o0.x, 0.f); o0.y = fmaxf(o0.y, 0.f);
                o1.x = fmaxf(o1.x, 0.f); o1.y = fmaxf(o1.y, 0.f);
            }
            if (r0 < M)     *(float2*)(C + (size_t)r0 * Nc + c)       = o0;
            if (r0 + 8 < M) *(float2*)(C + (size_t)(r0 + 8) * Nc + c) = o1;
        }
    }
}

// ---------------- small GEMM (head MLP): 64x64 tile ----------------
template <int RELU>
__global__ void __launch_bounds__(256) gemm_bias(const float* __restrict__ A,
                                                 const float* __restrict__ B,
                                                 const float* __restrict__ bias,
                                                 float* __restrict__ C,
                                                 int M, int K, int Nc) {
    __shared__ float As[16][64];
    __shared__ float Bs[16][64];

    int tid  = threadIdx.x;
    int row0 = blockIdx.y * 64;
    int col0 = blockIdx.x * 64;
    int ty   = tid >> 4;
    int tx   = tid & 15;

    int ar = tid >> 2;
    int ak = (tid & 3) * 4;
    int bk = tid >> 4;
    int bc = (tid & 15) * 4;

    float acc[4][4];
#pragma unroll
    for (int i = 0; i < 4; i++)
#pragma unroll
        for (int j = 0; j < 4; j++) acc[i][j] = 0.f;

    int arow = row0 + ar;
    int bcol = col0 + bc;

    for (int k0 = 0; k0 < K; k0 += 16) {
        float4 av = make_float4(0.f, 0.f, 0.f, 0.f);
        if (arow < M)
            av = *(const float4*)(A + (size_t)arow * K + k0 + ak);
        As[ak + 0][ar] = av.x;
        As[ak + 1][ar] = av.y;
        As[ak + 2][ar] = av.z;
        As[ak + 3][ar] = av.w;

        float4 bv = make_float4(0.f, 0.f, 0.f, 0.f);
        if (bcol < Nc)
            bv = *(const float4*)(B + (size_t)(k0 + bk) * Nc + bcol);
        *(float4*)(&Bs[bk][bc]) = bv;

        __syncthreads();
#pragma unroll
        for (int k = 0; k < 16; k++) {
            float4 a4 = *(const float4*)(&As[k][ty * 4]);
            float4 b4 = *(const float4*)(&Bs[k][tx * 4]);
            float a[4] = {a4.x, a4.y, a4.z, a4.w};
            float b[4] = {b4.x, b4.y, b4.z, b4.w};
#pragma unroll
            for (int i = 0; i < 4; i++)
#pragma unroll
                for (int j = 0; j < 4; j++)
                    acc[i][j] = fmaf(a[i], b[j], acc[i][j]);
        }
        __syncthreads();
    }

#pragma unroll
    for (int i = 0; i < 4; i++) {
        int r = row0 + ty * 4 + i;
        if (r < M) {
#pragma unroll
            for (int j = 0; j < 4; j++) {
                int c = col0 + tx * 4 + j;
                if (c < Nc) {
                    float v = acc[i][j] + bias[c];
                    if (RELU) v = fmaxf(v, 0.f);
                    C[(size_t)r * Nc + c] = v;
                }
            }
        }
    }
}

// ---------------- batchnorm ----------------
__global__ void zero_stats_kernel() {
    g_sum[threadIdx.x]   = 0.f;
    g_sumsq[threadIdx.x] = 0.f;
}

__global__ void bn_stats_kernel() {
    int d = threadIdx.x;
    float s = 0.f, s2 = 0.f;
    for (int i = blockIdx.x; i < NN; i += gridDim.x) {
        float v = g_h[(size_t)i * DD + d];
        s  += v;
        s2 += v * v;
    }
    atomicAdd(&g_sum[d], s);
    atomicAdd(&g_sumsq[d], s2);
}

__global__ void bn_apply_fused_kernel(const float* __restrict__ gamma,
                                      const float* __restrict__ beta,
                                      int relu,
                                      const float* __restrict__ ee1n,
                                      const float* __restrict__ ee2n,
                                      int write_agg) {
    int i = blockIdx.x * 256 + threadIdx.x;
    if (i >= NN * DD) return;
    int d = i & (DD - 1);
    const float invN = 1.f / (float)NN;
    float mu  = g_sum[d] * invN;
    float var = g_sumsq[d] * invN - mu * mu;
    float v = (g_h[i] - mu) * rsqrtf(var + 1e-5f) * gamma[d] + beta[d];
    if (relu) v = fmaxf(v, 0.f);
    g_h[i] = v;
    if (write_agg) g_agg[i] = v + ee1n[d] + ee2n[d];
}

// ---------------- pooling ----------------
__global__ void zero_pool_kernel() {
    int i = blockIdx.x * 256 + threadIdx.x;
    if (i < GG * DD) g_mol[i] = 0.f;
    if (i < GG) g_cnt[i] = 0.f;
}

__global__ void count_kernel(const int* __restrict__ batch) {
    int i = blockIdx.x * 256 + threadIdx.x;
    if (i < NN) atomicAdd(&g_cnt[batch[i]], 1.f);
}

__global__ void pool_scatter_kernel(const int* __restrict__ batch) {
    int n = blockIdx.x * 4 + (threadIdx.x >> 6);
    int c = threadIdx.x & 63;
    if (n >= NN) return;
    int g = batch[n];
    float4 v = ((const float4*)(g_h + (size_t)n * DD))[c];
    red_add_v4(g_mol + (size_t)g * DD + c * 4, v);
}

__global__ void pool_div_kernel() {
    int i = blockIdx.x * 256 + threadIdx.x;
    if (i >= GG * DD) return;
    g_mol[i] /= fmaxf(g_cnt[i >> 8], 1.f);
}

// ---------------- head final ----------------
__global__ void head_final_kernel(const float* __restrict__ w,
                                  const float* __restrict__ b,
                                  float* __restrict__ out) {
    int g = blockIdx.x * 256 + threadIdx.x;
    if (g >= GG) return;
    float acc = b[0];
#pragma unroll
    for (int k = 0; k < 32; k++)
        acc = fmaf(g_z2[g * 32 + k], w[k], acc);
    out[g] = acc;
}

// ---------------- launch ----------------
extern "C" void kernel_launch(void* const* d_in, const int* in_sizes, int n_in,
                              void* d_out, int out_size) {
    const float* x          = (const float*)d_in[0];
    const int*   edge_index = (const int*)d_in[1];
    const int*   edge_attr  = (const int*)d_in[2];
    const int*   batch      = (const int*)d_in[3];
    const float* embW       = (const float*)d_in[4];
    const float* embB       = (const float*)d_in[5];
    const float* ee1        = (const float*)d_in[6];
    const float* ee2        = (const float*)d_in[7];
    const float* W1         = (const float*)d_in[8];
    const float* b1         = (const float*)d_in[9];
    const float* W2         = (const float*)d_in[10];
    const float* b2         = (const float*)d_in[11];
    const float* bn_g       = (const float*)d_in[12];
    const float* bn_b       = (const float*)d_in[13];
    const float* hW0 = (const float*)d_in[14];
    const float* hb0 = (const float*)d_in[15];
    const float* hW1 = (const float*)d_in[16];
    const float* hb1 = (const float*)d_in[17];
    const float* hW2 = (const float*)d_in[18];
    const float* hb2 = (const float*)d_in[19];
    const float* hW3 = (const float*)d_in[20];
    const float* hb3 = (const float*)d_in[21];
    const float* hWo = (const float*)d_in[22];
    const float* hbo = (const float*)d_in[23];
    float* out = (float*)d_out;

    float *p_agg, *p_t, *p_h, *p_mol, *p_z1, *p_z2;
    cudaGetSymbolAddress((void**)&p_h,   g_h);
    cudaGetSymbolAddress((void**)&p_agg, g_agg);
    cudaGetSymbolAddress((void**)&p_t,   g_t);
    cudaGetSymbolAddress((void**)&p_mol, g_mol);
    cudaGetSymbolAddress((void**)&p_z1,  g_z1);
    cudaGetSymbolAddress((void**)&p_z2,  g_z2);

    static int smem_set = 0;
    if (!smem_set) {
        cudaFuncSetAttribute(gemm_tc<1>, cudaFuncAttributeMaxDynamicSharedMemorySize, 2 * STAGE);
        cudaFuncSetAttribute(gemm_tc<0>, cudaFuncAttributeMaxDynamicSharedMemorySize, 2 * STAGE);
        smem_set = 1;
    }

    const int elemGrid = (NN * DD + 255) / 256;
    const int rowBlocks = (NN + 127) / 128;

    embed_kernel<<<NN, 256>>>(x, embW, embB);
    init_agg_kernel<<<elemGrid, 256>>>(ee1 + 4 * DD, ee2);

    for (int l = 0; l < LL; l++) {
        const float* ee1l = ee1 + (size_t)l * 6 * DD;
        const float* ee2l = ee2 + (size_t)l * 3 * DD;
        scatter_kernel<<<(EE + 3) / 4, 256>>>(edge_index, edge_index + EE,
                                              edge_attr, ee1l, ee2l);
        gemm_tc<1><<<dim3(4, rowBlocks), 256, 2 * STAGE>>>(
            p_agg, W1 + (size_t)l * DD * 2 * DD, b1 + (size_t)l * 2 * DD,
            p_t, NN, DD, 2 * DD);
        gemm_tc<0><<<dim3(2, rowBlocks), 256, 2 * STAGE>>>(
            p_t, W2 + (size_t)l * 2 * DD * DD, b2 + (size_t)l * DD,
            p_h, NN, 2 * DD, DD);
        zero_stats_kernel<<<1, 256>>>();
        bn_stats_kernel<<<512, 256>>>();
        int last = (l == LL - 1);
        const float* ee1n = ee1 + (size_t)(l + 1) * 6 * DD + 4 * DD;
        const float* ee2n = ee2 + (size_t)(l + 1) * 3 * DD;
        bn_apply_fused_kernel<<<elemGrid, 256>>>(
            bn_g + (size_t)l * DD, bn_b + (size_t)l * DD,
            last ? 0 : 1,
            last ? ee1 : ee1n, last ? ee2 : ee2n,
            last ? 0 : 1);
    }

    zero_pool_kernel<<<(GG * DD + 255) / 256, 256>>>();
    count_kernel<<<(NN + 255) / 256, 256>>>(batch);
    pool_scatter_kernel<<<(NN + 3) / 4, 256>>>(batch);
    pool_div_kernel<<<(GG * DD + 255) / 256, 256>>>();

    gemm_bias<1><<<dim3(4, (GG + 63) / 64), 256>>>(p_mol, hW0, hb0, p_z1, GG, 256, 256);
    gemm_bias<1><<<dim3(2, (GG + 63) / 64), 256>>>(p_z1,  hW1, hb1, p_z2, GG, 256, 128);
    gemm_bias<1><<<dim3(1, (GG + 63) / 64), 256>>>(p_z2,  hW2, hb2, p_z1, GG, 128, 64);
    gemm_bias<1><<<dim3(1, (GG + 63) / 64), 256>>>(p_z1,  hW3, hb3, p_z2, GG, 64, 32);
    head_final_kernel<<<(GG + 255) / 256, 256>>>(hWo, hbo, out);
}

// round 6
// speedup vs baseline: 2.6717x; 1.3580x over previous
#include <cuda_runtime.h>
#include <cuda_bf16.h>
#include <cstdint>

#define NN 100000
#define EE 300000
#define DD 256
#define GG 4000
#define LL 5
#define F_IN 40

// ---------------- scratch (device globals: allocation-free) ----------------
__device__ float g_h[NN * DD];
__device__ float g_agg[NN * DD];
__device__ __align__(16) __nv_bfloat16 g_aggH[NN * DD];
__device__ __align__(16) __nv_bfloat16 g_aggL[NN * DD];
__device__ __align__(16) __nv_bfloat16 g_tH[NN * 2 * DD];
__device__ __align__(16) __nv_bfloat16 g_tL[NN * 2 * DD];
__device__ uint4 g_W1t[163840];   // 5 layers x 4 colblk x 8 kt x 16KB
__device__ uint4 g_W2t[163840];   // 5 layers x 2 colblk x 16 kt x 16KB
__device__ float g_sum[DD];
__device__ float g_sumsq[DD];
__device__ float g_mol[GG * DD];
__device__ float g_cnt[GG];
__device__ float g_z1[GG * DD];
__device__ float g_z2[GG * DD];

// ---------------- helpers ----------------
__device__ __forceinline__ void red_add_v4(float* addr, float4 v) {
    asm volatile("red.global.add.v4.f32 [%0], {%1,%2,%3,%4};"
                 :: "l"(addr), "f"(v.x), "f"(v.y), "f"(v.z), "f"(v.w)
                 : "memory");
}
__device__ __forceinline__ void ldsm4(uint32_t r[4], uint32_t addr) {
    asm volatile("ldmatrix.sync.aligned.m8n8.x4.shared.b16 {%0,%1,%2,%3}, [%4];"
        : "=r"(r[0]), "=r"(r[1]), "=r"(r[2]), "=r"(r[3]) : "r"(addr));
}
__device__ __forceinline__ void ldsm4t(uint32_t r[4], uint32_t addr) {
    asm volatile("ldmatrix.sync.aligned.m8n8.x4.trans.shared.b16 {%0,%1,%2,%3}, [%4];"
        : "=r"(r[0]), "=r"(r[1]), "=r"(r[2]), "=r"(r[3]) : "r"(addr));
}
__device__ __forceinline__ void mma16816(float c[4], const uint32_t a[4],
                                         uint32_t b0, uint32_t b1) {
    asm volatile("mma.sync.aligned.m16n8k16.row.col.f32.bf16.bf16.f32 "
        "{%0,%1,%2,%3}, {%4,%5,%6,%7}, {%8,%9}, {%0,%1,%2,%3};"
        : "+f"(c[0]), "+f"(c[1]), "+f"(c[2]), "+f"(c[3])
        : "r"(a[0]), "r"(a[1]), "r"(a[2]), "r"(a[3]), "r"(b0), "r"(b1));
}
__device__ __forceinline__ void cpa16(uint32_t dst, const void* src, uint32_t sz) {
    asm volatile("cp.async.cg.shared.global [%0], [%1], 16, %2;"
                 :: "r"(dst), "l"(src), "r"(sz) : "memory");
}

// ---------------- embed ----------------
__global__ void embed_kernel(const float* __restrict__ x,
                             const float* __restrict__ W,
                             const float* __restrict__ b) {
    int node = blockIdx.x;
    __shared__ float xs[F_IN];
    if (threadIdx.x < F_IN) xs[threadIdx.x] = x[node * F_IN + threadIdx.x];
    __syncthreads();
    int d = threadIdx.x;
    float acc = b[d];
#pragma unroll
    for (int k = 0; k < F_IN; k++)
        acc = fmaf(xs[k], W[k * DD + d], acc);
    g_h[node * DD + d] = fmaxf(acc, 0.f);
}

// ---------------- agg init ----------------
__global__ void init_agg_kernel(const float* __restrict__ ee1s,
                                const float* __restrict__ ee2s) {
    int i = blockIdx.x * 256 + threadIdx.x;
    if (i >= NN * DD) return;
    int d = i & (DD - 1);
    g_agg[i] = g_h[i] + ee1s[d] + ee2s[d];
}

// ---------------- edge scatter ----------------
__global__ void scatter_kernel(const int* __restrict__ src,
                               const int* __restrict__ dst,
                               const int* __restrict__ eattr,
                               const float* __restrict__ ee1l,
                               const float* __restrict__ ee2l) {
    int e = blockIdx.x * 4 + (threadIdx.x >> 6);
    int c = threadIdx.x & 63;
    if (e >= EE) return;
    int s  = src[e];
    int d  = dst[e];
    int a0 = eattr[2 * e];
    int a1 = eattr[2 * e + 1];
    float4 v  = ((const float4*)(g_h + (size_t)s * DD))[c];
    float4 t1 = ((const float4*)(ee1l + a0 * DD))[c];
    float4 t2 = ((const float4*)(ee2l + a1 * DD))[c];
    v.x += t1.x + t2.x;
    v.y += t1.y + t2.y;
    v.z += t1.z + t2.z;
    v.w += t1.w + t2.w;
    red_add_v4(g_agg + (size_t)d * DD + c * 4, v);
}

// ---------------- split agg into bf16 hi/lo planes ----------------
__global__ void split_agg_kernel() {
    int i = (blockIdx.x * 256 + threadIdx.x) * 4;
    if (i >= NN * DD) return;
    float4 v = *(const float4*)(g_agg + i);
    __nv_bfloat16 hx = __float2bfloat16(v.x), hy = __float2bfloat16(v.y);
    __nv_bfloat16 hz = __float2bfloat16(v.z), hw = __float2bfloat16(v.w);
    __nv_bfloat162 h0(hx, hy), h1(hz, hw);
    __nv_bfloat162 l0(__float2bfloat16(v.x - __bfloat162float(hx)),
                      __float2bfloat16(v.y - __bfloat162float(hy)));
    __nv_bfloat162 l1(__float2bfloat16(v.z - __bfloat162float(hz)),
                      __float2bfloat16(v.w - __bfloat162float(hw)));
    uint2 h, l;
    h.x = *(uint32_t*)&h0; h.y = *(uint32_t*)&h1;
    l.x = *(uint32_t*)&l0; l.y = *(uint32_t*)&l1;
    *(uint2*)(g_aggH + i) = h;
    *(uint2*)(g_aggL + i) = l;
}

// ---------------- weight prep: split + pre-swizzle into smem tile image ----
// blob per (layer, colblk, ktile): [hi 8KB | lo 8KB], byte-identical to the
// B smem plane the GEMM expects.
__global__ void prep_w(const float* __restrict__ W, uint4* __restrict__ dst,
                       int Nc, int ktiles) {
    int cb = blockIdx.x, kt = blockIdx.y, l = blockIdx.z;
    const float* Wl = W + (size_t)l * (ktiles * 32) * Nc;
    char* blob = (char*)dst + (((size_t)l * gridDim.x + cb) * ktiles + kt) * 16384;
    for (int e = threadIdx.x; e < 4096; e += 256) {
        int k = e >> 7, n = e & 127;
        float v = Wl[(size_t)(kt * 32 + k) * Nc + cb * 128 + n];
        __nv_bfloat16 h = __float2bfloat16(v);
        __nv_bfloat16 lo = __float2bfloat16(v - __bfloat162float(h));
        uint32_t off = k * 256 + n * 2;
        uint32_t sw = off ^ ((k & 7) << 4);
        *(__nv_bfloat16*)(blob + sw) = h;
        *(__nv_bfloat16*)(blob + 8192 + sw) = lo;
    }
}

// ============ tensor-core GEMM, bf16 3-way split, cp.async, occ 2 ============
// OUT=1: C = relu(A@B + bias) written as bf16 hi/lo planes (CH, CL).
// OUT=0: C = A@B + bias written fp32 (Cf) + column sum/sumsq atomics.
#define STAGE 32768
#define P_AH 0
#define P_AL 8192
#define P_BH 16384
#define P_BL 24576

template <int OUT>
__global__ void __launch_bounds__(256, 2) gemm_cp(
    const __nv_bfloat16* __restrict__ AH, const __nv_bfloat16* __restrict__ AL,
    const char* __restrict__ Btiles, const float* __restrict__ bias,
    float* __restrict__ Cf, __nv_bfloat16* __restrict__ CH,
    __nv_bfloat16* __restrict__ CL, int M, int K, int Nc) {
    extern __shared__ __align__(16) char sm[];
    const int tid  = threadIdx.x;
    const int lane = tid & 31;
    const int warp = tid >> 5;
    const int wm   = warp >> 1;
    const int wn   = warp & 1;
    const int row0 = blockIdx.y * 128;
    const int col0 = blockIdx.x * 128;
    const int ktiles = K >> 5;

    uint32_t smbase;
    asm("{ .reg .u64 t; cvta.to.shared.u64 t, %1; cvt.u32.u64 %0, t; }"
        : "=r"(smbase) : "l"(sm));

    // A chunk mapping: 512 16B-chunks per plane, 2 per thread per plane
    const int m0 = tid >> 2, kq0 = tid & 3;
    const int m1 = (tid + 256) >> 2, kq1 = (tid + 256) & 3;
    const uint32_t dA0 = (uint32_t)(m0 * 64 + kq0 * 16) ^ ((m0 & 6) << 3);
    const uint32_t dA1 = (uint32_t)(m1 * 64 + kq1 * 16) ^ ((m1 & 6) << 3);
    const uint32_t ok0 = (row0 + m0 < M) ? 16u : 0u;
    const uint32_t ok1 = (row0 + m1 < M) ? 16u : 0u;
    const __nv_bfloat16* sH0 = AH + (size_t)(row0 + m0) * K + kq0 * 8;
    const __nv_bfloat16* sH1 = AH + (size_t)(row0 + m1) * K + kq1 * 8;
    const __nv_bfloat16* sL0 = AL + (size_t)(row0 + m0) * K + kq0 * 8;
    const __nv_bfloat16* sL1 = AL + (size_t)(row0 + m1) * K + kq1 * 8;
    const char* tbase = Btiles + (size_t)blockIdx.x * ktiles * 16384;

    float acc[2][8][4];
#pragma unroll
    for (int mi = 0; mi < 2; mi++)
#pragma unroll
        for (int nt = 0; nt < 8; nt++)
#pragma unroll
            for (int q = 0; q < 4; q++) acc[mi][nt][q] = 0.f;

#define ISSUE(kt, st) do {                                                    \
        uint32_t sb = smbase + (st) * STAGE;                                  \
        int ko = (kt) * 32;                                                   \
        cpa16(sb + P_AH + dA0, sH0 + ko, ok0);                                \
        cpa16(sb + P_AH + dA1, sH1 + ko, ok1);                                \
        cpa16(sb + P_AL + dA0, sL0 + ko, ok0);                                \
        cpa16(sb + P_AL + dA1, sL1 + ko, ok1);                                \
        const char* tb = tbase + (size_t)(kt) * 16384;                        \
        cpa16(sb + P_BH + tid * 16,        tb + tid * 16, 16);                \
        cpa16(sb + P_BH + tid * 16 + 4096, tb + tid * 16 + 4096, 16);         \
        cpa16(sb + P_BL + tid * 16,        tb + 8192 + tid * 16, 16);         \
        cpa16(sb + P_BL + tid * 16 + 4096, tb + 12288 + tid * 16, 16);        \
        asm volatile("cp.async.commit_group;" ::: "memory");                  \
    } while (0)

    ISSUE(0, 0);

    for (int kt = 0; kt < ktiles; kt++) {
        if (kt) __syncthreads();          // done reading stage (kt+1)&1
        const bool more = (kt + 1) < ktiles;
        if (more) {
            ISSUE(kt + 1, (kt + 1) & 1);
            asm volatile("cp.async.wait_group 1;" ::: "memory");
        } else {
            asm volatile("cp.async.wait_group 0;" ::: "memory");
        }
        __syncthreads();                  // stage kt&1 visible to all

        const uint32_t cbase = smbase + (kt & 1) * STAGE;
#pragma unroll
        for (int ks = 0; ks < 2; ks++) {
            uint32_t a_h[2][4], a_l[2][4];
#pragma unroll
            for (int mi = 0; mi < 2; mi++) {
                int m = wm * 32 + mi * 16 + (lane & 15);
                int k = ks * 16 + (lane >> 4) * 8;
                uint32_t byte = (uint32_t)(m * 64 + k * 2) ^ ((m & 6) << 3);
                ldsm4(a_h[mi], cbase + P_AH + byte);
                ldsm4(a_l[mi], cbase + P_AL + byte);
            }
#pragma unroll
            for (int nj = 0; nj < 4; nj++) {
                int k = ks * 16 + (lane & 15);
                int n = wn * 64 + nj * 16 + (lane >> 4) * 8;
                uint32_t byte = (uint32_t)(k * 256 + n * 2) ^ ((k & 7) << 4);
                uint32_t bh[4], bl[4];
                ldsm4t(bh, cbase + P_BH + byte);
                ldsm4t(bl, cbase + P_BL + byte);
#pragma unroll
                for (int mi = 0; mi < 2; mi++) {
                    mma16816(acc[mi][2 * nj],     a_h[mi], bh[0], bh[1]);
                    mma16816(acc[mi][2 * nj],     a_h[mi], bl[0], bl[1]);
                    mma16816(acc[mi][2 * nj],     a_l[mi], bh[0], bh[1]);
                    mma16816(acc[mi][2 * nj + 1], a_h[mi], bh[2], bh[3]);
                    mma16816(acc[mi][2 * nj + 1], a_h[mi], bl[2], bl[3]);
                    mma16816(acc[mi][2 * nj + 1], a_l[mi], bh[2], bh[3]);
                }
            }
        }
    }
#undef ISSUE

    if (OUT == 1) {
        // relu + split -> bf16 hi/lo planes
#pragma unroll
        for (int mi = 0; mi < 2; mi++) {
            int r0 = row0 + wm * 32 + mi * 16 + (lane >> 2);
#pragma unroll
            for (int nt = 0; nt < 8; nt++) {
                int c = col0 + wn * 64 + nt * 8 + (lane & 3) * 2;
                float2 bv = *(const float2*)(bias + c);
                float* a4 = acc[mi][nt];
#pragma unroll
                for (int half = 0; half < 2; half++) {
                    int r = r0 + half * 8;
                    if (r < M) {
                        float v0 = fmaxf(a4[2 * half + 0] + bv.x, 0.f);
                        float v1 = fmaxf(a4[2 * half + 1] + bv.y, 0.f);
                        __nv_bfloat16 h0 = __float2bfloat16(v0);
                        __nv_bfloat16 h1 = __float2bfloat16(v1);
                        __nv_bfloat162 hp(h0, h1);
                        __nv_bfloat162 lp(__float2bfloat16(v0 - __bfloat162float(h0)),
                                          __float2bfloat16(v1 - __bfloat162float(h1)));
                        *(__nv_bfloat162*)(CH + (size_t)r * Nc + c) = hp;
                        *(__nv_bfloat162*)(CL + (size_t)r * Nc + c) = lp;
                    }
                }
            }
        }
    } else {
        // fp32 out + fused bn stats
        float cs[16], cq[16];
#pragma unroll
        for (int j = 0; j < 16; j++) { cs[j] = 0.f; cq[j] = 0.f; }
#pragma unroll
        for (int mi = 0; mi < 2; mi++) {
            int r0 = row0 + wm * 32 + mi * 16 + (lane >> 2);
#pragma unroll
            for (int nt = 0; nt < 8; nt++) {
                int c = col0 + wn * 64 + nt * 8 + (lane & 3) * 2;
                float2 bv = *(const float2*)(bias + c);
                float* a4 = acc[mi][nt];
#pragma unroll
                for (int half = 0; half < 2; half++) {
                    int r = r0 + half * 8;
                    if (r < M) {
                        float v0 = a4[2 * half + 0] + bv.x;
                        float v1 = a4[2 * half + 1] + bv.y;
                        float2 o; o.x = v0; o.y = v1;
                        *(float2*)(Cf + (size_t)r * Nc + c) = o;
                        cs[nt * 2 + 0] += v0; cq[nt * 2 + 0] += v0 * v0;
                        cs[nt * 2 + 1] += v1; cq[nt * 2 + 1] += v1 * v1;
                    }
                }
            }
        }
        // reduce over the 8 row-lanes (same lane&3 share columns)
#pragma unroll
        for (int j = 0; j < 16; j++) {
#pragma unroll
            for (int msk = 4; msk <= 16; msk <<= 1) {
                cs[j] += __shfl_xor_sync(0xFFFFFFFF, cs[j], msk);
                cq[j] += __shfl_xor_sync(0xFFFFFFFF, cq[j], msk);
            }
        }
        float* ssum = (float*)sm;
        float* ssq  = ssum + 128;
        __syncthreads();
        if (tid < 128) { ssum[tid] = 0.f; ssq[tid] = 0.f; }
        __syncthreads();
        if ((lane >> 2) == 0) {
#pragma unroll
            for (int j = 0; j < 16; j++) {
                int cl = wn * 64 + (j >> 1) * 8 + (lane & 3) * 2 + (j & 1);
                atomicAdd(&ssum[cl], cs[j]);
                atomicAdd(&ssq[cl],  cq[j]);
            }
        }
        __syncthreads();
        if (tid < 128) {
            atomicAdd(&g_sum[col0 + tid],   ssum[tid]);
            atomicAdd(&g_sumsq[col0 + tid], ssq[tid]);
        }
    }
}

// ---------------- small GEMM (head MLP): 64x64 tile ----------------
template <int RELU>
__global__ void __launch_bounds__(256) gemm_bias(const float* __restrict__ A,
                                                 const float* __restrict__ B,
                                                 const float* __restrict__ bias,
                                                 float* __restrict__ C,
                                                 int M, int K, int Nc) {
    __shared__ float As[16][64];
    __shared__ float Bs[16][64];

    int tid  = threadIdx.x;
    int row0 = blockIdx.y * 64;
    int col0 = blockIdx.x * 64;
    int ty   = tid >> 4;
    int tx   = tid & 15;

    int ar = tid >> 2;
    int ak = (tid & 3) * 4;
    int bk = tid >> 4;
    int bc = (tid & 15) * 4;

    float acc[4][4];
#pragma unroll
    for (int i = 0; i < 4; i++)
#pragma unroll
        for (int j = 0; j < 4; j++) acc[i][j] = 0.f;

    int arow = row0 + ar;
    int bcol = col0 + bc;

    for (int k0 = 0; k0 < K; k0 += 16) {
        float4 av = make_float4(0.f, 0.f, 0.f, 0.f);
        if (arow < M)
            av = *(const float4*)(A + (size_t)arow * K + k0 + ak);
        As[ak + 0][ar] = av.x;
        As[ak + 1][ar] = av.y;
        As[ak + 2][ar] = av.z;
        As[ak + 3][ar] = av.w;

        float4 bv = make_float4(0.f, 0.f, 0.f, 0.f);
        if (bcol < Nc)
            bv = *(const float4*)(B + (size_t)(k0 + bk) * Nc + bcol);
        *(float4*)(&Bs[bk][bc]) = bv;

        __syncthreads();
#pragma unroll
        for (int k = 0; k < 16; k++) {
            float4 a4 = *(const float4*)(&As[k][ty * 4]);
            float4 b4 = *(const float4*)(&Bs[k][tx * 4]);
            float a[4] = {a4.x, a4.y, a4.z, a4.w};
            float b[4] = {b4.x, b4.y, b4.z, b4.w};
#pragma unroll
            for (int i = 0; i < 4; i++)
#pragma unroll
                for (int j = 0; j < 4; j++)
                    acc[i][j] = fmaf(a[i], b[j], acc[i][j]);
        }
        __syncthreads();
    }

#pragma unroll
    for (int i = 0; i < 4; i++) {
        int r = row0 + ty * 4 + i;
        if (r < M) {
#pragma unroll
            for (int j = 0; j < 4; j++) {
                int c = col0 + tx * 4 + j;
                if (c < Nc) {
                    float v = acc[i][j] + bias[c];
                    if (RELU) v = fmaxf(v, 0.f);
                    C[(size_t)r * Nc + c] = v;
                }
            }
        }
    }
}

// ---------------- batchnorm ----------------
__global__ void zero_stats_kernel() {
    g_sum[threadIdx.x]   = 0.f;
    g_sumsq[threadIdx.x] = 0.f;
}

__global__ void bn_apply_fused_kernel(const float* __restrict__ gamma,
                                      const float* __restrict__ beta,
                                      int relu,
                                      const float* __restrict__ ee1n,
                                      const float* __restrict__ ee2n,
                                      int write_agg) {
    int i = blockIdx.x * 256 + threadIdx.x;
    if (i >= NN * DD) return;
    int d = i & (DD - 1);
    const float invN = 1.f / (float)NN;
    float mu  = g_sum[d] * invN;
    float var = g_sumsq[d] * invN - mu * mu;
    float v = (g_h[i] - mu) * rsqrtf(var + 1e-5f) * gamma[d] + beta[d];
    if (relu) v = fmaxf(v, 0.f);
    g_h[i] = v;
    if (write_agg) g_agg[i] = v + ee1n[d] + ee2n[d];
}

// ---------------- pooling ----------------
__global__ void zero_pool_kernel() {
    int i = blockIdx.x * 256 + threadIdx.x;
    if (i < GG * DD) g_mol[i] = 0.f;
    if (i < GG) g_cnt[i] = 0.f;
}

__global__ void count_kernel(const int* __restrict__ batch) {
    int i = blockIdx.x * 256 + threadIdx.x;
    if (i < NN) atomicAdd(&g_cnt[batch[i]], 1.f);
}

__global__ void pool_scatter_kernel(const int* __restrict__ batch) {
    int n = blockIdx.x * 4 + (threadIdx.x >> 6);
    int c = threadIdx.x & 63;
    if (n >= NN) return;
    int g = batch[n];
    float4 v = ((const float4*)(g_h + (size_t)n * DD))[c];
    red_add_v4(g_mol + (size_t)g * DD + c * 4, v);
}

__global__ void pool_div_kernel() {
    int i = blockIdx.x * 256 + threadIdx.x;
    if (i >= GG * DD) return;
    g_mol[i] /= fmaxf(g_cnt[i >> 8], 1.f);
}

// ---------------- head final ----------------
__global__ void head_final_kernel(const float* __restrict__ w,
                                  const float* __restrict__ b,
                                  float* __restrict__ out) {
    int g = blockIdx.x * 256 + threadIdx.x;
    if (g >= GG) return;
    float acc = b[0];
#pragma unroll
    for (int k = 0; k < 32; k++)
        acc = fmaf(g_z2[g * 32 + k], w[k], acc);
    out[g] = acc;
}

// ---------------- launch ----------------
extern "C" void kernel_launch(void* const* d_in, const int* in_sizes, int n_in,
                              void* d_out, int out_size) {
    const float* x          = (const float*)d_in[0];
    const int*   edge_index = (const int*)d_in[1];
    const int*   edge_attr  = (const int*)d_in[2];
    const int*   batch      = (const int*)d_in[3];
    const float* embW       = (const float*)d_in[4];
    const float* embB       = (const float*)d_in[5];
    const float* ee1        = (const float*)d_in[6];
    const float* ee2        = (const float*)d_in[7];
    const float* W1         = (const float*)d_in[8];
    const float* b1         = (const float*)d_in[9];
    const float* W2         = (const float*)d_in[10];
    const float* b2         = (const float*)d_in[11];
    const float* bn_g       = (const float*)d_in[12];
    const float* bn_b       = (const float*)d_in[13];
    const float* hW0 = (const float*)d_in[14];
    const float* hb0 = (const float*)d_in[15];
    const float* hW1 = (const float*)d_in[16];
    const float* hb1 = (const float*)d_in[17];
    const float* hW2 = (const float*)d_in[18];
    const float* hb2 = (const float*)d_in[19];
    const float* hW3 = (const float*)d_in[20];
    const float* hb3 = (const float*)d_in[21];
    const float* hWo = (const float*)d_in[22];
    const float* hbo = (const float*)d_in[23];
    float* out = (float*)d_out;

    float *p_h, *p_mol, *p_z1, *p_z2;
    __nv_bfloat16 *p_aggH, *p_aggL, *p_tH, *p_tL;
    uint4 *p_W1t, *p_W2t;
    cudaGetSymbolAddress((void**)&p_h,    g_h);
    cudaGetSymbolAddress((void**)&p_mol,  g_mol);
    cudaGetSymbolAddress((void**)&p_z1,   g_z1);
    cudaGetSymbolAddress((void**)&p_z2,   g_z2);
    cudaGetSymbolAddress((void**)&p_aggH, g_aggH);
    cudaGetSymbolAddress((void**)&p_aggL, g_aggL);
    cudaGetSymbolAddress((void**)&p_tH,   g_tH);
    cudaGetSymbolAddress((void**)&p_tL,   g_tL);
    cudaGetSymbolAddress((void**)&p_W1t,  g_W1t);
    cudaGetSymbolAddress((void**)&p_W2t,  g_W2t);

    static int smem_set = 0;
    if (!smem_set) {
        cudaFuncSetAttribute(gemm_cp<1>, cudaFuncAttributeMaxDynamicSharedMemorySize, 2 * STAGE);
        cudaFuncSetAttribute(gemm_cp<0>, cudaFuncAttributeMaxDynamicSharedMemorySize, 2 * STAGE);
        smem_set = 1;
    }

    const int elemGrid  = (NN * DD + 255) / 256;
    const int rowBlocks = (NN + 127) / 128;

    // weight prep (per-call; tiny)
    prep_w<<<dim3(4, 8, 5),  256>>>(W1, p_W1t, 512, 8);
    prep_w<<<dim3(2, 16, 5), 256>>>(W2, p_W2t, 256, 16);

    embed_kernel<<<NN, 256>>>(x, embW, embB);
    init_agg_kernel<<<elemGrid, 256>>>(ee1 + 4 * DD, ee2);

    for (int l = 0; l < LL; l++) {
        const float* ee1l = ee1 + (size_t)l * 6 * DD;
        const float* ee2l = ee2 + (size_t)l * 3 * DD;
        scatter_kernel<<<(EE + 3) / 4, 256>>>(edge_index, edge_index + EE,
                                              edge_attr, ee1l, ee2l);
        split_agg_kernel<<<(NN * DD / 4 + 255) / 256, 256>>>();
        gemm_cp<1><<<dim3(4, rowBlocks), 256, 2 * STAGE>>>(
            p_aggH, p_aggL, (const char*)p_W1t + (size_t)l * 4 * 8 * 16384,
            b1 + (size_t)l * 2 * DD, nullptr, p_tH, p_tL, NN, DD, 2 * DD);
        zero_stats_kernel<<<1, 256>>>();
        gemm_cp<0><<<dim3(2, rowBlocks), 256, 2 * STAGE>>>(
            p_tH, p_tL, (const char*)p_W2t + (size_t)l * 2 * 16 * 16384,
            b2 + (size_t)l * DD, p_h, nullptr, nullptr, NN, 2 * DD, DD);
        int last = (l == LL - 1);
        const float* ee1n = ee1 + (size_t)(l + 1) * 6 * DD + 4 * DD;
        const float* ee2n = ee2 + (size_t)(l + 1) * 3 * DD;
        bn_apply_fused_kernel<<<elemGrid, 256>>>(
            bn_g + (size_t)l * DD, bn_b + (size_t)l * DD,
            last ? 0 : 1,
            last ? ee1 : ee1n, last ? ee2 : ee2n,
            last ? 0 : 1);
    }

    zero_pool_kernel<<<(GG * DD + 255) / 256, 256>>>();
    count_kernel<<<(NN + 255) / 256, 256>>>(batch);
    pool_scatter_kernel<<<(NN + 3) / 4, 256>>>(batch);
    pool_div_kernel<<<(GG * DD + 255) / 256, 256>>>();

    gemm_bias<1><<<dim3(4, (GG + 63) / 64), 256>>>(p_mol, hW0, hb0, p_z1, GG, 256, 256);
    gemm_bias<1><<<dim3(2, (GG + 63) / 64), 256>>>(p_z1,  hW1, hb1, p_z2, GG, 256, 128);
    gemm_bias<1><<<dim3(1, (GG + 63) / 64), 256>>>(p_z2,  hW2, hb2, p_z1, GG, 128, 64);
    gemm_bias<1><<<dim3(1, (GG + 63) / 64), 256>>>(p_z1,  hW3, hb3, p_z2, GG, 64, 32);
    head_final_kernel<<<(GG + 255) / 256, 256>>>(hWo, hbo, out);
}

// round 7
// speedup vs baseline: 2.8313x; 1.0597x over previous
#include <cuda_runtime.h>
#include <cuda_bf16.h>
#include <cstdint>

#define NN 100000
#define EE 300000
#define DD 256
#define GG 4000
#define LL 5
#define F_IN 40

// ---------------- scratch (device globals: allocation-free) ----------------
__device__ float g_h[NN * DD];
__device__ __align__(16) __nv_bfloat16 g_aggH[NN * DD];
__device__ __align__(16) __nv_bfloat16 g_aggL[NN * DD];
__device__ __align__(16) __nv_bfloat16 g_tH[NN * 2 * DD];
__device__ __align__(16) __nv_bfloat16 g_tL[NN * 2 * DD];
__device__ uint4 g_W1t[163840];
__device__ uint4 g_W2t[163840];
__device__ float g_sum[DD];
__device__ float g_sumsq[DD];
__device__ float g_mol[GG * DD];
__device__ float g_cnt[GG];
__device__ float g_z1[GG * DD];
__device__ float g_z2[GG * DD];
// CSR (built once per call)
__device__ int g_deg[NN];
__device__ int g_rowptr[NN + 1];
__device__ int g_fill[NN];
__device__ int g_esort[EE];

// ---------------- helpers ----------------
__device__ __forceinline__ void red_add_v4(float* addr, float4 v) {
    asm volatile("red.global.add.v4.f32 [%0], {%1,%2,%3,%4};"
                 :: "l"(addr), "f"(v.x), "f"(v.y), "f"(v.z), "f"(v.w)
                 : "memory");
}
__device__ __forceinline__ void ldsm4(uint32_t r[4], uint32_t addr) {
    asm volatile("ldmatrix.sync.aligned.m8n8.x4.shared.b16 {%0,%1,%2,%3}, [%4];"
        : "=r"(r[0]), "=r"(r[1]), "=r"(r[2]), "=r"(r[3]) : "r"(addr));
}
__device__ __forceinline__ void ldsm4t(uint32_t r[4], uint32_t addr) {
    asm volatile("ldmatrix.sync.aligned.m8n8.x4.trans.shared.b16 {%0,%1,%2,%3}, [%4];"
        : "=r"(r[0]), "=r"(r[1]), "=r"(r[2]), "=r"(r[3]) : "r"(addr));
}
__device__ __forceinline__ void mma16816(float c[4], const uint32_t a[4],
                                         uint32_t b0, uint32_t b1) {
    asm volatile("mma.sync.aligned.m16n8k16.row.col.f32.bf16.bf16.f32 "
        "{%0,%1,%2,%3}, {%4,%5,%6,%7}, {%8,%9}, {%0,%1,%2,%3};"
        : "+f"(c[0]), "+f"(c[1]), "+f"(c[2]), "+f"(c[3])
        : "r"(a[0]), "r"(a[1]), "r"(a[2]), "r"(a[3]), "r"(b0), "r"(b1));
}
__device__ __forceinline__ void cpa16(uint32_t dst, const void* src, uint32_t sz) {
    asm volatile("cp.async.cg.shared.global [%0], [%1], 16, %2;"
                 :: "r"(dst), "l"(src), "r"(sz) : "memory");
}

// ---------------- embed ----------------
__global__ void embed_kernel(const float* __restrict__ x,
                             const float* __restrict__ W,
                             const float* __restrict__ b) {
    int node = blockIdx.x;
    __shared__ float xs[F_IN];
    if (threadIdx.x < F_IN) xs[threadIdx.x] = x[node * F_IN + threadIdx.x];
    __syncthreads();
    int d = threadIdx.x;
    float acc = b[d];
#pragma unroll
    for (int k = 0; k < F_IN; k++)
        acc = fmaf(xs[k], W[k * DD + d], acc);
    g_h[node * DD + d] = fmaxf(acc, 0.f);
}

// ---------------- CSR build ----------------
__global__ void zero_deg_kernel() {
    int i = blockIdx.x * 256 + threadIdx.x;
    if (i < NN) g_deg[i] = 0;
}
__global__ void hist_kernel(const int* __restrict__ dst) {
    int e = blockIdx.x * 256 + threadIdx.x;
    if (e < EE) atomicAdd(&g_deg[dst[e]], 1);
}
__global__ void scan_kernel() {
    __shared__ int ss[1024];
    int t = threadIdx.x;
    const int chunk = (NN + 1023) / 1024;
    int s0 = t * chunk;
    int s1 = min(s0 + chunk, NN);
    int s = 0;
    for (int i = s0; i < s1; i++) s += g_deg[i];
    ss[t] = s;
    __syncthreads();
    // Hillis-Steele inclusive scan
    for (int d = 1; d < 1024; d <<= 1) {
        int v = (t >= d) ? ss[t - d] : 0;
        __syncthreads();
        ss[t] += v;
        __syncthreads();
    }
    int off = ss[t] - s;   // exclusive prefix
    for (int i = s0; i < s1; i++) {
        g_rowptr[i] = off;
        g_fill[i]   = off;
        off += g_deg[i];
    }
    if (t == 1023) g_rowptr[NN] = ss[1023];
}
__global__ void fill_kernel(const int* __restrict__ dst) {
    int e = blockIdx.x * 256 + threadIdx.x;
    if (e >= EE) return;
    int pos = atomicAdd(&g_fill[dst[e]], 1);
    g_esort[pos] = e;
}

// ------- fused aggregate: agg = h[n]+ee1[4]+ee2[0]+Σ msg; write bf16 planes -
__global__ void __launch_bounds__(256) agg_kernel(const int* __restrict__ src,
                                                  const int* __restrict__ eattr,
                                                  const float* __restrict__ ee1l,
                                                  const float* __restrict__ ee2l) {
    int node = blockIdx.x * 4 + (threadIdx.x >> 6);
    int c    = threadIdx.x & 63;
    if (node >= NN) return;
    const float4* h4 = (const float4*)g_h;

    float4 acc = h4[(size_t)node * 64 + c];
    {
        float4 t1 = ((const float4*)(ee1l + 4 * DD))[c];
        float4 t2 = ((const float4*)ee2l)[c];
        acc.x += t1.x + t2.x; acc.y += t1.y + t2.y;
        acc.z += t1.z + t2.z; acc.w += t1.w + t2.w;
    }
    int p0 = g_rowptr[node], p1 = g_rowptr[node + 1];
    for (int p = p0; p < p1; p++) {
        int e  = g_esort[p];
        int s  = src[e];
        int a0 = eattr[2 * e];
        int a1 = eattr[2 * e + 1];
        float4 v  = h4[(size_t)s * 64 + c];
        float4 u1 = ((const float4*)(ee1l + a0 * DD))[c];
        float4 u2 = ((const float4*)(ee2l + a1 * DD))[c];
        acc.x += v.x + u1.x + u2.x;
        acc.y += v.y + u1.y + u2.y;
        acc.z += v.z + u1.z + u2.z;
        acc.w += v.w + u1.w + u2.w;
    }
    // split fp32 -> bf16 hi/lo
    __nv_bfloat16 hx = __float2bfloat16(acc.x), hy = __float2bfloat16(acc.y);
    __nv_bfloat16 hz = __float2bfloat16(acc.z), hw = __float2bfloat16(acc.w);
    __nv_bfloat162 h0(hx, hy), h1(hz, hw);
    __nv_bfloat162 l0(__float2bfloat16(acc.x - __bfloat162float(hx)),
                      __float2bfloat16(acc.y - __bfloat162float(hy)));
    __nv_bfloat162 l1(__float2bfloat16(acc.z - __bfloat162float(hz)),
                      __float2bfloat16(acc.w - __bfloat162float(hw)));
    uint2 h, l;
    h.x = *(uint32_t*)&h0; h.y = *(uint32_t*)&h1;
    l.x = *(uint32_t*)&l0; l.y = *(uint32_t*)&l1;
    *(uint2*)(g_aggH + (size_t)node * DD + c * 4) = h;
    *(uint2*)(g_aggL + (size_t)node * DD + c * 4) = l;
}

// ---------------- weight prep ----------------
__global__ void prep_w(const float* __restrict__ W, uint4* __restrict__ dst,
                       int Nc, int ktiles) {
    int cb = blockIdx.x, kt = blockIdx.y, l = blockIdx.z;
    const float* Wl = W + (size_t)l * (ktiles * 32) * Nc;
    char* blob = (char*)dst + (((size_t)l * gridDim.x + cb) * ktiles + kt) * 16384;
    for (int e = threadIdx.x; e < 4096; e += 256) {
        int k = e >> 7, n = e & 127;
        float v = Wl[(size_t)(kt * 32 + k) * Nc + cb * 128 + n];
        __nv_bfloat16 h = __float2bfloat16(v);
        __nv_bfloat16 lo = __float2bfloat16(v - __bfloat162float(h));
        uint32_t off = k * 256 + n * 2;
        uint32_t sw = off ^ ((k & 7) << 4);
        *(__nv_bfloat16*)(blob + sw) = h;
        *(__nv_bfloat16*)(blob + 8192 + sw) = lo;
    }
}

// ============ tensor-core GEMM, bf16 3-way split, cp.async, occ 2 ============
#define STAGE 32768
#define P_AH 0
#define P_AL 8192
#define P_BH 16384
#define P_BL 24576

template <int OUT>
__global__ void __launch_bounds__(256, 2) gemm_cp(
    const __nv_bfloat16* __restrict__ AH, const __nv_bfloat16* __restrict__ AL,
    const char* __restrict__ Btiles, const float* __restrict__ bias,
    float* __restrict__ Cf, __nv_bfloat16* __restrict__ CH,
    __nv_bfloat16* __restrict__ CL, int M, int K, int Nc) {
    extern __shared__ __align__(16) char sm[];
    const int tid  = threadIdx.x;
    const int lane = tid & 31;
    const int warp = tid >> 5;
    const int wm   = warp >> 1;
    const int wn   = warp & 1;
    const int row0 = blockIdx.y * 128;
    const int col0 = blockIdx.x * 128;
    const int ktiles = K >> 5;

    uint32_t smbase;
    asm("{ .reg .u64 t; cvta.to.shared.u64 t, %1; cvt.u32.u64 %0, t; }"
        : "=r"(smbase) : "l"(sm));

    const int m0 = tid >> 2, kq0 = tid & 3;
    const int m1 = (tid + 256) >> 2, kq1 = (tid + 256) & 3;
    const uint32_t dA0 = (uint32_t)(m0 * 64 + kq0 * 16) ^ ((m0 & 6) << 3);
    const uint32_t dA1 = (uint32_t)(m1 * 64 + kq1 * 16) ^ ((m1 & 6) << 3);
    const uint32_t ok0 = (row0 + m0 < M) ? 16u : 0u;
    const uint32_t ok1 = (row0 + m1 < M) ? 16u : 0u;
    const __nv_bfloat16* sH0 = AH + (size_t)(row0 + m0) * K + kq0 * 8;
    const __nv_bfloat16* sH1 = AH + (size_t)(row0 + m1) * K + kq1 * 8;
    const __nv_bfloat16* sL0 = AL + (size_t)(row0 + m0) * K + kq0 * 8;
    const __nv_bfloat16* sL1 = AL + (size_t)(row0 + m1) * K + kq1 * 8;
    const char* tbase = Btiles + (size_t)blockIdx.x * ktiles * 16384;

    float acc[2][8][4];
#pragma unroll
    for (int mi = 0; mi < 2; mi++)
#pragma unroll
        for (int nt = 0; nt < 8; nt++)
#pragma unroll
            for (int q = 0; q < 4; q++) acc[mi][nt][q] = 0.f;

#define ISSUE(kt, st) do {                                                    \
        uint32_t sb = smbase + (st) * STAGE;                                  \
        int ko = (kt) * 32;                                                   \
        cpa16(sb + P_AH + dA0, sH0 + ko, ok0);                                \
        cpa16(sb + P_AH + dA1, sH1 + ko, ok1);                                \
        cpa16(sb + P_AL + dA0, sL0 + ko, ok0);                                \
        cpa16(sb + P_AL + dA1, sL1 + ko, ok1);                                \
        const char* tb = tbase + (size_t)(kt) * 16384;                        \
        cpa16(sb + P_BH + tid * 16,        tb + tid * 16, 16);                \
        cpa16(sb + P_BH + tid * 16 + 4096, tb + tid * 16 + 4096, 16);         \
        cpa16(sb + P_BL + tid * 16,        tb + 8192 + tid * 16, 16);         \
        cpa16(sb + P_BL + tid * 16 + 4096, tb + 12288 + tid * 16, 16);        \
        asm volatile("cp.async.commit_group;" ::: "memory");                  \
    } while (0)

    ISSUE(0, 0);

    for (int kt = 0; kt < ktiles; kt++) {
        if (kt) __syncthreads();
        const bool more = (kt + 1) < ktiles;
        if (more) {
            ISSUE(kt + 1, (kt + 1) & 1);
            asm volatile("cp.async.wait_group 1;" ::: "memory");
        } else {
            asm volatile("cp.async.wait_group 0;" ::: "memory");
        }
        __syncthreads();

        const uint32_t cbase = smbase + (kt & 1) * STAGE;
#pragma unroll
        for (int ks = 0; ks < 2; ks++) {
            uint32_t a_h[2][4], a_l[2][4];
#pragma unroll
            for (int mi = 0; mi < 2; mi++) {
                int m = wm * 32 + mi * 16 + (lane & 15);
                int k = ks * 16 + (lane >> 4) * 8;
                uint32_t byte = (uint32_t)(m * 64 + k * 2) ^ ((m & 6) << 3);
                ldsm4(a_h[mi], cbase + P_AH + byte);
                ldsm4(a_l[mi], cbase + P_AL + byte);
            }
#pragma unroll
            for (int nj = 0; nj < 4; nj++) {
                int k = ks * 16 + (lane & 15);
                int n = wn * 64 + nj * 16 + (lane >> 4) * 8;
                uint32_t byte = (uint32_t)(k * 256 + n * 2) ^ ((k & 7) << 4);
                uint32_t bh[4], bl[4];
                ldsm4t(bh, cbase + P_BH + byte);
                ldsm4t(bl, cbase + P_BL + byte);
#pragma unroll
                for (int mi = 0; mi < 2; mi++) {
                    mma16816(acc[mi][2 * nj],     a_h[mi], bh[0], bh[1]);
                    mma16816(acc[mi][2 * nj],     a_h[mi], bl[0], bl[1]);
                    mma16816(acc[mi][2 * nj],     a_l[mi], bh[0], bh[1]);
                    mma16816(acc[mi][2 * nj + 1], a_h[mi], bh[2], bh[3]);
                    mma16816(acc[mi][2 * nj + 1], a_h[mi], bl[2], bl[3]);
                    mma16816(acc[mi][2 * nj + 1], a_l[mi], bh[2], bh[3]);
                }
            }
        }
    }
#undef ISSUE

    if (OUT == 1) {
#pragma unroll
        for (int mi = 0; mi < 2; mi++) {
            int r0 = row0 + wm * 32 + mi * 16 + (lane >> 2);
#pragma unroll
            for (int nt = 0; nt < 8; nt++) {
                int c = col0 + wn * 64 + nt * 8 + (lane & 3) * 2;
                float2 bv = *(const float2*)(bias + c);
                float* a4 = acc[mi][nt];
#pragma unroll
                for (int half = 0; half < 2; half++) {
                    int r = r0 + half * 8;
                    if (r < M) {
                        float v0 = fmaxf(a4[2 * half + 0] + bv.x, 0.f);
                        float v1 = fmaxf(a4[2 * half + 1] + bv.y, 0.f);
                        __nv_bfloat16 h0 = __float2bfloat16(v0);
                        __nv_bfloat16 h1 = __float2bfloat16(v1);
                        __nv_bfloat162 hp(h0, h1);
                        __nv_bfloat162 lp(__float2bfloat16(v0 - __bfloat162float(h0)),
                                          __float2bfloat16(v1 - __bfloat162float(h1)));
                        *(__nv_bfloat162*)(CH + (size_t)r * Nc + c) = hp;
                        *(__nv_bfloat162*)(CL + (size_t)r * Nc + c) = lp;
                    }
                }
            }
        }
    } else {
        float cs[16], cq[16];
#pragma unroll
        for (int j = 0; j < 16; j++) { cs[j] = 0.f; cq[j] = 0.f; }
#pragma unroll
        for (int mi = 0; mi < 2; mi++) {
            int r0 = row0 + wm * 32 + mi * 16 + (lane >> 2);
#pragma unroll
            for (int nt = 0; nt < 8; nt++) {
                int c = col0 + wn * 64 + nt * 8 + (lane & 3) * 2;
                float2 bv = *(const float2*)(bias + c);
                float* a4 = acc[mi][nt];
#pragma unroll
                for (int half = 0; half < 2; half++) {
                    int r = r0 + half * 8;
                    if (r < M) {
                        float v0 = a4[2 * half + 0] + bv.x;
                        float v1 = a4[2 * half + 1] + bv.y;
                        float2 o; o.x = v0; o.y = v1;
                        *(float2*)(Cf + (size_t)r * Nc + c) = o;
                        cs[nt * 2 + 0] += v0; cq[nt * 2 + 0] += v0 * v0;
                        cs[nt * 2 + 1] += v1; cq[nt * 2 + 1] += v1 * v1;
                    }
                }
            }
        }
#pragma unroll
        for (int j = 0; j < 16; j++) {
#pragma unroll
            for (int msk = 4; msk <= 16; msk <<= 1) {
                cs[j] += __shfl_xor_sync(0xFFFFFFFF, cs[j], msk);
                cq[j] += __shfl_xor_sync(0xFFFFFFFF, cq[j], msk);
            }
        }
        float* ssum = (float*)sm;
        float* ssq  = ssum + 128;
        __syncthreads();
        if (tid < 128) { ssum[tid] = 0.f; ssq[tid] = 0.f; }
        __syncthreads();
        if ((lane >> 2) == 0) {
#pragma unroll
            for (int j = 0; j < 16; j++) {
                int cl = wn * 64 + (j >> 1) * 8 + (lane & 3) * 2 + (j & 1);
                atomicAdd(&ssum[cl], cs[j]);
                atomicAdd(&ssq[cl],  cq[j]);
            }
        }
        __syncthreads();
        if (tid < 128) {
            atomicAdd(&g_sum[col0 + tid],   ssum[tid]);
            atomicAdd(&g_sumsq[col0 + tid], ssq[tid]);
        }
    }
}

// ---------------- small GEMM (head MLP) ----------------
template <int RELU>
__global__ void __launch_bounds__(256) gemm_bias(const float* __restrict__ A,
                                                 const float* __restrict__ B,
                                                 const float* __restrict__ bias,
                                                 float* __restrict__ C,
                                                 int M, int K, int Nc) {
    __shared__ float As[16][64];
    __shared__ float Bs[16][64];

    int tid  = threadIdx.x;
    int row0 = blockIdx.y * 64;
    int col0 = blockIdx.x * 64;
    int ty   = tid >> 4;
    int tx   = tid & 15;

    int ar = tid >> 2;
    int ak = (tid & 3) * 4;
    int bk = tid >> 4;
    int bc = (tid & 15) * 4;

    float acc[4][4];
#pragma unroll
    for (int i = 0; i < 4; i++)
#pragma unroll
        for (int j = 0; j < 4; j++) acc[i][j] = 0.f;

    int arow = row0 + ar;
    int bcol = col0 + bc;

    for (int k0 = 0; k0 < K; k0 += 16) {
        float4 av = make_float4(0.f, 0.f, 0.f, 0.f);
        if (arow < M)
            av = *(const float4*)(A + (size_t)arow * K + k0 + ak);
        As[ak + 0][ar] = av.x;
        As[ak + 1][ar] = av.y;
        As[ak + 2][ar] = av.z;
        As[ak + 3][ar] = av.w;

        float4 bv = make_float4(0.f, 0.f, 0.f, 0.f);
        if (bcol < Nc)
            bv = *(const float4*)(B + (size_t)(k0 + bk) * Nc + bcol);
        *(float4*)(&Bs[bk][bc]) = bv;

        __syncthreads();
#pragma unroll
        for (int k = 0; k < 16; k++) {
            float4 a4 = *(const float4*)(&As[k][ty * 4]);
            float4 b4 = *(const float4*)(&Bs[k][tx * 4]);
            float a[4] = {a4.x, a4.y, a4.z, a4.w};
            float b[4] = {b4.x, b4.y, b4.z, b4.w};
#pragma unroll
            for (int i = 0; i < 4; i++)
#pragma unroll
                for (int j = 0; j < 4; j++)
                    acc[i][j] = fmaf(a[i], b[j], acc[i][j]);
        }
        __syncthreads();
    }

#pragma unroll
    for (int i = 0; i < 4; i++) {
        int r = row0 + ty * 4 + i;
        if (r < M) {
#pragma unroll
            for (int j = 0; j < 4; j++) {
                int c = col0 + tx * 4 + j;
                if (c < Nc) {
                    float v = acc[i][j] + bias[c];
                    if (RELU) v = fmaxf(v, 0.f);
                    C[(size_t)r * Nc + c] = v;
                }
            }
        }
    }
}

// ---------------- batchnorm ----------------
__global__ void zero_stats_kernel() {
    g_sum[threadIdx.x]   = 0.f;
    g_sumsq[threadIdx.x] = 0.f;
}

__global__ void bn_apply_kernel(const float* __restrict__ gamma,
                                const float* __restrict__ beta,
                                int relu) {
    int i = blockIdx.x * 256 + threadIdx.x;
    if (i >= NN * DD) return;
    int d = i & (DD - 1);
    const float invN = 1.f / (float)NN;
    float mu  = g_sum[d] * invN;
    float var = g_sumsq[d] * invN - mu * mu;
    float v = (g_h[i] - mu) * rsqrtf(var + 1e-5f) * gamma[d] + beta[d];
    g_h[i] = relu ? fmaxf(v, 0.f) : v;
}

// ---------------- pooling ----------------
__global__ void zero_pool_kernel() {
    int i = blockIdx.x * 256 + threadIdx.x;
    if (i < GG * DD) g_mol[i] = 0.f;
    if (i < GG) g_cnt[i] = 0.f;
}

__global__ void count_kernel(const int* __restrict__ batch) {
    int i = blockIdx.x * 256 + threadIdx.x;
    if (i < NN) atomicAdd(&g_cnt[batch[i]], 1.f);
}

__global__ void pool_scatter_kernel(const int* __restrict__ batch) {
    int n = blockIdx.x * 4 + (threadIdx.x >> 6);
    int c = threadIdx.x & 63;
    if (n >= NN) return;
    int g = batch[n];
    float4 v = ((const float4*)(g_h + (size_t)n * DD))[c];
    red_add_v4(g_mol + (size_t)g * DD + c * 4, v);
}

__global__ void pool_div_kernel() {
    int i = blockIdx.x * 256 + threadIdx.x;
    if (i >= GG * DD) return;
    g_mol[i] /= fmaxf(g_cnt[i >> 8], 1.f);
}

// ---------------- head final ----------------
__global__ void head_final_kernel(const float* __restrict__ w,
                                  const float* __restrict__ b,
                                  float* __restrict__ out) {
    int g = blockIdx.x * 256 + threadIdx.x;
    if (g >= GG) return;
    float acc = b[0];
#pragma unroll
    for (int k = 0; k < 32; k++)
        acc = fmaf(g_z2[g * 32 + k], w[k], acc);
    out[g] = acc;
}

// ---------------- launch ----------------
extern "C" void kernel_launch(void* const* d_in, const int* in_sizes, int n_in,
                              void* d_out, int out_size) {
    const float* x          = (const float*)d_in[0];
    const int*   edge_index = (const int*)d_in[1];
    const int*   edge_attr  = (const int*)d_in[2];
    const int*   batch      = (const int*)d_in[3];
    const float* embW       = (const float*)d_in[4];
    const float* embB       = (const float*)d_in[5];
    const float* ee1        = (const float*)d_in[6];
    const float* ee2        = (const float*)d_in[7];
    const float* W1         = (const float*)d_in[8];
    const float* b1         = (const float*)d_in[9];
    const float* W2         = (const float*)d_in[10];
    const float* b2         = (const float*)d_in[11];
    const float* bn_g       = (const float*)d_in[12];
    const float* bn_b       = (const float*)d_in[13];
    const float* hW0 = (const float*)d_in[14];
    const float* hb0 = (const float*)d_in[15];
    const float* hW1 = (const float*)d_in[16];
    const float* hb1 = (const float*)d_in[17];
    const float* hW2 = (const float*)d_in[18];
    const float* hb2 = (const float*)d_in[19];
    const float* hW3 = (const float*)d_in[20];
    const float* hb3 = (const float*)d_in[21];
    const float* hWo = (const float*)d_in[22];
    const float* hbo = (const float*)d_in[23];
    float* out = (float*)d_out;

    const int* src = edge_index;
    const int* dst = edge_index + EE;

    float *p_h, *p_mol, *p_z1, *p_z2;
    __nv_bfloat16 *p_aggH, *p_aggL, *p_tH, *p_tL;
    uint4 *p_W1t, *p_W2t;
    cudaGetSymbolAddress((void**)&p_h,    g_h);
    cudaGetSymbolAddress((void**)&p_mol,  g_mol);
    cudaGetSymbolAddress((void**)&p_z1,   g_z1);
    cudaGetSymbolAddress((void**)&p_z2,   g_z2);
    cudaGetSymbolAddress((void**)&p_aggH, g_aggH);
    cudaGetSymbolAddress((void**)&p_aggL, g_aggL);
    cudaGetSymbolAddress((void**)&p_tH,   g_tH);
    cudaGetSymbolAddress((void**)&p_tL,   g_tL);
    cudaGetSymbolAddress((void**)&p_W1t,  g_W1t);
    cudaGetSymbolAddress((void**)&p_W2t,  g_W2t);

    static int smem_set = 0;
    if (!smem_set) {
        cudaFuncSetAttribute(gemm_cp<1>, cudaFuncAttributeMaxDynamicSharedMemorySize, 2 * STAGE);
        cudaFuncSetAttribute(gemm_cp<0>, cudaFuncAttributeMaxDynamicSharedMemorySize, 2 * STAGE);
        smem_set = 1;
    }

    const int elemGrid  = (NN * DD + 255) / 256;
    const int rowBlocks = (NN + 127) / 128;

    // weight prep + CSR build (once per call)
    prep_w<<<dim3(4, 8, 5),  256>>>(W1, p_W1t, 512, 8);
    prep_w<<<dim3(2, 16, 5), 256>>>(W2, p_W2t, 256, 16);
    zero_deg_kernel<<<(NN + 255) / 256, 256>>>();
    hist_kernel<<<(EE + 255) / 256, 256>>>(dst);
    scan_kernel<<<1, 1024>>>();
    fill_kernel<<<(EE + 255) / 256, 256>>>(dst);

    embed_kernel<<<NN, 256>>>(x, embW, embB);

    for (int l = 0; l < LL; l++) {
        const float* ee1l = ee1 + (size_t)l * 6 * DD;
        const float* ee2l = ee2 + (size_t)l * 3 * DD;
        agg_kernel<<<(NN + 3) / 4, 256>>>(src, edge_attr, ee1l, ee2l);
        gemm_cp<1><<<dim3(4, rowBlocks), 256, 2 * STAGE>>>(
            p_aggH, p_aggL, (const char*)p_W1t + (size_t)l * 4 * 8 * 16384,
            b1 + (size_t)l * 2 * DD, nullptr, p_tH, p_tL, NN, DD, 2 * DD);
        zero_stats_kernel<<<1, 256>>>();
        gemm_cp<0><<<dim3(2, rowBlocks), 256, 2 * STAGE>>>(
            p_tH, p_tL, (const char*)p_W2t + (size_t)l * 2 * 16 * 16384,
            b2 + (size_t)l * DD, p_h, nullptr, nullptr, NN, 2 * DD, DD);
        bn_apply_kernel<<<elemGrid, 256>>>(bn_g + (size_t)l * DD,
                                           bn_b + (size_t)l * DD,
                                           (l < LL - 1) ? 1 : 0);
    }

    zero_pool_kernel<<<(GG * DD + 255) / 256, 256>>>();
    count_kernel<<<(NN + 255) / 256, 256>>>(batch);
    pool_scatter_kernel<<<(NN + 3) / 4, 256>>>(batch);
    pool_div_kernel<<<(GG * DD + 255) / 256, 256>>>();

    gemm_bias<1><<<dim3(4, (GG + 63) / 64), 256>>>(p_mol, hW0, hb0, p_z1, GG, 256, 256);
    gemm_bias<1><<<dim3(2, (GG + 63) / 64), 256>>>(p_z1,  hW1, hb1, p_z2, GG, 256, 128);
    gemm_bias<1><<<dim3(1, (GG + 63) / 64), 256>>>(p_z2,  hW2, hb2, p_z1, GG, 128, 64);
    gemm_bias<1><<<dim3(1, (GG + 63) / 64), 256>>>(p_z1,  hW3, hb3, p_z2, GG, 64, 32);
    head_final_kernel<<<(GG + 255) / 256, 256>>>(hWo, hbo, out);
}

// round 8
// speedup vs baseline: 2.9700x; 1.0490x over previous
#include <cuda_runtime.h>
#include <cuda_bf16.h>
#include <cstdint>

#define NN 100000
#define EE 300000
#define DD 256
#define GG 4000
#define LL 5
#define F_IN 40

// ---------------- scratch (device globals: allocation-free) ----------------
__device__ float g_h[NN * DD];                     // raw (pre-BN) features
__device__ __align__(16) __nv_bfloat16 g_aggH[NN * DD];
__device__ __align__(16) __nv_bfloat16 g_aggL[NN * DD];
__device__ __align__(16) __nv_bfloat16 g_tH[NN * 2 * DD];
__device__ __align__(16) __nv_bfloat16 g_tL[NN * 2 * DD];
__device__ uint4 g_W1t[163840];
__device__ uint4 g_W2t[163840];
__device__ float g_sum[DD];
__device__ float g_sumsq[DD];
__device__ float g_bna[DD];
__device__ float g_bnc[DD];
__device__ float g_mol[GG * DD];
__device__ float g_cnt[GG];
__device__ float g_z1[GG * DD];
__device__ float g_z2[GG * DD];
// CSR (built once per call)
__device__ int g_deg[NN];
__device__ int g_rowptr[NN + 1];
__device__ int g_fill[NN];
__device__ int g_esort[EE];

// ---------------- helpers ----------------
__device__ __forceinline__ void red_add_v4(float* addr, float4 v) {
    asm volatile("red.global.add.v4.f32 [%0], {%1,%2,%3,%4};"
                 :: "l"(addr), "f"(v.x), "f"(v.y), "f"(v.z), "f"(v.w)
                 : "memory");
}
__device__ __forceinline__ void ldsm4(uint32_t r[4], uint32_t addr) {
    asm volatile("ldmatrix.sync.aligned.m8n8.x4.shared.b16 {%0,%1,%2,%3}, [%4];"
        : "=r"(r[0]), "=r"(r[1]), "=r"(r[2]), "=r"(r[3]) : "r"(addr));
}
__device__ __forceinline__ void ldsm4t(uint32_t r[4], uint32_t addr) {
    asm volatile("ldmatrix.sync.aligned.m8n8.x4.trans.shared.b16 {%0,%1,%2,%3}, [%4];"
        : "=r"(r[0]), "=r"(r[1]), "=r"(r[2]), "=r"(r[3]) : "r"(addr));
}
__device__ __forceinline__ void mma16816(float c[4], const uint32_t a[4],
                                         uint32_t b0, uint32_t b1) {
    asm volatile("mma.sync.aligned.m16n8k16.row.col.f32.bf16.bf16.f32 "
        "{%0,%1,%2,%3}, {%4,%5,%6,%7}, {%8,%9}, {%0,%1,%2,%3};"
        : "+f"(c[0]), "+f"(c[1]), "+f"(c[2]), "+f"(c[3])
        : "r"(a[0]), "r"(a[1]), "r"(a[2]), "r"(a[3]), "r"(b0), "r"(b1));
}
__device__ __forceinline__ void cpa16(uint32_t dst, const void* src, uint32_t sz) {
    asm volatile("cp.async.cg.shared.global [%0], [%1], 16, %2;"
                 :: "r"(dst), "l"(src), "r"(sz) : "memory");
}

// ---------------- embed ----------------
__global__ void embed_kernel(const float* __restrict__ x,
                             const float* __restrict__ W,
                             const float* __restrict__ b) {
    int node = blockIdx.x;
    __shared__ float xs[F_IN];
    if (threadIdx.x < F_IN) xs[threadIdx.x] = x[node * F_IN + threadIdx.x];
    __syncthreads();
    int d = threadIdx.x;
    float acc = b[d];
#pragma unroll
    for (int k = 0; k < F_IN; k++)
        acc = fmaf(xs[k], W[k * DD + d], acc);
    g_h[node * DD + d] = fmaxf(acc, 0.f);
}

// ---------------- CSR build ----------------
__global__ void zero_deg_kernel() {
    int i = blockIdx.x * 256 + threadIdx.x;
    if (i < NN) g_deg[i] = 0;
}
__global__ void hist_kernel(const int* __restrict__ dst) {
    int e = blockIdx.x * 256 + threadIdx.x;
    if (e < EE) atomicAdd(&g_deg[dst[e]], 1);
}
__global__ void scan_kernel() {
    __shared__ int ss[1024];
    int t = threadIdx.x;
    const int chunk = (NN + 1023) / 1024;
    int s0 = t * chunk;
    int s1 = min(s0 + chunk, NN);
    int s = 0;
    for (int i = s0; i < s1; i++) s += g_deg[i];
    ss[t] = s;
    __syncthreads();
    for (int d = 1; d < 1024; d <<= 1) {
        int v = (t >= d) ? ss[t - d] : 0;
        __syncthreads();
        ss[t] += v;
        __syncthreads();
    }
    int off = ss[t] - s;
    for (int i = s0; i < s1; i++) {
        g_rowptr[i] = off;
        g_fill[i]   = off;
        off += g_deg[i];
    }
    if (t == 1023) g_rowptr[NN] = ss[1023];
}
__global__ void fill_kernel(const int* __restrict__ dst) {
    int e = blockIdx.x * 256 + threadIdx.x;
    if (e >= EE) return;
    int pos = atomicAdd(&g_fill[dst[e]], 1);
    g_esort[pos] = e;
}

// ------- fused aggregate with lazy BN+relu on gathered values ----------
// f(v) = useBN ? max(a*v + c, 0) : v   (h already relu'd when useBN==0)
__global__ void __launch_bounds__(256) agg_kernel(const int* __restrict__ src,
                                                  const int* __restrict__ eattr,
                                                  const float* __restrict__ ee1l,
                                                  const float* __restrict__ ee2l,
                                                  int useBN) {
    int node = blockIdx.x * 4 + (threadIdx.x >> 6);
    int c    = threadIdx.x & 63;
    if (node >= NN) return;
    const float4* h4 = (const float4*)g_h;

    float4 av = make_float4(1.f, 1.f, 1.f, 1.f);
    float4 cv = make_float4(0.f, 0.f, 0.f, 0.f);
    if (useBN) {
        av = ((const float4*)g_bna)[c];
        cv = ((const float4*)g_bnc)[c];
    }

    float4 v = h4[(size_t)node * 64 + c];
    float4 acc;
    if (useBN) {
        acc.x = fmaxf(fmaf(av.x, v.x, cv.x), 0.f);
        acc.y = fmaxf(fmaf(av.y, v.y, cv.y), 0.f);
        acc.z = fmaxf(fmaf(av.z, v.z, cv.z), 0.f);
        acc.w = fmaxf(fmaf(av.w, v.w, cv.w), 0.f);
    } else {
        acc = v;
    }
    {
        float4 t1 = ((const float4*)(ee1l + 4 * DD))[c];
        float4 t2 = ((const float4*)ee2l)[c];
        acc.x += t1.x + t2.x; acc.y += t1.y + t2.y;
        acc.z += t1.z + t2.z; acc.w += t1.w + t2.w;
    }
    int p0 = g_rowptr[node], p1 = g_rowptr[node + 1];
    for (int p = p0; p < p1; p++) {
        int e  = g_esort[p];
        int s  = src[e];
        int a0 = eattr[2 * e];
        int a1 = eattr[2 * e + 1];
        float4 w  = h4[(size_t)s * 64 + c];
        if (useBN) {
            w.x = fmaxf(fmaf(av.x, w.x, cv.x), 0.f);
            w.y = fmaxf(fmaf(av.y, w.y, cv.y), 0.f);
            w.z = fmaxf(fmaf(av.z, w.z, cv.z), 0.f);
            w.w = fmaxf(fmaf(av.w, w.w, cv.w), 0.f);
        }
        float4 u1 = ((const float4*)(ee1l + a0 * DD))[c];
        float4 u2 = ((const float4*)(ee2l + a1 * DD))[c];
        acc.x += w.x + u1.x + u2.x;
        acc.y += w.y + u1.y + u2.y;
        acc.z += w.z + u1.z + u2.z;
        acc.w += w.w + u1.w + u2.w;
    }
    // split fp32 -> bf16 hi/lo
    __nv_bfloat16 hx = __float2bfloat16(acc.x), hy = __float2bfloat16(acc.y);
    __nv_bfloat16 hz = __float2bfloat16(acc.z), hw = __float2bfloat16(acc.w);
    __nv_bfloat162 h0(hx, hy), h1(hz, hw);
    __nv_bfloat162 l0(__float2bfloat16(acc.x - __bfloat162float(hx)),
                      __float2bfloat16(acc.y - __bfloat162float(hy)));
    __nv_bfloat162 l1(__float2bfloat16(acc.z - __bfloat162float(hz)),
                      __float2bfloat16(acc.w - __bfloat162float(hw)));
    uint2 h, l;
    h.x = *(uint32_t*)&h0; h.y = *(uint32_t*)&h1;
    l.x = *(uint32_t*)&l0; l.y = *(uint32_t*)&l1;
    *(uint2*)(g_aggH + (size_t)node * DD + c * 4) = h;
    *(uint2*)(g_aggL + (size_t)node * DD + c * 4) = l;
}

// ---------------- weight prep ----------------
__global__ void prep_w(const float* __restrict__ W, uint4* __restrict__ dst,
                       int Nc, int ktiles) {
    int cb = blockIdx.x, kt = blockIdx.y, l = blockIdx.z;
    const float* Wl = W + (size_t)l * (ktiles * 32) * Nc;
    char* blob = (char*)dst + (((size_t)l * gridDim.x + cb) * ktiles + kt) * 16384;
    for (int e = threadIdx.x; e < 4096; e += 256) {
        int k = e >> 7, n = e & 127;
        float v = Wl[(size_t)(kt * 32 + k) * Nc + cb * 128 + n];
        __nv_bfloat16 h = __float2bfloat16(v);
        __nv_bfloat16 lo = __float2bfloat16(v - __bfloat162float(h));
        uint32_t off = k * 256 + n * 2;
        uint32_t sw = off ^ ((k & 7) << 4);
        *(__nv_bfloat16*)(blob + sw) = h;
        *(__nv_bfloat16*)(blob + 8192 + sw) = lo;
    }
}

// ============ tensor-core GEMM, bf16 3-way split, cp.async, occ 2 ============
#define STAGE 32768
#define P_AH 0
#define P_AL 8192
#define P_BH 16384
#define P_BL 24576

template <int OUT>
__global__ void __launch_bounds__(256, 2) gemm_cp(
    const __nv_bfloat16* __restrict__ AH, const __nv_bfloat16* __restrict__ AL,
    const char* __restrict__ Btiles, const float* __restrict__ bias,
    float* __restrict__ Cf, __nv_bfloat16* __restrict__ CH,
    __nv_bfloat16* __restrict__ CL, int M, int K, int Nc) {
    extern __shared__ __align__(16) char sm[];
    const int tid  = threadIdx.x;
    const int lane = tid & 31;
    const int warp = tid >> 5;
    const int wm   = warp >> 1;
    const int wn   = warp & 1;
    const int row0 = blockIdx.y * 128;
    const int col0 = blockIdx.x * 128;
    const int ktiles = K >> 5;

    uint32_t smbase;
    asm("{ .reg .u64 t; cvta.to.shared.u64 t, %1; cvt.u32.u64 %0, t; }"
        : "=r"(smbase) : "l"(sm));

    const int m0 = tid >> 2, kq0 = tid & 3;
    const int m1 = (tid + 256) >> 2, kq1 = (tid + 256) & 3;
    const uint32_t dA0 = (uint32_t)(m0 * 64 + kq0 * 16) ^ ((m0 & 6) << 3);
    const uint32_t dA1 = (uint32_t)(m1 * 64 + kq1 * 16) ^ ((m1 & 6) << 3);
    const uint32_t ok0 = (row0 + m0 < M) ? 16u : 0u;
    const uint32_t ok1 = (row0 + m1 < M) ? 16u : 0u;
    const __nv_bfloat16* sH0 = AH + (size_t)(row0 + m0) * K + kq0 * 8;
    const __nv_bfloat16* sH1 = AH + (size_t)(row0 + m1) * K + kq1 * 8;
    const __nv_bfloat16* sL0 = AL + (size_t)(row0 + m0) * K + kq0 * 8;
    const __nv_bfloat16* sL1 = AL + (size_t)(row0 + m1) * K + kq1 * 8;
    const char* tbase = Btiles + (size_t)blockIdx.x * ktiles * 16384;

    float acc[2][8][4];
#pragma unroll
    for (int mi = 0; mi < 2; mi++)
#pragma unroll
        for (int nt = 0; nt < 8; nt++)
#pragma unroll
            for (int q = 0; q < 4; q++) acc[mi][nt][q] = 0.f;

#define ISSUE(kt, st) do {                                                    \
        uint32_t sb = smbase + (st) * STAGE;                                  \
        int ko = (kt) * 32;                                                   \
        cpa16(sb + P_AH + dA0, sH0 + ko, ok0);                                \
        cpa16(sb + P_AH + dA1, sH1 + ko, ok1);                                \
        cpa16(sb + P_AL + dA0, sL0 + ko, ok0);                                \
        cpa16(sb + P_AL + dA1, sL1 + ko, ok1);                                \
        const char* tb = tbase + (size_t)(kt) * 16384;                        \
        cpa16(sb + P_BH + tid * 16,        tb + tid * 16, 16);                \
        cpa16(sb + P_BH + tid * 16 + 4096, tb + tid * 16 + 4096, 16);         \
        cpa16(sb + P_BL + tid * 16,        tb + 8192 + tid * 16, 16);         \
        cpa16(sb + P_BL + tid * 16 + 4096, tb + 12288 + tid * 16, 16);        \
        asm volatile("cp.async.commit_group;" ::: "memory");                  \
    } while (0)

    ISSUE(0, 0);

    for (int kt = 0; kt < ktiles; kt++) {
        if (kt) __syncthreads();
        const bool more = (kt + 1) < ktiles;
        if (more) {
            ISSUE(kt + 1, (kt + 1) & 1);
            asm volatile("cp.async.wait_group 1;" ::: "memory");
        } else {
            asm volatile("cp.async.wait_group 0;" ::: "memory");
        }
        __syncthreads();

        const uint32_t cbase = smbase + (kt & 1) * STAGE;
#pragma unroll
        for (int ks = 0; ks < 2; ks++) {
            uint32_t a_h[2][4], a_l[2][4];
#pragma unroll
            for (int mi = 0; mi < 2; mi++) {
                int m = wm * 32 + mi * 16 + (lane & 15);
                int k = ks * 16 + (lane >> 4) * 8;
                uint32_t byte = (uint32_t)(m * 64 + k * 2) ^ ((m & 6) << 3);
                ldsm4(a_h[mi], cbase + P_AH + byte);
                ldsm4(a_l[mi], cbase + P_AL + byte);
            }
#pragma unroll
            for (int nj = 0; nj < 4; nj++) {
                int k = ks * 16 + (lane & 15);
                int n = wn * 64 + nj * 16 + (lane >> 4) * 8;
                uint32_t byte = (uint32_t)(k * 256 + n * 2) ^ ((k & 7) << 4);
                uint32_t bh[4], bl[4];
                ldsm4t(bh, cbase + P_BH + byte);
                ldsm4t(bl, cbase + P_BL + byte);
#pragma unroll
                for (int mi = 0; mi < 2; mi++) {
                    mma16816(acc[mi][2 * nj],     a_h[mi], bh[0], bh[1]);
                    mma16816(acc[mi][2 * nj],     a_h[mi], bl[0], bl[1]);
                    mma16816(acc[mi][2 * nj],     a_l[mi], bh[0], bh[1]);
                    mma16816(acc[mi][2 * nj + 1], a_h[mi], bh[2], bh[3]);
                    mma16816(acc[mi][2 * nj + 1], a_h[mi], bl[2], bl[3]);
                    mma16816(acc[mi][2 * nj + 1], a_l[mi], bh[2], bh[3]);
                }
            }
        }
    }
#undef ISSUE

    if (OUT == 1) {
#pragma unroll
        for (int mi = 0; mi < 2; mi++) {
            int r0 = row0 + wm * 32 + mi * 16 + (lane >> 2);
#pragma unroll
            for (int nt = 0; nt < 8; nt++) {
                int c = col0 + wn * 64 + nt * 8 + (lane & 3) * 2;
                float2 bv = *(const float2*)(bias + c);
                float* a4 = acc[mi][nt];
#pragma unroll
                for (int half = 0; half < 2; half++) {
                    int r = r0 + half * 8;
                    if (r < M) {
                        float v0 = fmaxf(a4[2 * half + 0] + bv.x, 0.f);
                        float v1 = fmaxf(a4[2 * half + 1] + bv.y, 0.f);
                        __nv_bfloat16 h0 = __float2bfloat16(v0);
                        __nv_bfloat16 h1 = __float2bfloat16(v1);
                        __nv_bfloat162 hp(h0, h1);
                        __nv_bfloat162 lp(__float2bfloat16(v0 - __bfloat162float(h0)),
                                          __float2bfloat16(v1 - __bfloat162float(h1)));
                        *(__nv_bfloat162*)(CH + (size_t)r * Nc + c) = hp;
                        *(__nv_bfloat162*)(CL + (size_t)r * Nc + c) = lp;
                    }
                }
            }
        }
    } else {
        float cs[16], cq[16];
#pragma unroll
        for (int j = 0; j < 16; j++) { cs[j] = 0.f; cq[j] = 0.f; }
#pragma unroll
        for (int mi = 0; mi < 2; mi++) {
            int r0 = row0 + wm * 32 + mi * 16 + (lane >> 2);
#pragma unroll
            for (int nt = 0; nt < 8; nt++) {
                int c = col0 + wn * 64 + nt * 8 + (lane & 3) * 2;
                float2 bv = *(const float2*)(bias + c);
                float* a4 = acc[mi][nt];
#pragma unroll
                for (int half = 0; half < 2; half++) {
                    int r = r0 + half * 8;
                    if (r < M) {
                        float v0 = a4[2 * half + 0] + bv.x;
                        float v1 = a4[2 * half + 1] + bv.y;
                        float2 o; o.x = v0; o.y = v1;
                        *(float2*)(Cf + (size_t)r * Nc + c) = o;
                        cs[nt * 2 + 0] += v0; cq[nt * 2 + 0] += v0 * v0;
                        cs[nt * 2 + 1] += v1; cq[nt * 2 + 1] += v1 * v1;
                    }
                }
            }
        }
#pragma unroll
        for (int j = 0; j < 16; j++) {
#pragma unroll
            for (int msk = 4; msk <= 16; msk <<= 1) {
                cs[j] += __shfl_xor_sync(0xFFFFFFFF, cs[j], msk);
                cq[j] += __shfl_xor_sync(0xFFFFFFFF, cq[j], msk);
            }
        }
        float* ssum = (float*)sm;
        float* ssq  = ssum + 128;
        __syncthreads();
        if (tid < 128) { ssum[tid] = 0.f; ssq[tid] = 0.f; }
        __syncthreads();
        if ((lane >> 2) == 0) {
#pragma unroll
            for (int j = 0; j < 16; j++) {
                int cl = wn * 64 + (j >> 1) * 8 + (lane & 3) * 2 + (j & 1);
                atomicAdd(&ssum[cl], cs[j]);
                atomicAdd(&ssq[cl],  cq[j]);
            }
        }
        __syncthreads();
        if (tid < 128) {
            atomicAdd(&g_sum[col0 + tid],   ssum[tid]);
            atomicAdd(&g_sumsq[col0 + tid], ssq[tid]);
        }
    }
}

// ---------------- small GEMM (head MLP) ----------------
template <int RELU>
__global__ void __launch_bounds__(256) gemm_bias(const float* __restrict__ A,
                                                 const float* __restrict__ B,
                                                 const float* __restrict__ bias,
                                                 float* __restrict__ C,
                                                 int M, int K, int Nc) {
    __shared__ float As[16][64];
    __shared__ float Bs[16][64];

    int tid  = threadIdx.x;
    int row0 = blockIdx.y * 64;
    int col0 = blockIdx.x * 64;
    int ty   = tid >> 4;
    int tx   = tid & 15;

    int ar = tid >> 2;
    int ak = (tid & 3) * 4;
    int bk = tid >> 4;
    int bc = (tid & 15) * 4;

    float acc[4][4];
#pragma unroll
    for (int i = 0; i < 4; i++)
#pragma unroll
        for (int j = 0; j < 4; j++) acc[i][j] = 0.f;

    int arow = row0 + ar;
    int bcol = col0 + bc;

    for (int k0 = 0; k0 < K; k0 += 16) {
        float4 av = make_float4(0.f, 0.f, 0.f, 0.f);
        if (arow < M)
            av = *(const float4*)(A + (size_t)arow * K + k0 + ak);
        As[ak + 0][ar] = av.x;
        As[ak + 1][ar] = av.y;
        As[ak + 2][ar] = av.z;
        As[ak + 3][ar] = av.w;

        float4 bv = make_float4(0.f, 0.f, 0.f, 0.f);
        if (bcol < Nc)
            bv = *(const float4*)(B + (size_t)(k0 + bk) * Nc + bcol);
        *(float4*)(&Bs[bk][bc]) = bv;

        __syncthreads();
#pragma unroll
        for (int k = 0; k < 16; k++) {
            float4 a4 = *(const float4*)(&As[k][ty * 4]);
            float4 b4 = *(const float4*)(&Bs[k][tx * 4]);
            float a[4] = {a4.x, a4.y, a4.z, a4.w};
            float b[4] = {b4.x, b4.y, b4.z, b4.w};
#pragma unroll
            for (int i = 0; i < 4; i++)
#pragma unroll
                for (int j = 0; j < 4; j++)
                    acc[i][j] = fmaf(a[i], b[j], acc[i][j]);
        }
        __syncthreads();
    }

#pragma unroll
    for (int i = 0; i < 4; i++) {
        int r = row0 + ty * 4 + i;
        if (r < M) {
#pragma unroll
            for (int j = 0; j < 4; j++) {
                int c = col0 + tx * 4 + j;
                if (c < Nc) {
                    float v = acc[i][j] + bias[c];
                    if (RELU) v = fmaxf(v, 0.f);
                    C[(size_t)r * Nc + c] = v;
                }
            }
        }
    }
}

// ---------------- batchnorm coefficients ----------------
__global__ void zero_stats_kernel() {
    g_sum[threadIdx.x]   = 0.f;
    g_sumsq[threadIdx.x] = 0.f;
}

__global__ void bn_coef_kernel(const float* __restrict__ gamma,
                               const float* __restrict__ beta) {
    int d = threadIdx.x;
    const float invN = 1.f / (float)NN;
    float mu  = g_sum[d] * invN;
    float var = g_sumsq[d] * invN - mu * mu;
    float a = gamma[d] * rsqrtf(var + 1e-5f);
    g_bna[d] = a;
    g_bnc[d] = beta[d] - mu * a;
}

// ---------------- pooling (applies last-layer BN affine, no relu) ----------
__global__ void zero_pool_kernel() {
    int i = blockIdx.x * 256 + threadIdx.x;
    if (i < GG * DD) g_mol[i] = 0.f;
    if (i < GG) g_cnt[i] = 0.f;
}

__global__ void count_kernel(const int* __restrict__ batch) {
    int i = blockIdx.x * 256 + threadIdx.x;
    if (i < NN) atomicAdd(&g_cnt[batch[i]], 1.f);
}

__global__ void pool_scatter_kernel(const int* __restrict__ batch) {
    int n = blockIdx.x * 4 + (threadIdx.x >> 6);
    int c = threadIdx.x & 63;
    if (n >= NN) return;
    int g = batch[n];
    float4 v  = ((const float4*)(g_h + (size_t)n * DD))[c];
    float4 av = ((const float4*)g_bna)[c];
    float4 cv = ((const float4*)g_bnc)[c];
    v.x = fmaf(av.x, v.x, cv.x);
    v.y = fmaf(av.y, v.y, cv.y);
    v.z = fmaf(av.z, v.z, cv.z);
    v.w = fmaf(av.w, v.w, cv.w);
    red_add_v4(g_mol + (size_t)g * DD + c * 4, v);
}

__global__ void pool_div_kernel() {
    int i = blockIdx.x * 256 + threadIdx.x;
    if (i >= GG * DD) return;
    g_mol[i] /= fmaxf(g_cnt[i >> 8], 1.f);
}

// ---------------- head final ----------------
__global__ void head_final_kernel(const float* __restrict__ w,
                                  const float* __restrict__ b,
                                  float* __restrict__ out) {
    int g = blockIdx.x * 256 + threadIdx.x;
    if (g >= GG) return;
    float acc = b[0];
#pragma unroll
    for (int k = 0; k < 32; k++)
        acc = fmaf(g_z2[g * 32 + k], w[k], acc);
    out[g] = acc;
}

// ---------------- launch ----------------
extern "C" void kernel_launch(void* const* d_in, const int* in_sizes, int n_in,
                              void* d_out, int out_size) {
    const float* x          = (const float*)d_in[0];
    const int*   edge_index = (const int*)d_in[1];
    const int*   edge_attr  = (const int*)d_in[2];
    const int*   batch      = (const int*)d_in[3];
    const float* embW       = (const float*)d_in[4];
    const float* embB       = (const float*)d_in[5];
    const float* ee1        = (const float*)d_in[6];
    const float* ee2        = (const float*)d_in[7];
    const float* W1         = (const float*)d_in[8];
    const float* b1         = (const float*)d_in[9];
    const float* W2         = (const float*)d_in[10];
    const float* b2         = (const float*)d_in[11];
    const float* bn_g       = (const float*)d_in[12];
    const float* bn_b       = (const float*)d_in[13];
    const float* hW0 = (const float*)d_in[14];
    const float* hb0 = (const float*)d_in[15];
    const float* hW1 = (const float*)d_in[16];
    const float* hb1 = (const float*)d_in[17];
    const float* hW2 = (const float*)d_in[18];
    const float* hb2 = (const float*)d_in[19];
    const float* hW3 = (const float*)d_in[20];
    const float* hb3 = (const float*)d_in[21];
    const float* hWo = (const float*)d_in[22];
    const float* hbo = (const float*)d_in[23];
    float* out = (float*)d_out;

    const int* src = edge_index;
    const int* dst = edge_index + EE;

    float *p_h, *p_mol, *p_z1, *p_z2;
    __nv_bfloat16 *p_aggH, *p_aggL, *p_tH, *p_tL;
    uint4 *p_W1t, *p_W2t;
    cudaGetSymbolAddress((void**)&p_h,    g_h);
    cudaGetSymbolAddress((void**)&p_mol,  g_mol);
    cudaGetSymbolAddress((void**)&p_z1,   g_z1);
    cudaGetSymbolAddress((void**)&p_z2,   g_z2);
    cudaGetSymbolAddress((void**)&p_aggH, g_aggH);
    cudaGetSymbolAddress((void**)&p_aggL, g_aggL);
    cudaGetSymbolAddress((void**)&p_tH,   g_tH);
    cudaGetSymbolAddress((void**)&p_tL,   g_tL);
    cudaGetSymbolAddress((void**)&p_W1t,  g_W1t);
    cudaGetSymbolAddress((void**)&p_W2t,  g_W2t);

    static int smem_set = 0;
    if (!smem_set) {
        cudaFuncSetAttribute(gemm_cp<1>, cudaFuncAttributeMaxDynamicSharedMemorySize, 2 * STAGE);
        cudaFuncSetAttribute(gemm_cp<0>, cudaFuncAttributeMaxDynamicSharedMemorySize, 2 * STAGE);
        smem_set = 1;
    }

    const int rowBlocks = (NN + 127) / 128;

    // weight prep + CSR build (once per call)
    prep_w<<<dim3(4, 8, 5),  256>>>(W1, p_W1t, 512, 8);
    prep_w<<<dim3(2, 16, 5), 256>>>(W2, p_W2t, 256, 16);
    zero_deg_kernel<<<(NN + 255) / 256, 256>>>();
    hist_kernel<<<(EE + 255) / 256, 256>>>(dst);
    scan_kernel<<<1, 1024>>>();
    fill_kernel<<<(EE + 255) / 256, 256>>>(dst);

    embed_kernel<<<NN, 256>>>(x, embW, embB);

    for (int l = 0; l < LL; l++) {
        const float* ee1l = ee1 + (size_t)l * 6 * DD;
        const float* ee2l = ee2 + (size_t)l * 3 * DD;
        // l==0: h is relu(embed), no BN pending. l>0: fold BN(l-1)+relu lazily.
        agg_kernel<<<(NN + 3) / 4, 256>>>(src, edge_attr, ee1l, ee2l, l > 0 ? 1 : 0);
        gemm_cp<1><<<dim3(4, rowBlocks), 256, 2 * STAGE>>>(
            p_aggH, p_aggL, (const char*)p_W1t + (size_t)l * 4 * 8 * 16384,
            b1 + (size_t)l * 2 * DD, nullptr, p_tH, p_tL, NN, DD, 2 * DD);
        zero_stats_kernel<<<1, 256>>>();
        gemm_cp<0><<<dim3(2, rowBlocks), 256, 2 * STAGE>>>(
            p_tH, p_tL, (const char*)p_W2t + (size_t)l * 2 * 16 * 16384,
            b2 + (size_t)l * DD, p_h, nullptr, nullptr, NN, 2 * DD, DD);
        bn_coef_kernel<<<1, 256>>>(bn_g + (size_t)l * DD, bn_b + (size_t)l * DD);
    }

    // pooling applies layer-4 BN affine lazily (no relu on last layer)
    zero_pool_kernel<<<(GG * DD + 255) / 256, 256>>>();
    count_kernel<<<(NN + 255) / 256, 256>>>(batch);
    pool_scatter_kernel<<<(NN + 3) / 4, 256>>>(batch);
    pool_div_kernel<<<(GG * DD + 255) / 256, 256>>>();

    gemm_bias<1><<<dim3(4, (GG + 63) / 64), 256>>>(p_mol, hW0, hb0, p_z1, GG, 256, 256);
    gemm_bias<1><<<dim3(2, (GG + 63) / 64), 256>>>(p_z1,  hW1, hb1, p_z2, GG, 256, 128);
    gemm_bias<1><<<dim3(1, (GG + 63) / 64), 256>>>(p_z2,  hW2, hb2, p_z1, GG, 128, 64);
    gemm_bias<1><<<dim3(1, (GG + 63) / 64), 256>>>(p_z1,  hW3, hb3, p_z2, GG, 64, 32);
    head_final_kernel<<<(GG + 255) / 256, 256>>>(hWo, hbo, out);
}

// round 9
// speedup vs baseline: 3.0512x; 1.0273x over previous
#include <cuda_runtime.h>
#include <cuda_bf16.h>
#include <cstdint>

#define NN 100000
#define EE 300000
#define DD 256
#define GG 4000
#define LL 5
#define F_IN 40

// ---------------- scratch (device globals: allocation-free) ----------------
__device__ float g_h[NN * DD];                     // raw (pre-BN) features
__device__ __align__(16) __nv_bfloat16 g_aggH[NN * DD];
__device__ __align__(16) __nv_bfloat16 g_aggL[NN * DD];
__device__ __align__(16) __nv_bfloat16 g_tH[NN * 2 * DD];
__device__ __align__(16) __nv_bfloat16 g_tL[NN * 2 * DD];
__device__ uint4 g_W1t[163840];
__device__ uint4 g_W2t[163840];
__device__ float g_sum[DD];
__device__ float g_sumsq[DD];
__device__ float g_bna[DD];
__device__ float g_bnc[DD];
__device__ float g_mol[GG * DD];
__device__ float g_cnt[GG];
__device__ float g_z1[GG * DD];
__device__ float g_z2[GG * DD];
// CSR (built once per call)
__device__ int g_deg[NN];
__device__ int g_rowptr[NN + 1];
__device__ int g_fill[NN];
__device__ int g_esort[EE];

// ---------------- helpers ----------------
__device__ __forceinline__ void red_add_v4(float* addr, float4 v) {
    asm volatile("red.global.add.v4.f32 [%0], {%1,%2,%3,%4};"
                 :: "l"(addr), "f"(v.x), "f"(v.y), "f"(v.z), "f"(v.w)
                 : "memory");
}
__device__ __forceinline__ void ldsm4(uint32_t r[4], uint32_t addr) {
    asm volatile("ldmatrix.sync.aligned.m8n8.x4.shared.b16 {%0,%1,%2,%3}, [%4];"
        : "=r"(r[0]), "=r"(r[1]), "=r"(r[2]), "=r"(r[3]) : "r"(addr));
}
__device__ __forceinline__ void ldsm4t(uint32_t r[4], uint32_t addr) {
    asm volatile("ldmatrix.sync.aligned.m8n8.x4.trans.shared.b16 {%0,%1,%2,%3}, [%4];"
        : "=r"(r[0]), "=r"(r[1]), "=r"(r[2]), "=r"(r[3]) : "r"(addr));
}
__device__ __forceinline__ void mma16816(float c[4], const uint32_t a[4],
                                         uint32_t b0, uint32_t b1) {
    asm volatile("mma.sync.aligned.m16n8k16.row.col.f32.bf16.bf16.f32 "
        "{%0,%1,%2,%3}, {%4,%5,%6,%7}, {%8,%9}, {%0,%1,%2,%3};"
        : "+f"(c[0]), "+f"(c[1]), "+f"(c[2]), "+f"(c[3])
        : "r"(a[0]), "r"(a[1]), "r"(a[2]), "r"(a[3]), "r"(b0), "r"(b1));
}
__device__ __forceinline__ void cpa16(uint32_t dst, const void* src, uint32_t sz) {
    asm volatile("cp.async.cg.shared.global [%0], [%1], 16, %2;"
                 :: "r"(dst), "l"(src), "r"(sz) : "memory");
}

// ---------------- embed: smem-tiled, 64 nodes/block ----------------
__global__ void __launch_bounds__(256) embed_kernel(const float* __restrict__ x,
                                                    const float* __restrict__ W,
                                                    const float* __restrict__ b) {
    __shared__ float Ws[F_IN * DD];      // 40 KB
    __shared__ float xs[64 * F_IN];      // 10 KB
    const int tid   = threadIdx.x;
    const int node0 = blockIdx.x * 64;
    const int nNodes = min(64, NN - node0);

    for (int i = tid; i < F_IN * DD; i += 256) Ws[i] = W[i];
    for (int i = tid; i < nNodes * F_IN; i += 256) xs[i] = x[node0 * F_IN + i];
    __syncthreads();

    const float bias = b[tid];
    for (int n = 0; n < nNodes; n += 4) {
        float a0 = bias, a1 = bias, a2 = bias, a3 = bias;
#pragma unroll
        for (int k = 0; k < F_IN; k++) {
            float w = Ws[k * DD + tid];
            a0 = fmaf(xs[(n + 0) * F_IN + k], w, a0);
            a1 = fmaf(xs[(n + 1) * F_IN + k], w, a1);
            a2 = fmaf(xs[(n + 2) * F_IN + k], w, a2);
            a3 = fmaf(xs[(n + 3) * F_IN + k], w, a3);
        }
        g_h[(size_t)(node0 + n + 0) * DD + tid] = fmaxf(a0, 0.f);
        g_h[(size_t)(node0 + n + 1) * DD + tid] = fmaxf(a1, 0.f);
        g_h[(size_t)(node0 + n + 2) * DD + tid] = fmaxf(a2, 0.f);
        g_h[(size_t)(node0 + n + 3) * DD + tid] = fmaxf(a3, 0.f);
    }
}

// ---------------- CSR build ----------------
__global__ void zero_deg_kernel() {
    int i = blockIdx.x * 256 + threadIdx.x;
    if (i < NN) g_deg[i] = 0;
}
__global__ void hist_kernel(const int* __restrict__ dst) {
    int e = blockIdx.x * 256 + threadIdx.x;
    if (e < EE) atomicAdd(&g_deg[dst[e]], 1);
}
__global__ void scan_kernel() {
    __shared__ int ss[1024];
    int t = threadIdx.x;
    const int chunk = (NN + 1023) / 1024;
    int s0 = t * chunk;
    int s1 = min(s0 + chunk, NN);
    int s = 0;
    for (int i = s0; i < s1; i++) s += g_deg[i];
    ss[t] = s;
    __syncthreads();
    for (int d = 1; d < 1024; d <<= 1) {
        int v = (t >= d) ? ss[t - d] : 0;
        __syncthreads();
        ss[t] += v;
        __syncthreads();
    }
    int off = ss[t] - s;
    for (int i = s0; i < s1; i++) {
        g_rowptr[i] = off;
        g_fill[i]   = off;
        off += g_deg[i];
    }
    if (t == 1023) g_rowptr[NN] = ss[1023];
}
__global__ void fill_kernel(const int* __restrict__ dst) {
    int e = blockIdx.x * 256 + threadIdx.x;
    if (e >= EE) return;
    int pos = atomicAdd(&g_fill[dst[e]], 1);
    g_esort[pos] = e;
}

// ------- fused aggregate with lazy BN+relu on gathered values ----------
__global__ void __launch_bounds__(256) agg_kernel(const int* __restrict__ src,
                                                  const int* __restrict__ eattr,
                                                  const float* __restrict__ ee1l,
                                                  const float* __restrict__ ee2l,
                                                  int useBN) {
    int node = blockIdx.x * 4 + (threadIdx.x >> 6);
    int c    = threadIdx.x & 63;
    if (node >= NN) return;
    const float4* h4 = (const float4*)g_h;

    float4 av = make_float4(1.f, 1.f, 1.f, 1.f);
    float4 cv = make_float4(0.f, 0.f, 0.f, 0.f);
    if (useBN) {
        av = ((const float4*)g_bna)[c];
        cv = ((const float4*)g_bnc)[c];
    }

    float4 v = h4[(size_t)node * 64 + c];
    float4 acc;
    if (useBN) {
        acc.x = fmaxf(fmaf(av.x, v.x, cv.x), 0.f);
        acc.y = fmaxf(fmaf(av.y, v.y, cv.y), 0.f);
        acc.z = fmaxf(fmaf(av.z, v.z, cv.z), 0.f);
        acc.w = fmaxf(fmaf(av.w, v.w, cv.w), 0.f);
    } else {
        acc = v;
    }
    {
        float4 t1 = ((const float4*)(ee1l + 4 * DD))[c];
        float4 t2 = ((const float4*)ee2l)[c];
        acc.x += t1.x + t2.x; acc.y += t1.y + t2.y;
        acc.z += t1.z + t2.z; acc.w += t1.w + t2.w;
    }
    int p0 = g_rowptr[node], p1 = g_rowptr[node + 1];
    for (int p = p0; p < p1; p++) {
        int e  = g_esort[p];
        int s  = src[e];
        int a0 = eattr[2 * e];
        int a1 = eattr[2 * e + 1];
        float4 w  = h4[(size_t)s * 64 + c];
        if (useBN) {
            w.x = fmaxf(fmaf(av.x, w.x, cv.x), 0.f);
            w.y = fmaxf(fmaf(av.y, w.y, cv.y), 0.f);
            w.z = fmaxf(fmaf(av.z, w.z, cv.z), 0.f);
            w.w = fmaxf(fmaf(av.w, w.w, cv.w), 0.f);
        }
        float4 u1 = ((const float4*)(ee1l + a0 * DD))[c];
        float4 u2 = ((const float4*)(ee2l + a1 * DD))[c];
        acc.x += w.x + u1.x + u2.x;
        acc.y += w.y + u1.y + u2.y;
        acc.z += w.z + u1.z + u2.z;
        acc.w += w.w + u1.w + u2.w;
    }
    __nv_bfloat16 hx = __float2bfloat16(acc.x), hy = __float2bfloat16(acc.y);
    __nv_bfloat16 hz = __float2bfloat16(acc.z), hw = __float2bfloat16(acc.w);
    __nv_bfloat162 h0(hx, hy), h1(hz, hw);
    __nv_bfloat162 l0(__float2bfloat16(acc.x - __bfloat162float(hx)),
                      __float2bfloat16(acc.y - __bfloat162float(hy)));
    __nv_bfloat162 l1(__float2bfloat16(acc.z - __bfloat162float(hz)),
                      __float2bfloat16(acc.w - __bfloat162float(hw)));
    uint2 h, l;
    h.x = *(uint32_t*)&h0; h.y = *(uint32_t*)&h1;
    l.x = *(uint32_t*)&l0; l.y = *(uint32_t*)&l1;
    *(uint2*)(g_aggH + (size_t)node * DD + c * 4) = h;
    *(uint2*)(g_aggL + (size_t)node * DD + c * 4) = l;
}

// ---------------- weight prep ----------------
__global__ void prep_w(const float* __restrict__ W, uint4* __restrict__ dst,
                       int Nc, int ktiles) {
    int cb = blockIdx.x, kt = blockIdx.y, l = blockIdx.z;
    const float* Wl = W + (size_t)l * (ktiles * 32) * Nc;
    char* blob = (char*)dst + (((size_t)l * gridDim.x + cb) * ktiles + kt) * 16384;
    for (int e = threadIdx.x; e < 4096; e += 256) {
        int k = e >> 7, n = e & 127;
        float v = Wl[(size_t)(kt * 32 + k) * Nc + cb * 128 + n];
        __nv_bfloat16 h = __float2bfloat16(v);
        __nv_bfloat16 lo = __float2bfloat16(v - __bfloat162float(h));
        uint32_t off = k * 256 + n * 2;
        uint32_t sw = off ^ ((k & 7) << 4);
        *(__nv_bfloat16*)(blob + sw) = h;
        *(__nv_bfloat16*)(blob + 8192 + sw) = lo;
    }
}

// ====== tensor-core GEMM, bf16 3-way split, 3-stage cp.async, occ 2 ======
#define STAGE 32768
#define NSTAGE 3
#define P_AH 0
#define P_AL 8192
#define P_BH 16384
#define P_BL 24576

template <int OUT>
__global__ void __launch_bounds__(256, 2) gemm_cp(
    const __nv_bfloat16* __restrict__ AH, const __nv_bfloat16* __restrict__ AL,
    const char* __restrict__ Btiles, const float* __restrict__ bias,
    float* __restrict__ Cf, __nv_bfloat16* __restrict__ CH,
    __nv_bfloat16* __restrict__ CL, int M, int K, int Nc) {
    extern __shared__ __align__(16) char sm[];
    const int tid  = threadIdx.x;
    const int lane = tid & 31;
    const int warp = tid >> 5;
    const int wm   = warp >> 1;
    const int wn   = warp & 1;
    const int row0 = blockIdx.y * 128;
    const int col0 = blockIdx.x * 128;
    const int ktiles = K >> 5;

    uint32_t smbase;
    asm("{ .reg .u64 t; cvta.to.shared.u64 t, %1; cvt.u32.u64 %0, t; }"
        : "=r"(smbase) : "l"(sm));

    const int m0 = tid >> 2, kq0 = tid & 3;
    const int m1 = (tid + 256) >> 2, kq1 = (tid + 256) & 3;
    const uint32_t dA0 = (uint32_t)(m0 * 64 + kq0 * 16) ^ ((m0 & 6) << 3);
    const uint32_t dA1 = (uint32_t)(m1 * 64 + kq1 * 16) ^ ((m1 & 6) << 3);
    const uint32_t ok0 = (row0 + m0 < M) ? 16u : 0u;
    const uint32_t ok1 = (row0 + m1 < M) ? 16u : 0u;
    const __nv_bfloat16* sH0 = AH + (size_t)(row0 + m0) * K + kq0 * 8;
    const __nv_bfloat16* sH1 = AH + (size_t)(row0 + m1) * K + kq1 * 8;
    const __nv_bfloat16* sL0 = AL + (size_t)(row0 + m0) * K + kq0 * 8;
    const __nv_bfloat16* sL1 = AL + (size_t)(row0 + m1) * K + kq1 * 8;
    const char* tbase = Btiles + (size_t)blockIdx.x * ktiles * 16384;

    float acc[2][8][4];
#pragma unroll
    for (int mi = 0; mi < 2; mi++)
#pragma unroll
        for (int nt = 0; nt < 8; nt++)
#pragma unroll
            for (int q = 0; q < 4; q++) acc[mi][nt][q] = 0.f;

#define ISSUE(kt, st) do {                                                    \
        uint32_t sb = smbase + (st) * STAGE;                                  \
        int ko = (kt) * 32;                                                   \
        cpa16(sb + P_AH + dA0, sH0 + ko, ok0);                                \
        cpa16(sb + P_AH + dA1, sH1 + ko, ok1);                                \
        cpa16(sb + P_AL + dA0, sL0 + ko, ok0);                                \
        cpa16(sb + P_AL + dA1, sL1 + ko, ok1);                                \
        const char* tb = tbase + (size_t)(kt) * 16384;                        \
        cpa16(sb + P_BH + tid * 16,        tb + tid * 16, 16);                \
        cpa16(sb + P_BH + tid * 16 + 4096, tb + tid * 16 + 4096, 16);         \
        cpa16(sb + P_BL + tid * 16,        tb + 8192 + tid * 16, 16);         \
        cpa16(sb + P_BL + tid * 16 + 4096, tb + 12288 + tid * 16, 16);        \
        asm volatile("cp.async.commit_group;" ::: "memory");                  \
    } while (0)

    ISSUE(0, 0);
    if (ktiles > 1) ISSUE(1, 1);

    int stage = 0;
    for (int kt = 0; kt < ktiles; kt++) {
        // stage kt must be complete: allow only the (kt+1) group to pend
        if (kt + 1 < ktiles) {
            asm volatile("cp.async.wait_group 1;" ::: "memory");
        } else {
            asm volatile("cp.async.wait_group 0;" ::: "memory");
        }
        __syncthreads();   // all warps see stage kt; all done reading stage (kt-1)

        if (kt + 2 < ktiles) {
            int nst = stage + 2;
            if (nst >= NSTAGE) nst -= NSTAGE;
            ISSUE(kt + 2, nst);
        }

        const uint32_t cbase = smbase + stage * STAGE;
#pragma unroll
        for (int ks = 0; ks < 2; ks++) {
            uint32_t a_h[2][4], a_l[2][4];
#pragma unroll
            for (int mi = 0; mi < 2; mi++) {
                int m = wm * 32 + mi * 16 + (lane & 15);
                int k = ks * 16 + (lane >> 4) * 8;
                uint32_t byte = (uint32_t)(m * 64 + k * 2) ^ ((m & 6) << 3);
                ldsm4(a_h[mi], cbase + P_AH + byte);
                ldsm4(a_l[mi], cbase + P_AL + byte);
            }
#pragma unroll
            for (int nj = 0; nj < 4; nj++) {
                int k = ks * 16 + (lane & 15);
                int n = wn * 64 + nj * 16 + (lane >> 4) * 8;
                uint32_t byte = (uint32_t)(k * 256 + n * 2) ^ ((k & 7) << 4);
                uint32_t bh[4], bl[4];
                ldsm4t(bh, cbase + P_BH + byte);
                ldsm4t(bl, cbase + P_BL + byte);
#pragma unroll
                for (int mi = 0; mi < 2; mi++) {
                    mma16816(acc[mi][2 * nj],     a_h[mi], bh[0], bh[1]);
                    mma16816(acc[mi][2 * nj],     a_h[mi], bl[0], bl[1]);
                    mma16816(acc[mi][2 * nj],     a_l[mi], bh[0], bh[1]);
                    mma16816(acc[mi][2 * nj + 1], a_h[mi], bh[2], bh[3]);
                    mma16816(acc[mi][2 * nj + 1], a_h[mi], bl[2], bl[3]);
                    mma16816(acc[mi][2 * nj + 1], a_l[mi], bh[2], bh[3]);
                }
            }
        }
        if (++stage >= NSTAGE) stage = 0;
    }
#undef ISSUE

    if (OUT == 1) {
#pragma unroll
        for (int mi = 0; mi < 2; mi++) {
            int r0 = row0 + wm * 32 + mi * 16 + (lane >> 2);
#pragma unroll
            for (int nt = 0; nt < 8; nt++) {
                int c = col0 + wn * 64 + nt * 8 + (lane & 3) * 2;
                float2 bv = *(const float2*)(bias + c);
                float* a4 = acc[mi][nt];
#pragma unroll
                for (int half = 0; half < 2; half++) {
                    int r = r0 + half * 8;
                    if (r < M) {
                        float v0 = fmaxf(a4[2 * half + 0] + bv.x, 0.f);
                        float v1 = fmaxf(a4[2 * half + 1] + bv.y, 0.f);
                        __nv_bfloat16 h0 = __float2bfloat16(v0);
                        __nv_bfloat16 h1 = __float2bfloat16(v1);
                        __nv_bfloat162 hp(h0, h1);
                        __nv_bfloat162 lp(__float2bfloat16(v0 - __bfloat162float(h0)),
                                          __float2bfloat16(v1 - __bfloat162float(h1)));
                        *(__nv_bfloat162*)(CH + (size_t)r * Nc + c) = hp;
                        *(__nv_bfloat162*)(CL + (size_t)r * Nc + c) = lp;
                    }
                }
            }
        }
    } else {
        float cs[16], cq[16];
#pragma unroll
        for (int j = 0; j < 16; j++) { cs[j] = 0.f; cq[j] = 0.f; }
#pragma unroll
        for (int mi = 0; mi < 2; mi++) {
            int r0 = row0 + wm * 32 + mi * 16 + (lane >> 2);
#pragma unroll
            for (int nt = 0; nt < 8; nt++) {
                int c = col0 + wn * 64 + nt * 8 + (lane & 3) * 2;
                float2 bv = *(const float2*)(bias + c);
                float* a4 = acc[mi][nt];
#pragma unroll
                for (int half = 0; half < 2; half++) {
                    int r = r0 + half * 8;
                    if (r < M) {
                        float v0 = a4[2 * half + 0] + bv.x;
                        float v1 = a4[2 * half + 1] + bv.y;
                        float2 o; o.x = v0; o.y = v1;
                        *(float2*)(Cf + (size_t)r * Nc + c) = o;
                        cs[nt * 2 + 0] += v0; cq[nt * 2 + 0] += v0 * v0;
                        cs[nt * 2 + 1] += v1; cq[nt * 2 + 1] += v1 * v1;
                    }
                }
            }
        }
#pragma unroll
        for (int j = 0; j < 16; j++) {
#pragma unroll
            for (int msk = 4; msk <= 16; msk <<= 1) {
                cs[j] += __shfl_xor_sync(0xFFFFFFFF, cs[j], msk);
                cq[j] += __shfl_xor_sync(0xFFFFFFFF, cq[j], msk);
            }
        }
        float* ssum = (float*)sm;
        float* ssq  = ssum + 128;
        __syncthreads();
        if (tid < 128) { ssum[tid] = 0.f; ssq[tid] = 0.f; }
        __syncthreads();
        if ((lane >> 2) == 0) {
#pragma unroll
            for (int j = 0; j < 16; j++) {
                int cl = wn * 64 + (j >> 1) * 8 + (lane & 3) * 2 + (j & 1);
                atomicAdd(&ssum[cl], cs[j]);
                atomicAdd(&ssq[cl],  cq[j]);
            }
        }
        __syncthreads();
        if (tid < 128) {
            atomicAdd(&g_sum[col0 + tid],   ssum[tid]);
            atomicAdd(&g_sumsq[col0 + tid], ssq[tid]);
        }
    }
}

// ---------------- small GEMM (head MLP) ----------------
template <int RELU>
__global__ void __launch_bounds__(256) gemm_bias(const float* __restrict__ A,
                                                 const float* __restrict__ B,
                                                 const float* __restrict__ bias,
                                                 float* __restrict__ C,
                                                 int M, int K, int Nc) {
    __shared__ float As[16][64];
    __shared__ float Bs[16][64];

    int tid  = threadIdx.x;
    int row0 = blockIdx.y * 64;
    int col0 = blockIdx.x * 64;
    int ty   = tid >> 4;
    int tx   = tid & 15;

    int ar = tid >> 2;
    int ak = (tid & 3) * 4;
    int bk = tid >> 4;
    int bc = (tid & 15) * 4;

    float acc[4][4];
#pragma unroll
    for (int i = 0; i < 4; i++)
#pragma unroll
        for (int j = 0; j < 4; j++) acc[i][j] = 0.f;

    int arow = row0 + ar;
    int bcol = col0 + bc;

    for (int k0 = 0; k0 < K; k0 += 16) {
        float4 av = make_float4(0.f, 0.f, 0.f, 0.f);
        if (arow < M)
            av = *(const float4*)(A + (size_t)arow * K + k0 + ak);
        As[ak + 0][ar] = av.x;
        As[ak + 1][ar] = av.y;
        As[ak + 2][ar] = av.z;
        As[ak + 3][ar] = av.w;

        float4 bv = make_float4(0.f, 0.f, 0.f, 0.f);
        if (bcol < Nc)
            bv = *(const float4*)(B + (size_t)(k0 + bk) * Nc + bcol);
        *(float4*)(&Bs[bk][bc]) = bv;

        __syncthreads();
#pragma unroll
        for (int k = 0; k < 16; k++) {
            float4 a4 = *(const float4*)(&As[k][ty * 4]);
            float4 b4 = *(const float4*)(&Bs[k][tx * 4]);
            float a[4] = {a4.x, a4.y, a4.z, a4.w};
            float b[4] = {b4.x, b4.y, b4.z, b4.w};
#pragma unroll
            for (int i = 0; i < 4; i++)
#pragma unroll
                for (int j = 0; j < 4; j++)
                    acc[i][j] = fmaf(a[i], b[j], acc[i][j]);
        }
        __syncthreads();
    }

#pragma unroll
    for (int i = 0; i < 4; i++) {
        int r = row0 + ty * 4 + i;
        if (r < M) {
#pragma unroll
            for (int j = 0; j < 4; j++) {
                int c = col0 + tx * 4 + j;
                if (c < Nc) {
                    float v = acc[i][j] + bias[c];
                    if (RELU) v = fmaxf(v, 0.f);
                    C[(size_t)r * Nc + c] = v;
                }
            }
        }
    }
}

// ---------------- batchnorm coefficients ----------------
__global__ void zero_stats_kernel() {
    g_sum[threadIdx.x]   = 0.f;
    g_sumsq[threadIdx.x] = 0.f;
}

__global__ void bn_coef_kernel(const float* __restrict__ gamma,
                               const float* __restrict__ beta) {
    int d = threadIdx.x;
    const float invN = 1.f / (float)NN;
    float mu  = g_sum[d] * invN;
    float var = g_sumsq[d] * invN - mu * mu;
    float a = gamma[d] * rsqrtf(var + 1e-5f);
    g_bna[d] = a;
    g_bnc[d] = beta[d] - mu * a;
}

// ---------------- pooling (applies last-layer BN affine, no relu) ----------
__global__ void zero_pool_kernel() {
    int i = blockIdx.x * 256 + threadIdx.x;
    if (i < GG * DD) g_mol[i] = 0.f;
    if (i < GG) g_cnt[i] = 0.f;
}

__global__ void count_kernel(const int* __restrict__ batch) {
    int i = blockIdx.x * 256 + threadIdx.x;
    if (i < NN) atomicAdd(&g_cnt[batch[i]], 1.f);
}

__global__ void pool_scatter_kernel(const int* __restrict__ batch) {
    int n = blockIdx.x * 4 + (threadIdx.x >> 6);
    int c = threadIdx.x & 63;
    if (n >= NN) return;
    int g = batch[n];
    float4 v  = ((const float4*)(g_h + (size_t)n * DD))[c];
    float4 av = ((const float4*)g_bna)[c];
    float4 cv = ((const float4*)g_bnc)[c];
    v.x = fmaf(av.x, v.x, cv.x);
    v.y = fmaf(av.y, v.y, cv.y);
    v.z = fmaf(av.z, v.z, cv.z);
    v.w = fmaf(av.w, v.w, cv.w);
    red_add_v4(g_mol + (size_t)g * DD + c * 4, v);
}

__global__ void pool_div_kernel() {
    int i = blockIdx.x * 256 + threadIdx.x;
    if (i >= GG * DD) return;
    g_mol[i] /= fmaxf(g_cnt[i >> 8], 1.f);
}

// ---------------- head final ----------------
__global__ void head_final_kernel(const float* __restrict__ w,
                                  const float* __restrict__ b,
                                  float* __restrict__ out) {
    int g = blockIdx.x * 256 + threadIdx.x;
    if (g >= GG) return;
    float acc = b[0];
#pragma unroll
    for (int k = 0; k < 32; k++)
        acc = fmaf(g_z2[g * 32 + k], w[k], acc);
    out[g] = acc;
}

// ---------------- launch ----------------
extern "C" void kernel_launch(void* const* d_in, const int* in_sizes, int n_in,
                              void* d_out, int out_size) {
    const float* x          = (const float*)d_in[0];
    const int*   edge_index = (const int*)d_in[1];
    const int*   edge_attr  = (const int*)d_in[2];
    const int*   batch      = (const int*)d_in[3];
    const float* embW       = (const float*)d_in[4];
    const float* embB       = (const float*)d_in[5];
    const float* ee1        = (const float*)d_in[6];
    const float* ee2        = (const float*)d_in[7];
    const float* W1         = (const float*)d_in[8];
    const float* b1         = (const float*)d_in[9];
    const float* W2         = (const float*)d_in[10];
    const float* b2         = (const float*)d_in[11];
    const float* bn_g       = (const float*)d_in[12];
    const float* bn_b       = (const float*)d_in[13];
    const float* hW0 = (const float*)d_in[14];
    const float* hb0 = (const float*)d_in[15];
    const float* hW1 = (const float*)d_in[16];
    const float* hb1 = (const float*)d_in[17];
    const float* hW2 = (const float*)d_in[18];
    const float* hb2 = (const float*)d_in[19];
    const float* hW3 = (const float*)d_in[20];
    const float* hb3 = (const float*)d_in[21];
    const float* hWo = (const float*)d_in[22];
    const float* hbo = (const float*)d_in[23];
    float* out = (float*)d_out;

    const int* src = edge_index;
    const int* dst = edge_index + EE;

    float *p_h, *p_mol, *p_z1, *p_z2;
    __nv_bfloat16 *p_aggH, *p_aggL, *p_tH, *p_tL;
    uint4 *p_W1t, *p_W2t;
    cudaGetSymbolAddress((void**)&p_h,    g_h);
    cudaGetSymbolAddress((void**)&p_mol,  g_mol);
    cudaGetSymbolAddress((void**)&p_z1,   g_z1);
    cudaGetSymbolAddress((void**)&p_z2,   g_z2);
    cudaGetSymbolAddress((void**)&p_aggH, g_aggH);
    cudaGetSymbolAddress((void**)&p_aggL, g_aggL);
    cudaGetSymbolAddress((void**)&p_tH,   g_tH);
    cudaGetSymbolAddress((void**)&p_tL,   g_tL);
    cudaGetSymbolAddress((void**)&p_W1t,  g_W1t);
    cudaGetSymbolAddress((void**)&p_W2t,  g_W2t);

    static int smem_set = 0;
    if (!smem_set) {
        cudaFuncSetAttribute(gemm_cp<1>, cudaFuncAttributeMaxDynamicSharedMemorySize, NSTAGE * STAGE);
        cudaFuncSetAttribute(gemm_cp<0>, cudaFuncAttributeMaxDynamicSharedMemorySize, NSTAGE * STAGE);
        smem_set = 1;
    }

    const int rowBlocks = (NN + 127) / 128;

    // weight prep + CSR build (once per call)
    prep_w<<<dim3(4, 8, 5),  256>>>(W1, p_W1t, 512, 8);
    prep_w<<<dim3(2, 16, 5), 256>>>(W2, p_W2t, 256, 16);
    zero_deg_kernel<<<(NN + 255) / 256, 256>>>();
    hist_kernel<<<(EE + 255) / 256, 256>>>(dst);
    scan_kernel<<<1, 1024>>>();
    fill_kernel<<<(EE + 255) / 256, 256>>>(dst);

    embed_kernel<<<(NN + 63) / 64, 256>>>(x, embW, embB);

    for (int l = 0; l < LL; l++) {
        const float* ee1l = ee1 + (size_t)l * 6 * DD;
        const float* ee2l = ee2 + (size_t)l * 3 * DD;
        agg_kernel<<<(NN + 3) / 4, 256>>>(src, edge_attr, ee1l, ee2l, l > 0 ? 1 : 0);
        gemm_cp<1><<<dim3(4, rowBlocks), 256, NSTAGE * STAGE>>>(
            p_aggH, p_aggL, (const char*)p_W1t + (size_t)l * 4 * 8 * 16384,
            b1 + (size_t)l * 2 * DD, nullptr, p_tH, p_tL, NN, DD, 2 * DD);
        zero_stats_kernel<<<1, 256>>>();
        gemm_cp<0><<<dim3(2, rowBlocks), 256, NSTAGE * STAGE>>>(
            p_tH, p_tL, (const char*)p_W2t + (size_t)l * 2 * 16 * 16384,
            b2 + (size_t)l * DD, p_h, nullptr, nullptr, NN, 2 * DD, DD);
        bn_coef_kernel<<<1, 256>>>(bn_g + (size_t)l * DD, bn_b + (size_t)l * DD);
    }

    zero_pool_kernel<<<(GG * DD + 255) / 256, 256>>>();
    count_kernel<<<(NN + 255) / 256, 256>>>(batch);
    pool_scatter_kernel<<<(NN + 3) / 4, 256>>>(batch);
    pool_div_kernel<<<(GG * DD + 255) / 256, 256>>>();

    gemm_bias<1><<<dim3(4, (GG + 63) / 64), 256>>>(p_mol, hW0, hb0, p_z1, GG, 256, 256);
    gemm_bias<1><<<dim3(2, (GG + 63) / 64), 256>>>(p_z1,  hW1, hb1, p_z2, GG, 256, 128);
    gemm_bias<1><<<dim3(1, (GG + 63) / 64), 256>>>(p_z2,  hW2, hb2, p_z1, GG, 128, 64);
    gemm_bias<1><<<dim3(1, (GG + 63) / 64), 256>>>(p_z1,  hW3, hb3, p_z2, GG, 64, 32);
    head_final_kernel<<<(GG + 255) / 256, 256>>>(hWo, hbo, out);
}

// round 10
// speedup vs baseline: 3.2234x; 1.0564x over previous
#include <cuda_runtime.h>
#include <cuda_bf16.h>
#include <cstdint>

#define NN 100000
#define EE 300000
#define DD 256
#define GG 4000
#define LL 5
#define F_IN 40

// ---------------- scratch (device globals: allocation-free) ----------------
__device__ float g_h[NN * DD];                     // raw (pre-BN) features
__device__ __align__(16) __nv_bfloat16 g_aggH[NN * DD];
__device__ __align__(16) __nv_bfloat16 g_aggL[NN * DD];
__device__ __align__(16) __nv_bfloat16 g_tH[NN * 2 * DD];
__device__ __align__(16) __nv_bfloat16 g_tL[NN * 2 * DD];
__device__ uint4 g_W1t[163840];
__device__ uint4 g_W2t[163840];
__device__ float g_sum[DD];
__device__ float g_sumsq[DD];
__device__ float g_bna[DD];
__device__ float g_bnc[DD];
__device__ __align__(16) float g_combo[LL * 9 * DD];   // ee1[a0]+ee2[a1]
__device__ __align__(16) float g_self[LL * DD];        // ee1[4]+ee2[0]
__device__ float g_mol[GG * DD];
__device__ float g_cnt[GG];
__device__ float g_z1[GG * DD];
__device__ float g_z2[GG * DD];
// CSR (built once per call)
__device__ int g_deg[NN];
__device__ int g_rowptr[NN + 1];
__device__ int g_fill[NN];
__device__ int g_esort[EE];      // packed: src | (a0*3+a1)<<20

// ---------------- helpers ----------------
__device__ __forceinline__ void red_add_v4(float* addr, float4 v) {
    asm volatile("red.global.add.v4.f32 [%0], {%1,%2,%3,%4};"
                 :: "l"(addr), "f"(v.x), "f"(v.y), "f"(v.z), "f"(v.w)
                 : "memory");
}
__device__ __forceinline__ void ldsm4(uint32_t r[4], uint32_t addr) {
    asm volatile("ldmatrix.sync.aligned.m8n8.x4.shared.b16 {%0,%1,%2,%3}, [%4];"
        : "=r"(r[0]), "=r"(r[1]), "=r"(r[2]), "=r"(r[3]) : "r"(addr));
}
__device__ __forceinline__ void ldsm4t(uint32_t r[4], uint32_t addr) {
    asm volatile("ldmatrix.sync.aligned.m8n8.x4.trans.shared.b16 {%0,%1,%2,%3}, [%4];"
        : "=r"(r[0]), "=r"(r[1]), "=r"(r[2]), "=r"(r[3]) : "r"(addr));
}
__device__ __forceinline__ void mma16816(float c[4], const uint32_t a[4],
                                         uint32_t b0, uint32_t b1) {
    asm volatile("mma.sync.aligned.m16n8k16.row.col.f32.bf16.bf16.f32 "
        "{%0,%1,%2,%3}, {%4,%5,%6,%7}, {%8,%9}, {%0,%1,%2,%3};"
        : "+f"(c[0]), "+f"(c[1]), "+f"(c[2]), "+f"(c[3])
        : "r"(a[0]), "r"(a[1]), "r"(a[2]), "r"(a[3]), "r"(b0), "r"(b1));
}
__device__ __forceinline__ void cpa16(uint32_t dst, const void* src, uint32_t sz) {
    asm volatile("cp.async.cg.shared.global [%0], [%1], 16, %2;"
                 :: "r"(dst), "l"(src), "r"(sz) : "memory");
}

// ---------------- embed: smem-tiled, 64 nodes/block ----------------
__global__ void __launch_bounds__(256) embed_kernel(const float* __restrict__ x,
                                                    const float* __restrict__ W,
                                                    const float* __restrict__ b) {
    __shared__ float Ws[F_IN * DD];
    __shared__ float xs[64 * F_IN];
    const int tid   = threadIdx.x;
    const int node0 = blockIdx.x * 64;
    const int nNodes = min(64, NN - node0);

    for (int i = tid; i < F_IN * DD; i += 256) Ws[i] = W[i];
    for (int i = tid; i < nNodes * F_IN; i += 256) xs[i] = x[node0 * F_IN + i];
    __syncthreads();

    const float bias = b[tid];
    for (int n = 0; n < nNodes; n += 4) {
        float a0 = bias, a1 = bias, a2 = bias, a3 = bias;
#pragma unroll
        for (int k = 0; k < F_IN; k++) {
            float w = Ws[k * DD + tid];
            a0 = fmaf(xs[(n + 0) * F_IN + k], w, a0);
            a1 = fmaf(xs[(n + 1) * F_IN + k], w, a1);
            a2 = fmaf(xs[(n + 2) * F_IN + k], w, a2);
            a3 = fmaf(xs[(n + 3) * F_IN + k], w, a3);
        }
        g_h[(size_t)(node0 + n + 0) * DD + tid] = fmaxf(a0, 0.f);
        g_h[(size_t)(node0 + n + 1) * DD + tid] = fmaxf(a1, 0.f);
        g_h[(size_t)(node0 + n + 2) * DD + tid] = fmaxf(a2, 0.f);
        g_h[(size_t)(node0 + n + 3) * DD + tid] = fmaxf(a3, 0.f);
    }
}

// ---------------- CSR build ----------------
__global__ void zero_deg_kernel() {
    int i = blockIdx.x * 256 + threadIdx.x;
    if (i < NN) g_deg[i] = 0;
}
__global__ void hist_kernel(const int* __restrict__ dst) {
    int e = blockIdx.x * 256 + threadIdx.x;
    if (e < EE) atomicAdd(&g_deg[dst[e]], 1);
}
__global__ void scan_kernel() {
    __shared__ int ss[1024];
    int t = threadIdx.x;
    const int chunk = (NN + 1023) / 1024;
    int s0 = t * chunk;
    int s1 = min(s0 + chunk, NN);
    int s = 0;
    for (int i = s0; i < s1; i++) s += g_deg[i];
    ss[t] = s;
    __syncthreads();
    for (int d = 1; d < 1024; d <<= 1) {
        int v = (t >= d) ? ss[t - d] : 0;
        __syncthreads();
        ss[t] += v;
        __syncthreads();
    }
    int off = ss[t] - s;
    for (int i = s0; i < s1; i++) {
        g_rowptr[i] = off;
        g_fill[i]   = off;
        off += g_deg[i];
    }
    if (t == 1023) g_rowptr[NN] = ss[1023];
}
__global__ void fill_kernel(const int* __restrict__ src,
                            const int* __restrict__ dst,
                            const int* __restrict__ eattr) {
    int e = blockIdx.x * 256 + threadIdx.x;
    if (e >= EE) return;
    int pos = atomicAdd(&g_fill[dst[e]], 1);
    int ci  = eattr[2 * e] * 3 + eattr[2 * e + 1];
    g_esort[pos] = src[e] | (ci << 20);
}

// ---------------- combo table prep ----------------
__global__ void prep_combo(const float* __restrict__ ee1,
                           const float* __restrict__ ee2) {
    int ci = blockIdx.x;   // 0..8
    int l  = blockIdx.y;   // 0..4
    int d  = threadIdx.x;  // 0..255
    int a0 = ci / 3, a1 = ci % 3;
    g_combo[((size_t)l * 9 + ci) * DD + d] =
        ee1[((size_t)l * 6 + a0) * DD + d] + ee2[((size_t)l * 3 + a1) * DD + d];
    if (ci == 0)
        g_self[(size_t)l * DD + d] =
            ee1[((size_t)l * 6 + 4) * DD + d] + ee2[(size_t)l * 3 * DD + d];
}

// ------- fused aggregate: packed edges, warp-cooperative indices ----------
__global__ void __launch_bounds__(256) agg_kernel(const float* __restrict__ combo,
                                                  const float* __restrict__ selfadd,
                                                  int useBN) {
    int node = blockIdx.x * 4 + (threadIdx.x >> 6);
    int c    = threadIdx.x & 63;
    int lane = threadIdx.x & 31;
    if (node >= NN) return;
    const float4* h4 = (const float4*)g_h;
    const float4* cb4 = (const float4*)combo;

    float4 av = make_float4(1.f, 1.f, 1.f, 1.f);
    float4 cv = make_float4(0.f, 0.f, 0.f, 0.f);
    if (useBN) {
        av = ((const float4*)g_bna)[c];
        cv = ((const float4*)g_bnc)[c];
    }

    float4 v = h4[(size_t)node * 64 + c];
    float4 acc;
    if (useBN) {
        acc.x = fmaxf(fmaf(av.x, v.x, cv.x), 0.f);
        acc.y = fmaxf(fmaf(av.y, v.y, cv.y), 0.f);
        acc.z = fmaxf(fmaf(av.z, v.z, cv.z), 0.f);
        acc.w = fmaxf(fmaf(av.w, v.w, cv.w), 0.f);
    } else {
        acc = v;
    }
    {
        float4 t = ((const float4*)selfadd)[c];
        acc.x += t.x; acc.y += t.y; acc.z += t.z; acc.w += t.w;
    }

    int p0 = g_rowptr[node], p1 = g_rowptr[node + 1];
    int p = p0;
    while (p < p1) {
        int cnt = min(32, p1 - p);
        int rec = (lane < cnt) ? g_esort[p + lane] : 0;
        for (int j = 0; j < cnt; j++) {
            int r  = __shfl_sync(0xFFFFFFFFu, rec, j);
            int s  = r & 0xFFFFF;
            int ci = r >> 20;
            float4 w = h4[(size_t)s * 64 + c];
            if (useBN) {
                w.x = fmaxf(fmaf(av.x, w.x, cv.x), 0.f);
                w.y = fmaxf(fmaf(av.y, w.y, cv.y), 0.f);
                w.z = fmaxf(fmaf(av.z, w.z, cv.z), 0.f);
                w.w = fmaxf(fmaf(av.w, w.w, cv.w), 0.f);
            }
            float4 u = cb4[(size_t)ci * 64 + c];
            acc.x += w.x + u.x;
            acc.y += w.y + u.y;
            acc.z += w.z + u.z;
            acc.w += w.w + u.w;
        }
        p += cnt;
    }

    __nv_bfloat16 hx = __float2bfloat16(acc.x), hy = __float2bfloat16(acc.y);
    __nv_bfloat16 hz = __float2bfloat16(acc.z), hw = __float2bfloat16(acc.w);
    __nv_bfloat162 h0(hx, hy), h1(hz, hw);
    __nv_bfloat162 l0(__float2bfloat16(acc.x - __bfloat162float(hx)),
                      __float2bfloat16(acc.y - __bfloat162float(hy)));
    __nv_bfloat162 l1(__float2bfloat16(acc.z - __bfloat162float(hz)),
                      __float2bfloat16(acc.w - __bfloat162float(hw)));
    uint2 h, l;
    h.x = *(uint32_t*)&h0; h.y = *(uint32_t*)&h1;
    l.x = *(uint32_t*)&l0; l.y = *(uint32_t*)&l1;
    *(uint2*)(g_aggH + (size_t)node * DD + c * 4) = h;
    *(uint2*)(g_aggL + (size_t)node * DD + c * 4) = l;
}

// ---------------- weight prep ----------------
__global__ void prep_w(const float* __restrict__ W, uint4* __restrict__ dst,
                       int Nc, int ktiles) {
    int cb = blockIdx.x, kt = blockIdx.y, l = blockIdx.z;
    const float* Wl = W + (size_t)l * (ktiles * 32) * Nc;
    char* blob = (char*)dst + (((size_t)l * gridDim.x + cb) * ktiles + kt) * 16384;
    for (int e = threadIdx.x; e < 4096; e += 256) {
        int k = e >> 7, n = e & 127;
        float v = Wl[(size_t)(kt * 32 + k) * Nc + cb * 128 + n];
        __nv_bfloat16 h = __float2bfloat16(v);
        __nv_bfloat16 lo = __float2bfloat16(v - __bfloat162float(h));
        uint32_t off = k * 256 + n * 2;
        uint32_t sw = off ^ ((k & 7) << 4);
        *(__nv_bfloat16*)(blob + sw) = h;
        *(__nv_bfloat16*)(blob + 8192 + sw) = lo;
    }
}

// ====== tensor-core GEMM, bf16 3-way split, 3-stage cp.async, occ 2 ======
#define STAGE 32768
#define NSTAGE 3
#define P_AH 0
#define P_AL 8192
#define P_BH 16384
#define P_BL 24576

template <int OUT>
__global__ void __launch_bounds__(256, 2) gemm_cp(
    const __nv_bfloat16* __restrict__ AH, const __nv_bfloat16* __restrict__ AL,
    const char* __restrict__ Btiles, const float* __restrict__ bias,
    float* __restrict__ Cf, __nv_bfloat16* __restrict__ CH,
    __nv_bfloat16* __restrict__ CL, int M, int K, int Nc) {
    extern __shared__ __align__(16) char sm[];
    const int tid  = threadIdx.x;
    const int lane = tid & 31;
    const int warp = tid >> 5;
    const int wm   = warp >> 1;
    const int wn   = warp & 1;
    const int row0 = blockIdx.y * 128;
    const int col0 = blockIdx.x * 128;
    const int ktiles = K >> 5;

    uint32_t smbase;
    asm("{ .reg .u64 t; cvta.to.shared.u64 t, %1; cvt.u32.u64 %0, t; }"
        : "=r"(smbase) : "l"(sm));

    const int m0 = tid >> 2, kq0 = tid & 3;
    const int m1 = (tid + 256) >> 2, kq1 = (tid + 256) & 3;
    const uint32_t dA0 = (uint32_t)(m0 * 64 + kq0 * 16) ^ ((m0 & 6) << 3);
    const uint32_t dA1 = (uint32_t)(m1 * 64 + kq1 * 16) ^ ((m1 & 6) << 3);
    const uint32_t ok0 = (row0 + m0 < M) ? 16u : 0u;
    const uint32_t ok1 = (row0 + m1 < M) ? 16u : 0u;
    const __nv_bfloat16* sH0 = AH + (size_t)(row0 + m0) * K + kq0 * 8;
    const __nv_bfloat16* sH1 = AH + (size_t)(row0 + m1) * K + kq1 * 8;
    const __nv_bfloat16* sL0 = AL + (size_t)(row0 + m0) * K + kq0 * 8;
    const __nv_bfloat16* sL1 = AL + (size_t)(row0 + m1) * K + kq1 * 8;
    const char* tbase = Btiles + (size_t)blockIdx.x * ktiles * 16384;

    float acc[2][8][4];
#pragma unroll
    for (int mi = 0; mi < 2; mi++)
#pragma unroll
        for (int nt = 0; nt < 8; nt++)
#pragma unroll
            for (int q = 0; q < 4; q++) acc[mi][nt][q] = 0.f;

#define ISSUE(kt, st) do {                                                    \
        uint32_t sb = smbase + (st) * STAGE;                                  \
        int ko = (kt) * 32;                                                   \
        cpa16(sb + P_AH + dA0, sH0 + ko, ok0);                                \
        cpa16(sb + P_AH + dA1, sH1 + ko, ok1);                                \
        cpa16(sb + P_AL + dA0, sL0 + ko, ok0);                                \
        cpa16(sb + P_AL + dA1, sL1 + ko, ok1);                                \
        const char* tb = tbase + (size_t)(kt) * 16384;                        \
        cpa16(sb + P_BH + tid * 16,        tb + tid * 16, 16);                \
        cpa16(sb + P_BH + tid * 16 + 4096, tb + tid * 16 + 4096, 16);         \
        cpa16(sb + P_BL + tid * 16,        tb + 8192 + tid * 16, 16);         \
        cpa16(sb + P_BL + tid * 16 + 4096, tb + 12288 + tid * 16, 16);        \
        asm volatile("cp.async.commit_group;" ::: "memory");                  \
    } while (0)

    ISSUE(0, 0);
    if (ktiles > 1) ISSUE(1, 1);

    int stage = 0;
    for (int kt = 0; kt < ktiles; kt++) {
        if (kt + 1 < ktiles) {
            asm volatile("cp.async.wait_group 1;" ::: "memory");
        } else {
            asm volatile("cp.async.wait_group 0;" ::: "memory");
        }
        __syncthreads();

        if (kt + 2 < ktiles) {
            int nst = stage + 2;
            if (nst >= NSTAGE) nst -= NSTAGE;
            ISSUE(kt + 2, nst);
        }

        const uint32_t cbase = smbase + stage * STAGE;
#pragma unroll
        for (int ks = 0; ks < 2; ks++) {
            uint32_t a_h[2][4], a_l[2][4];
#pragma unroll
            for (int mi = 0; mi < 2; mi++) {
                int m = wm * 32 + mi * 16 + (lane & 15);
                int k = ks * 16 + (lane >> 4) * 8;
                uint32_t byte = (uint32_t)(m * 64 + k * 2) ^ ((m & 6) << 3);
                ldsm4(a_h[mi], cbase + P_AH + byte);
                ldsm4(a_l[mi], cbase + P_AL + byte);
            }
#pragma unroll
            for (int nj = 0; nj < 4; nj++) {
                int k = ks * 16 + (lane & 15);
                int n = wn * 64 + nj * 16 + (lane >> 4) * 8;
                uint32_t byte = (uint32_t)(k * 256 + n * 2) ^ ((k & 7) << 4);
                uint32_t bh[4], bl[4];
                ldsm4t(bh, cbase + P_BH + byte);
                ldsm4t(bl, cbase + P_BL + byte);
#pragma unroll
                for (int mi = 0; mi < 2; mi++) {
                    mma16816(acc[mi][2 * nj],     a_h[mi], bh[0], bh[1]);
                    mma16816(acc[mi][2 * nj],     a_h[mi], bl[0], bl[1]);
                    mma16816(acc[mi][2 * nj],     a_l[mi], bh[0], bh[1]);
                    mma16816(acc[mi][2 * nj + 1], a_h[mi], bh[2], bh[3]);
                    mma16816(acc[mi][2 * nj + 1], a_h[mi], bl[2], bl[3]);
                    mma16816(acc[mi][2 * nj + 1], a_l[mi], bh[2], bh[3]);
                }
            }
        }
        if (++stage >= NSTAGE) stage = 0;
    }
#undef ISSUE

    if (OUT == 1) {
#pragma unroll
        for (int mi = 0; mi < 2; mi++) {
            int r0 = row0 + wm * 32 + mi * 16 + (lane >> 2);
#pragma unroll
            for (int nt = 0; nt < 8; nt++) {
                int c = col0 + wn * 64 + nt * 8 + (lane & 3) * 2;
                float2 bv = *(const float2*)(bias + c);
                float* a4 = acc[mi][nt];
#pragma unroll
                for (int half = 0; half < 2; half++) {
                    int r = r0 + half * 8;
                    if (r < M) {
                        float v0 = fmaxf(a4[2 * half + 0] + bv.x, 0.f);
                        float v1 = fmaxf(a4[2 * half + 1] + bv.y, 0.f);
                        __nv_bfloat16 h0 = __float2bfloat16(v0);
                        __nv_bfloat16 h1 = __float2bfloat16(v1);
                        __nv_bfloat162 hp(h0, h1);
                        __nv_bfloat162 lp(__float2bfloat16(v0 - __bfloat162float(h0)),
                                          __float2bfloat16(v1 - __bfloat162float(h1)));
                        *(__nv_bfloat162*)(CH + (size_t)r * Nc + c) = hp;
                        *(__nv_bfloat162*)(CL + (size_t)r * Nc + c) = lp;
                    }
                }
            }
        }
    } else {
        float cs[16], cq[16];
#pragma unroll
        for (int j = 0; j < 16; j++) { cs[j] = 0.f; cq[j] = 0.f; }
#pragma unroll
        for (int mi = 0; mi < 2; mi++) {
            int r0 = row0 + wm * 32 + mi * 16 + (lane >> 2);
#pragma unroll
            for (int nt = 0; nt < 8; nt++) {
                int c = col0 + wn * 64 + nt * 8 + (lane & 3) * 2;
                float2 bv = *(const float2*)(bias + c);
                float* a4 = acc[mi][nt];
#pragma unroll
                for (int half = 0; half < 2; half++) {
                    int r = r0 + half * 8;
                    if (r < M) {
                        float v0 = a4[2 * half + 0] + bv.x;
                        float v1 = a4[2 * half + 1] + bv.y;
                        float2 o; o.x = v0; o.y = v1;
                        *(float2*)(Cf + (size_t)r * Nc + c) = o;
                        cs[nt * 2 + 0] += v0; cq[nt * 2 + 0] += v0 * v0;
                        cs[nt * 2 + 1] += v1; cq[nt * 2 + 1] += v1 * v1;
                    }
                }
            }
        }
#pragma unroll
        for (int j = 0; j < 16; j++) {
#pragma unroll
            for (int msk = 4; msk <= 16; msk <<= 1) {
                cs[j] += __shfl_xor_sync(0xFFFFFFFF, cs[j], msk);
                cq[j] += __shfl_xor_sync(0xFFFFFFFF, cq[j], msk);
            }
        }
        float* ssum = (float*)sm;
        float* ssq  = ssum + 128;
        __syncthreads();
        if (tid < 128) { ssum[tid] = 0.f; ssq[tid] = 0.f; }
        __syncthreads();
        if ((lane >> 2) == 0) {
#pragma unroll
            for (int j = 0; j < 16; j++) {
                int cl = wn * 64 + (j >> 1) * 8 + (lane & 3) * 2 + (j & 1);
                atomicAdd(&ssum[cl], cs[j]);
                atomicAdd(&ssq[cl],  cq[j]);
            }
        }
        __syncthreads();
        if (tid < 128) {
            atomicAdd(&g_sum[col0 + tid],   ssum[tid]);
            atomicAdd(&g_sumsq[col0 + tid], ssq[tid]);
        }
    }
}

// ---------------- small GEMM (head MLP) ----------------
template <int RELU>
__global__ void __launch_bounds__(256) gemm_bias(const float* __restrict__ A,
                                                 const float* __restrict__ B,
                                                 const float* __restrict__ bias,
                                                 float* __restrict__ C,
                                                 int M, int K, int Nc) {
    __shared__ float As[16][64];
    __shared__ float Bs[16][64];

    int tid  = threadIdx.x;
    int row0 = blockIdx.y * 64;
    int col0 = blockIdx.x * 64;
    int ty   = tid >> 4;
    int tx   = tid & 15;

    int ar = tid >> 2;
    int ak = (tid & 3) * 4;
    int bk = tid >> 4;
    int bc = (tid & 15) * 4;

    float acc[4][4];
#pragma unroll
    for (int i = 0; i < 4; i++)
#pragma unroll
        for (int j = 0; j < 4; j++) acc[i][j] = 0.f;

    int arow = row0 + ar;
    int bcol = col0 + bc;

    for (int k0 = 0; k0 < K; k0 += 16) {
        float4 av = make_float4(0.f, 0.f, 0.f, 0.f);
        if (arow < M)
            av = *(const float4*)(A + (size_t)arow * K + k0 + ak);
        As[ak + 0][ar] = av.x;
        As[ak + 1][ar] = av.y;
        As[ak + 2][ar] = av.z;
        As[ak + 3][ar] = av.w;

        float4 bv = make_float4(0.f, 0.f, 0.f, 0.f);
        if (bcol < Nc)
            bv = *(const float4*)(B + (size_t)(k0 + bk) * Nc + bcol);
        *(float4*)(&Bs[bk][bc]) = bv;

        __syncthreads();
#pragma unroll
        for (int k = 0; k < 16; k++) {
            float4 a4 = *(const float4*)(&As[k][ty * 4]);
            float4 b4 = *(const float4*)(&Bs[k][tx * 4]);
            float a[4] = {a4.x, a4.y, a4.z, a4.w};
            float b[4] = {b4.x, b4.y, b4.z, b4.w};
#pragma unroll
            for (int i = 0; i < 4; i++)
#pragma unroll
                for (int j = 0; j < 4; j++)
                    acc[i][j] = fmaf(a[i], b[j], acc[i][j]);
        }
        __syncthreads();
    }

#pragma unroll
    for (int i = 0; i < 4; i++) {
        int r = row0 + ty * 4 + i;
        if (r < M) {
#pragma unroll
            for (int j = 0; j < 4; j++) {
                int c = col0 + tx * 4 + j;
                if (c < Nc) {
                    float v = acc[i][j] + bias[c];
                    if (RELU) v = fmaxf(v, 0.f);
                    C[(size_t)r * Nc + c] = v;
                }
            }
        }
    }
}

// ---------------- batchnorm coefficients (reads + resets stats) ----------
__global__ void zero_stats_kernel() {
    g_sum[threadIdx.x]   = 0.f;
    g_sumsq[threadIdx.x] = 0.f;
}

__global__ void bn_coef_kernel(const float* __restrict__ gamma,
                               const float* __restrict__ beta) {
    int d = threadIdx.x;
    const float invN = 1.f / (float)NN;
    float mu  = g_sum[d] * invN;
    float var = g_sumsq[d] * invN - mu * mu;
    float a = gamma[d] * rsqrtf(var + 1e-5f);
    g_bna[d] = a;
    g_bnc[d] = beta[d] - mu * a;
    g_sum[d]   = 0.f;     // reset for next layer's fused stats
    g_sumsq[d] = 0.f;
}

// ---------------- pooling (applies last-layer BN affine, no relu) ----------
__global__ void zero_pool_kernel() {
    int i = blockIdx.x * 256 + threadIdx.x;
    if (i < GG * DD) g_mol[i] = 0.f;
    if (i < GG) g_cnt[i] = 0.f;
}

__global__ void count_kernel(const int* __restrict__ batch) {
    int i = blockIdx.x * 256 + threadIdx.x;
    if (i < NN) atomicAdd(&g_cnt[batch[i]], 1.f);
}

__global__ void pool_scatter_kernel(const int* __restrict__ batch) {
    int n = blockIdx.x * 4 + (threadIdx.x >> 6);
    int c = threadIdx.x & 63;
    if (n >= NN) return;
    int g = batch[n];
    float4 v  = ((const float4*)(g_h + (size_t)n * DD))[c];
    float4 av = ((const float4*)g_bna)[c];
    float4 cv = ((const float4*)g_bnc)[c];
    v.x = fmaf(av.x, v.x, cv.x);
    v.y = fmaf(av.y, v.y, cv.y);
    v.z = fmaf(av.z, v.z, cv.z);
    v.w = fmaf(av.w, v.w, cv.w);
    red_add_v4(g_mol + (size_t)g * DD + c * 4, v);
}

__global__ void pool_div_kernel() {
    int i = blockIdx.x * 256 + threadIdx.x;
    if (i >= GG * DD) return;
    g_mol[i] /= fmaxf(g_cnt[i >> 8], 1.f);
}

// ---------------- head final ----------------
__global__ void head_final_kernel(const float* __restrict__ w,
                                  const float* __restrict__ b,
                                  float* __restrict__ out) {
    int g = blockIdx.x * 256 + threadIdx.x;
    if (g >= GG) return;
    float acc = b[0];
#pragma unroll
    for (int k = 0; k < 32; k++)
        acc = fmaf(g_z2[g * 32 + k], w[k], acc);
    out[g] = acc;
}

// ---------------- launch ----------------
extern "C" void kernel_launch(void* const* d_in, const int* in_sizes, int n_in,
                              void* d_out, int out_size) {
    const float* x          = (const float*)d_in[0];
    const int*   edge_index = (const int*)d_in[1];
    const int*   edge_attr  = (const int*)d_in[2];
    const int*   batch      = (const int*)d_in[3];
    const float* embW       = (const float*)d_in[4];
    const float* embB       = (const float*)d_in[5];
    const float* ee1        = (const float*)d_in[6];
    const float* ee2        = (const float*)d_in[7];
    const float* W1         = (const float*)d_in[8];
    const float* b1         = (const float*)d_in[9];
    const float* W2         = (const float*)d_in[10];
    const float* b2         = (const float*)d_in[11];
    const float* bn_g       = (const float*)d_in[12];
    const float* bn_b       = (const float*)d_in[13];
    const float* hW0 = (const float*)d_in[14];
    const float* hb0 = (const float*)d_in[15];
    const float* hW1 = (const float*)d_in[16];
    const float* hb1 = (const float*)d_in[17];
    const float* hW2 = (const float*)d_in[18];
    const float* hb2 = (const float*)d_in[19];
    const float* hW3 = (const float*)d_in[20];
    const float* hb3 = (const float*)d_in[21];
    const float* hWo = (const float*)d_in[22];
    const float* hbo = (const float*)d_in[23];
    float* out = (float*)d_out;

    const int* src = edge_index;
    const int* dst = edge_index + EE;

    float *p_h, *p_mol, *p_z1, *p_z2, *p_combo, *p_self;
    __nv_bfloat16 *p_aggH, *p_aggL, *p_tH, *p_tL;
    uint4 *p_W1t, *p_W2t;
    cudaGetSymbolAddress((void**)&p_h,     g_h);
    cudaGetSymbolAddress((void**)&p_mol,   g_mol);
    cudaGetSymbolAddress((void**)&p_z1,    g_z1);
    cudaGetSymbolAddress((void**)&p_z2,    g_z2);
    cudaGetSymbolAddress((void**)&p_aggH,  g_aggH);
    cudaGetSymbolAddress((void**)&p_aggL,  g_aggL);
    cudaGetSymbolAddress((void**)&p_tH,    g_tH);
    cudaGetSymbolAddress((void**)&p_tL,    g_tL);
    cudaGetSymbolAddress((void**)&p_W1t,   g_W1t);
    cudaGetSymbolAddress((void**)&p_W2t,   g_W2t);
    cudaGetSymbolAddress((void**)&p_combo, g_combo);
    cudaGetSymbolAddress((void**)&p_self,  g_self);

    static int smem_set = 0;
    if (!smem_set) {
        cudaFuncSetAttribute(gemm_cp<1>, cudaFuncAttributeMaxDynamicSharedMemorySize, NSTAGE * STAGE);
        cudaFuncSetAttribute(gemm_cp<0>, cudaFuncAttributeMaxDynamicSharedMemorySize, NSTAGE * STAGE);
        smem_set = 1;
    }

    const int rowBlocks = (NN + 127) / 128;

    // weight prep + combo tables + CSR build (once per call)
    prep_w<<<dim3(4, 8, 5),  256>>>(W1, p_W1t, 512, 8);
    prep_w<<<dim3(2, 16, 5), 256>>>(W2, p_W2t, 256, 16);
    prep_combo<<<dim3(9, 5), 256>>>(ee1, ee2);
    zero_deg_kernel<<<(NN + 255) / 256, 256>>>();
    hist_kernel<<<(EE + 255) / 256, 256>>>(dst);
    scan_kernel<<<1, 1024>>>();
    fill_kernel<<<(EE + 255) / 256, 256>>>(src, dst, edge_attr);
    zero_stats_kernel<<<1, 256>>>();

    embed_kernel<<<(NN + 63) / 64, 256>>>(x, embW, embB);

    for (int l = 0; l < LL; l++) {
        agg_kernel<<<(NN + 3) / 4, 256>>>(p_combo + (size_t)l * 9 * DD,
                                          p_self + (size_t)l * DD,
                                          l > 0 ? 1 : 0);
        gemm_cp<1><<<dim3(4, rowBlocks), 256, NSTAGE * STAGE>>>(
            p_aggH, p_aggL, (const char*)p_W1t + (size_t)l * 4 * 8 * 16384,
            b1 + (size_t)l * 2 * DD, nullptr, p_tH, p_tL, NN, DD, 2 * DD);
        gemm_cp<0><<<dim3(2, rowBlocks), 256, NSTAGE * STAGE>>>(
            p_tH, p_tL, (const char*)p_W2t + (size_t)l * 2 * 16 * 16384,
            b2 + (size_t)l * DD, p_h, nullptr, nullptr, NN, 2 * DD, DD);
        bn_coef_kernel<<<1, 256>>>(bn_g + (size_t)l * DD, bn_b + (size_t)l * DD);
    }

    zero_pool_kernel<<<(GG * DD + 255) / 256, 256>>>();
    count_kernel<<<(NN + 255) / 256, 256>>>(batch);
    pool_scatter_kernel<<<(NN + 3) / 4, 256>>>(batch);
    pool_div_kernel<<<(GG * DD + 255) / 256, 256>>>();

    gemm_bias<1><<<dim3(4, (GG + 63) / 64), 256>>>(p_mol, hW0, hb0, p_z1, GG, 256, 256);
    gemm_bias<1><<<dim3(2, (GG + 63) / 64), 256>>>(p_z1,  hW1, hb1, p_z2, GG, 256, 128);
    gemm_bias<1><<<dim3(1, (GG + 63) / 64), 256>>>(p_z2,  hW2, hb2, p_z1, GG, 128, 64);
    gemm_bias<1><<<dim3(1, (GG + 63) / 64), 256>>>(p_z1,  hW3, hb3, p_z2, GG, 64, 32);
    head_final_kernel<<<(GG + 255) / 256, 256>>>(hWo, hbo, out);
}